// round 7
// baseline (speedup 1.0000x reference)
#include <cuda_runtime.h>
#include <cuda_bf16.h>
#include <cstdint>

#define T_SEQ 2048
#define D_MODEL 1024
#define BT_ROWS 4096            // B*T

// ---------------------------------------------------------------------------
// Scratch (device globals; no allocations anywhere)
// ---------------------------------------------------------------------------
__device__ __nv_bfloat16 g_qkv_hi[(size_t)BT_ROWS * 3072];
__device__ __nv_bfloat16 g_qkv_lo[(size_t)BT_ROWS * 3072];
__device__ __nv_bfloat16 g_att_hi[(size_t)BT_ROWS * 1024];
__device__ __nv_bfloat16 g_att_lo[(size_t)BT_ROWS * 1024];
__device__ __nv_bfloat16 g_xa_hi[(size_t)BT_ROWS * 1024];
__device__ __nv_bfloat16 g_xa_lo[(size_t)BT_ROWS * 1024];
__device__ __nv_bfloat16 g_wa_hi[(size_t)3072 * 1024];  // w_attn^T [N,K]
__device__ __nv_bfloat16 g_wa_lo[(size_t)3072 * 1024];
__device__ __nv_bfloat16 g_wp_hi[(size_t)1024 * 1024];  // w_proj^T [N,K]
__device__ __nv_bfloat16 g_wp_lo[(size_t)1024 * 1024];

// ---------------------------------------------------------------------------
// Helpers (plain sm_80-era PTX only — harness compiles for sm_103 without 'a')
// ---------------------------------------------------------------------------
__device__ __forceinline__ uint32_t smem_u32(const void* p) {
    uint32_t a;
    asm("{ .reg .u64 t; cvta.to.shared.u64 t, %1; cvt.u32.u64 %0, t; }"
        : "=r"(a) : "l"(p));
    return a;
}

__device__ __forceinline__ void cpa16(uint32_t s, const void* g) {
    asm volatile("cp.async.cg.shared.global [%0], [%1], 16;" :: "r"(s), "l"(g));
}

__device__ __forceinline__ void ldsm4(uint32_t* r, uint32_t a) {
    asm volatile("ldmatrix.sync.aligned.m8n8.x4.shared.b16 {%0,%1,%2,%3}, [%4];"
                 : "=r"(r[0]), "=r"(r[1]), "=r"(r[2]), "=r"(r[3]) : "r"(a));
}

__device__ __forceinline__ void ldsm4t(uint32_t* r, uint32_t a) {
    asm volatile("ldmatrix.sync.aligned.m8n8.x4.trans.shared.b16 {%0,%1,%2,%3}, [%4];"
                 : "=r"(r[0]), "=r"(r[1]), "=r"(r[2]), "=r"(r[3]) : "r"(a));
}

__device__ __forceinline__ void mma16816(float* d, const uint32_t* a,
                                         const uint32_t* b) {
    asm volatile(
        "mma.sync.aligned.m16n8k16.row.col.f32.bf16.bf16.f32 "
        "{%0,%1,%2,%3}, {%4,%5,%6,%7}, {%8,%9}, {%0,%1,%2,%3};"
        : "+f"(d[0]), "+f"(d[1]), "+f"(d[2]), "+f"(d[3])
        : "r"(a[0]), "r"(a[1]), "r"(a[2]), "r"(a[3]), "r"(b[0]), "r"(b[1]));
}

// split a pair of fp32 into packed bf16x2 hi and lo
__device__ __forceinline__ void split2(float a, float b, uint32_t& hi, uint32_t& lo) {
    __nv_bfloat162 h, l;
    h.x = __float2bfloat16(a);
    h.y = __float2bfloat16(b);
    l.x = __float2bfloat16(a - __bfloat162float(h.x));
    l.y = __float2bfloat16(b - __bfloat162float(h.y));
    hi = *(uint32_t*)&h;
    lo = *(uint32_t*)&l;
}

// ---------------------------------------------------------------------------
// Split kernels: fp32 -> bf16 hi + bf16 lo
// ---------------------------------------------------------------------------
__global__ void split_mat(const float* __restrict__ in,
                          __nv_bfloat16* __restrict__ hi,
                          __nv_bfloat16* __restrict__ lo, int n) {
    int i = (blockIdx.x * blockDim.x + threadIdx.x) * 4;
    if (i >= n) return;
    float4 v = *(const float4*)(in + i);
    uint32_t h0, h1, l0, l1;
    split2(v.x, v.y, h0, l0);
    split2(v.z, v.w, h1, l1);
    ((uint32_t*)(hi + i))[0] = h0;
    ((uint32_t*)(hi + i))[1] = h1;
    ((uint32_t*)(lo + i))[0] = l0;
    ((uint32_t*)(lo + i))[1] = l1;
}

// w:[Kd,Nd] row-major -> out hi/lo:[Nd,Kd] (transposed), split to bf16
__global__ void split_wT(const float* __restrict__ w,
                         __nv_bfloat16* __restrict__ hi,
                         __nv_bfloat16* __restrict__ lo, int Kd, int Nd) {
    __shared__ float t[32][33];
    int k0 = blockIdx.y * 32, n0 = blockIdx.x * 32;
    int tx = threadIdx.x, ty = threadIdx.y;   // block (32,8)
#pragma unroll
    for (int j = 0; j < 32; j += 8)
        t[ty + j][tx] = w[(size_t)(k0 + ty + j) * Nd + n0 + tx];
    __syncthreads();
#pragma unroll
    for (int j = 0; j < 32; j += 8) {
        float v = t[tx][ty + j];
        __nv_bfloat16 h = __float2bfloat16(v);
        size_t o = (size_t)(n0 + ty + j) * Kd + k0 + tx;
        hi[o] = h;
        lo[o] = __float2bfloat16(v - __bfloat162float(h));
    }
}

// ---------------------------------------------------------------------------
// Persistent HMMA bf16-split GEMM: C[M,N] = A[M,K] @ B^T[N,K] + bias
// 128x128 tiles, 128 threads / 4 warps, warp tile 64x64, BK=32, 2-stage
// cp.async pipeline + ks fragment prefetch (R6 inner loop, unchanged).
// Grid = resident CTA count; each CTA strides over tiles (no wave tail).
// ---------------------------------------------------------------------------
#define GBK 32
#define ROWB 80
#define TILE_B (128 * ROWB)
#define STAGE_B (4 * TILE_B)
#define GEMM_SMEM (2 * STAGE_B)

template <int SPLIT_OUT>
__global__ __launch_bounds__(128) void gemm_hmma(
    const __nv_bfloat16* __restrict__ Ahi, const __nv_bfloat16* __restrict__ Alo,
    const __nv_bfloat16* __restrict__ Bhi, const __nv_bfloat16* __restrict__ Blo,
    const float* __restrict__ bias, float* __restrict__ C,
    __nv_bfloat16* __restrict__ Chi, __nv_bfloat16* __restrict__ Clo,
    int M, int N, int K)
{
    extern __shared__ char smc[];
    const uint32_t sb = smem_u32(smc);
    const int tid = threadIdx.x, lane = tid & 31, wid = tid >> 5;
    const int mbw = (wid & 1) * 64;
    const int nbw = (wid >> 1) * 64;

    const uint32_t aoff =
        (uint32_t)(mbw + (lane & 15)) * ROWB + (uint32_t)(lane >> 4) * 16;
    const uint32_t boff =
        (uint32_t)(nbw + (lane >> 4) * 8 + (lane & 7)) * ROWB +
        (uint32_t)((lane >> 3) & 1) * 16;

    const int mt = M >> 7;                  // tiles along M (fastest)
    const int ntiles = mt * (N >> 7);
    const int KT = K / GBK;

    for (int t = blockIdx.x; t < ntiles; t += gridDim.x) {
        const int bm = (t % mt) * 128;
        const int bn = (t / mt) * 128;

        float acc[4][8][4];
#pragma unroll
        for (int m = 0; m < 4; m++)
#pragma unroll
            for (int n = 0; n < 8; n++)
#pragma unroll
                for (int j = 0; j < 4; j++) acc[m][n][j] = 0.f;

        auto load_stage = [&](int s, int kt) {
            const uint32_t st = sb + s * STAGE_B;
            const int kc = kt * GBK;
            const __nv_bfloat16* gp[4] = {Ahi, Alo, Bhi, Blo};
#pragma unroll
            for (int tile = 0; tile < 4; tile++) {
                const int rbase = (tile < 2) ? bm : bn;
                const uint32_t td = st + tile * TILE_B;
#pragma unroll
                for (int i = 0; i < 2; i++) {
                    int p = tid + i * 128;
                    int row = p >> 1, hf = p & 1;
                    const __nv_bfloat16* g =
                        gp[tile] + (size_t)(rbase + row) * K + kc + hf * 16;
                    uint32_t sd = td + row * ROWB + hf * 32;
                    cpa16(sd, g);
                    cpa16(sd + 16, g + 8);
                }
            }
            asm volatile("cp.async.commit_group;" ::: "memory");
        };

        load_stage(0, 0);
        load_stage(1, 1);

        for (int kt = 0; kt < KT; kt++) {
            const int s = kt & 1;
            if (kt + 1 < KT)
                asm volatile("cp.async.wait_group 1;" ::: "memory");
            else
                asm volatile("cp.async.wait_group 0;" ::: "memory");
            __syncthreads();

            const uint32_t st = sb + s * STAGE_B;
            const uint32_t stAh = st, stAl = st + TILE_B;
            const uint32_t stBh = st + 2 * TILE_B, stBl = st + 3 * TILE_B;

            uint32_t bh[4][4], bl[4][4], ah[4][4], al[4][4];
            uint32_t bhP[4][4], ahP[4][4];

#pragma unroll
            for (int p = 0; p < 4; p++) ldsm4(bh[p], stBh + boff + p * 16 * ROWB);
#pragma unroll
            for (int m = 0; m < 4; m++) ldsm4(ah[m], stAh + aoff + m * 16 * ROWB);
#pragma unroll
            for (int p = 0; p < 4; p++) ldsm4(bl[p], stBl + boff + p * 16 * ROWB);
#pragma unroll
            for (int m = 0; m < 4; m++) ldsm4(al[m], stAl + aoff + m * 16 * ROWB);

#pragma unroll
            for (int n = 0; n < 8; n++)
#pragma unroll
                for (int m = 0; m < 4; m++)
                    mma16816(acc[m][n], ah[m], &bh[n >> 1][(n & 1) * 2]);

#pragma unroll
            for (int p = 0; p < 4; p++) ldsm4(bhP[p], stBh + boff + p * 16 * ROWB + 32);
#pragma unroll
            for (int m = 0; m < 4; m++) ldsm4(ahP[m], stAh + aoff + m * 16 * ROWB + 32);

#pragma unroll
            for (int n = 0; n < 8; n++)
#pragma unroll
                for (int m = 0; m < 4; m++)
                    mma16816(acc[m][n], ah[m], &bl[n >> 1][(n & 1) * 2]);

#pragma unroll
            for (int p = 0; p < 4; p++) ldsm4(bl[p], stBl + boff + p * 16 * ROWB + 32);

#pragma unroll
            for (int n = 0; n < 8; n++)
#pragma unroll
                for (int m = 0; m < 4; m++)
                    mma16816(acc[m][n], al[m], &bh[n >> 1][(n & 1) * 2]);

#pragma unroll
            for (int m = 0; m < 4; m++) ldsm4(al[m], stAl + aoff + m * 16 * ROWB + 32);

#pragma unroll
            for (int n = 0; n < 8; n++)
#pragma unroll
                for (int m = 0; m < 4; m++)
                    mma16816(acc[m][n], ahP[m], &bhP[n >> 1][(n & 1) * 2]);
#pragma unroll
            for (int n = 0; n < 8; n++)
#pragma unroll
                for (int m = 0; m < 4; m++)
                    mma16816(acc[m][n], ahP[m], &bl[n >> 1][(n & 1) * 2]);
#pragma unroll
            for (int n = 0; n < 8; n++)
#pragma unroll
                for (int m = 0; m < 4; m++)
                    mma16816(acc[m][n], al[m], &bhP[n >> 1][(n & 1) * 2]);

            __syncthreads();
            if (kt + 2 < KT) load_stage(s, kt + 2);
        }

        // Epilogue
        const int rql = lane >> 2, cql = (lane & 3) * 2;
#pragma unroll
        for (int m = 0; m < 4; m++) {
            const int row = bm + mbw + m * 16 + rql;
#pragma unroll
            for (int n = 0; n < 8; n++) {
                const int col = bn + nbw + n * 8 + cql;
                const float bx = bias[col], by = bias[col + 1];
                float v0 = acc[m][n][0] + bx, v1 = acc[m][n][1] + by;
                float v2 = acc[m][n][2] + bx, v3 = acc[m][n][3] + by;
                if (SPLIT_OUT) {
                    uint32_t h01, l01, h23, l23;
                    split2(v0, v1, h01, l01);
                    split2(v2, v3, h23, l23);
                    *(uint32_t*)(Chi + (size_t)row * N + col) = h01;
                    *(uint32_t*)(Clo + (size_t)row * N + col) = l01;
                    *(uint32_t*)(Chi + (size_t)(row + 8) * N + col) = h23;
                    *(uint32_t*)(Clo + (size_t)(row + 8) * N + col) = l23;
                } else {
                    *(float2*)(C + (size_t)row * N + col) = make_float2(v0, v1);
                    *(float2*)(C + (size_t)(row + 8) * N + col) = make_float2(v2, v3);
                }
            }
        }
    }
}

// ---------------------------------------------------------------------------
// Persistent HMMA flash attention with bf16 hi/lo split (R4/R6 inner loop).
// Grid = 148 CTAs; each strides over the 512 (qt,h,b) tiles; consecutive
// tiles share (h,b) -> KV reuse in L2.
// ---------------------------------------------------------------------------
#define AROW 144
#define ATT_QBYTES (128 * AROW)          // 18432
#define ATT_KVTILE (64 * AROW)           // 9216
#define ATT_STAGE (4 * ATT_KVTILE + 256) // 37120
#define ATT_SMEM (2 * ATT_QBYTES + 2 * ATT_STAGE)

__global__ __launch_bounds__(256) void attn_hmma(
    const __nv_bfloat16* __restrict__ qkv_hi,
    const __nv_bfloat16* __restrict__ qkv_lo,
    const float* __restrict__ mask,
    __nv_bfloat16* __restrict__ out_hi,
    __nv_bfloat16* __restrict__ out_lo)
{
    extern __shared__ char smc[];
    const uint32_t sb = smem_u32(smc);
    const int tid = threadIdx.x, lane = tid & 31, w = tid >> 5;
    const uint32_t stg0 = sb + 2 * ATT_QBYTES;

    const uint32_t aoffQ = (uint32_t)(w * 16 + (lane & 15)) * AROW +
                           (uint32_t)(lane >> 4) * 16;
    const uint32_t boffK = (uint32_t)((lane >> 4) * 8 + (lane & 7)) * AROW +
                           (uint32_t)((lane >> 3) & 1) * 16;
    const uint32_t voffV = (uint32_t)(lane & 15) * AROW +
                           (uint32_t)(lane >> 4) * 16;

    const int NTILES = (T_SEQ / 128) * 16 * 2;   // 512

    for (int t = blockIdx.x; t < NTILES; t += gridDim.x) {
        const int qt = (t & 15) * 128;
        const int h = (t >> 4) & 15;
        const int b = t >> 8;

        // ---- Q load (part of first commit group) ----
#pragma unroll
        for (int i = 0; i < 8; i++) {
            int idx = tid + i * 256;
            int half = idx >> 10;
            int rem = idx & 1023;
            int row = rem >> 3, c = rem & 7;
            const __nv_bfloat16* g = (half ? qkv_lo : qkv_hi) +
                (size_t)(b * T_SEQ + qt + row) * 3072 + h * 64 + c * 8;
            cpa16(sb + half * ATT_QBYTES + row * AROW + c * 16, g);
        }

        auto load_kv = [&](int s, int kt) {
            const uint32_t st = stg0 + s * ATT_STAGE;
#pragma unroll
            for (int i = 0; i < 8; i++) {
                int idx = tid + i * 256;
                int tile = idx >> 9;
                int rem = idx & 511;
                int row = rem >> 3, c = rem & 7;
                int coff = ((tile < 2) ? 1024 : 2048) + h * 64;
                const __nv_bfloat16* g = ((tile & 1) ? qkv_lo : qkv_hi) +
                    (size_t)(b * T_SEQ + kt * 64 + row) * 3072 + coff + c * 8;
                cpa16(st + tile * ATT_KVTILE + row * AROW + c * 16, g);
            }
            if (tid < 16)
                cpa16(st + 4 * ATT_KVTILE + tid * 16,
                      mask + (size_t)b * T_SEQ + kt * 64 + tid * 4);
            asm volatile("cp.async.commit_group;" ::: "memory");
        };

        load_kv(0, 0);
        asm volatile("cp.async.commit_group;" ::: "memory");
        load_kv(1, 1);

        float mst0 = -1e30f, mst1 = -1e30f, lst0 = 0.f, lst1 = 0.f;
        float O[8][4];
#pragma unroll
        for (int n = 0; n < 8; n++)
#pragma unroll
            for (int j = 0; j < 4; j++) O[n][j] = 0.f;

        const int NKV = T_SEQ / 64;
        for (int kt = 0; kt < NKV; kt++) {
            const int s = kt & 1;
            if (kt + 1 < NKV)
                asm volatile("cp.async.wait_group 1;" ::: "memory");
            else
                asm volatile("cp.async.wait_group 0;" ::: "memory");
            __syncthreads();

            const uint32_t st = stg0 + s * ATT_STAGE;
            const float* mskp = (const float*)(smc + 2 * ATT_QBYTES +
                                               s * ATT_STAGE + 4 * ATT_KVTILE);

            float S[8][4];
#pragma unroll
            for (int n = 0; n < 8; n++)
#pragma unroll
                for (int j = 0; j < 4; j++) S[n][j] = 0.f;

#pragma unroll
            for (int kg = 0; kg < 4; kg++) {
                uint32_t qh[4], ql[4];
                ldsm4(qh, sb + aoffQ + kg * 32);
                ldsm4(ql, sb + ATT_QBYTES + aoffQ + kg * 32);
#pragma unroll
                for (int nb = 0; nb < 4; nb++) {
                    uint32_t kh[4], kl[4];
                    ldsm4(kh, st + boffK + nb * 16 * AROW + kg * 32);
                    ldsm4(kl, st + ATT_KVTILE + boffK + nb * 16 * AROW + kg * 32);
                    mma16816(S[2 * nb],     qh, &kh[0]);
                    mma16816(S[2 * nb + 1], qh, &kh[2]);
                    mma16816(S[2 * nb],     qh, &kl[0]);
                    mma16816(S[2 * nb + 1], qh, &kl[2]);
                    mma16816(S[2 * nb],     ql, &kh[0]);
                    mma16816(S[2 * nb + 1], ql, &kh[2]);
                }
            }

            float mx0 = -1e30f, mx1 = -1e30f;
#pragma unroll
            for (int n = 0; n < 8; n++) {
                float2 mk = *(const float2*)(mskp + n * 8 + (lane & 3) * 2);
                float m0 = 2.f * mk.x, m1 = 2.f * mk.y;
                S[n][0] = fmaf(S[n][0], 0.125f, m0);
                S[n][1] = fmaf(S[n][1], 0.125f, m1);
                S[n][2] = fmaf(S[n][2], 0.125f, m0);
                S[n][3] = fmaf(S[n][3], 0.125f, m1);
                mx0 = fmaxf(mx0, fmaxf(S[n][0], S[n][1]));
                mx1 = fmaxf(mx1, fmaxf(S[n][2], S[n][3]));
            }
            mx0 = fmaxf(mx0, __shfl_xor_sync(0xffffffffu, mx0, 1));
            mx0 = fmaxf(mx0, __shfl_xor_sync(0xffffffffu, mx0, 2));
            mx1 = fmaxf(mx1, __shfl_xor_sync(0xffffffffu, mx1, 1));
            mx1 = fmaxf(mx1, __shfl_xor_sync(0xffffffffu, mx1, 2));

            const float mn0 = fmaxf(mst0, mx0), mn1 = fmaxf(mst1, mx1);
            const float cr0 = __expf(mst0 - mn0), cr1 = __expf(mst1 - mn1);
            mst0 = mn0; mst1 = mn1;

            float rs0 = 0.f, rs1 = 0.f;
#pragma unroll
            for (int n = 0; n < 8; n++) {
                S[n][0] = __expf(S[n][0] - mn0);
                S[n][1] = __expf(S[n][1] - mn0);
                S[n][2] = __expf(S[n][2] - mn1);
                S[n][3] = __expf(S[n][3] - mn1);
                rs0 += S[n][0] + S[n][1];
                rs1 += S[n][2] + S[n][3];
            }
            rs0 += __shfl_xor_sync(0xffffffffu, rs0, 1);
            rs0 += __shfl_xor_sync(0xffffffffu, rs0, 2);
            rs1 += __shfl_xor_sync(0xffffffffu, rs1, 1);
            rs1 += __shfl_xor_sync(0xffffffffu, rs1, 2);
            lst0 = lst0 * cr0 + rs0;
            lst1 = lst1 * cr1 + rs1;

#pragma unroll
            for (int n = 0; n < 8; n++) {
                O[n][0] *= cr0; O[n][1] *= cr0;
                O[n][2] *= cr1; O[n][3] *= cr1;
            }

#pragma unroll
            for (int kg = 0; kg < 4; kg++) {
                uint32_t ah[4], al[4];
                split2(S[2 * kg][0],     S[2 * kg][1],     ah[0], al[0]);
                split2(S[2 * kg][2],     S[2 * kg][3],     ah[1], al[1]);
                split2(S[2 * kg + 1][0], S[2 * kg + 1][1], ah[2], al[2]);
                split2(S[2 * kg + 1][2], S[2 * kg + 1][3], ah[3], al[3]);
#pragma unroll
                for (int nb = 0; nb < 4; nb++) {
                    uint32_t vh[4], vl[4];
                    ldsm4t(vh, st + 2 * ATT_KVTILE + voffV + kg * 16 * AROW + nb * 32);
                    ldsm4t(vl, st + 3 * ATT_KVTILE + voffV + kg * 16 * AROW + nb * 32);
                    mma16816(O[2 * nb],     ah, &vh[0]);
                    mma16816(O[2 * nb + 1], ah, &vh[2]);
                    mma16816(O[2 * nb],     al, &vh[0]);
                    mma16816(O[2 * nb + 1], al, &vh[2]);
                    mma16816(O[2 * nb],     ah, &vl[0]);
                    mma16816(O[2 * nb + 1], ah, &vl[2]);
                }
            }
            __syncthreads();
            if (kt + 2 < NKV) load_kv(s, kt + 2);
        }

        const float inv0 = 1.f / lst0, inv1 = 1.f / lst1;
        const int row0 = b * T_SEQ + qt + w * 16 + (lane >> 2);
        const int colb = h * 64 + (lane & 3) * 2;
#pragma unroll
        for (int n = 0; n < 8; n++) {
            uint32_t h01, l01, h23, l23;
            split2(O[n][0] * inv0, O[n][1] * inv0, h01, l01);
            split2(O[n][2] * inv1, O[n][3] * inv1, h23, l23);
            const size_t o0 = (size_t)row0 * D_MODEL + colb + n * 8;
            const size_t o1 = (size_t)(row0 + 8) * D_MODEL + colb + n * 8;
            *(uint32_t*)(out_hi + o0) = h01;
            *(uint32_t*)(out_lo + o0) = l01;
            *(uint32_t*)(out_hi + o1) = h23;
            *(uint32_t*)(out_lo + o1) = l23;
        }
    }
}

// ---------------------------------------------------------------------------
extern "C" void kernel_launch(void* const* d_in, const int* in_sizes, int n_in,
                              void* d_out, int out_size)
{
    const float* x      = (const float*)d_in[0];
    const float* mask   = (const float*)d_in[1];
    const float* w_attn = (const float*)d_in[2];
    const float* b_attn = (const float*)d_in[3];
    const float* w_proj = (const float*)d_in[4];
    const float* b_proj = (const float*)d_in[5];
    float* out = (float*)d_out;

    __nv_bfloat16 *qkv_hi, *qkv_lo, *att_hi, *att_lo;
    __nv_bfloat16 *xa_hi, *xa_lo, *wa_hi, *wa_lo, *wp_hi, *wp_lo;
    cudaGetSymbolAddress((void**)&qkv_hi, g_qkv_hi);
    cudaGetSymbolAddress((void**)&qkv_lo, g_qkv_lo);
    cudaGetSymbolAddress((void**)&att_hi, g_att_hi);
    cudaGetSymbolAddress((void**)&att_lo, g_att_lo);
    cudaGetSymbolAddress((void**)&xa_hi, g_xa_hi);
    cudaGetSymbolAddress((void**)&xa_lo, g_xa_lo);
    cudaGetSymbolAddress((void**)&wa_hi, g_wa_hi);
    cudaGetSymbolAddress((void**)&wa_lo, g_wa_lo);
    cudaGetSymbolAddress((void**)&wp_hi, g_wp_hi);
    cudaGetSymbolAddress((void**)&wp_lo, g_wp_lo);

    cudaFuncSetAttribute(gemm_hmma<0>,
                         cudaFuncAttributeMaxDynamicSharedMemorySize, GEMM_SMEM);
    cudaFuncSetAttribute(gemm_hmma<1>,
                         cudaFuncAttributeMaxDynamicSharedMemorySize, GEMM_SMEM);
    cudaFuncSetAttribute(attn_hmma,
                         cudaFuncAttributeMaxDynamicSharedMemorySize, ATT_SMEM);

    const int nx = BT_ROWS * 1024;
    const int NPERSIST = 296;   // 148 SMs x 2 CTAs (80KB smem each)

    split_mat<<<nx / 4 / 256, 256>>>(x, xa_hi, xa_lo, nx);
    split_wT<<<dim3(3072 / 32, 1024 / 32), dim3(32, 8)>>>(w_attn, wa_hi, wa_lo, 1024, 3072);
    split_wT<<<dim3(1024 / 32, 1024 / 32), dim3(32, 8)>>>(w_proj, wp_hi, wp_lo, 1024, 1024);

    gemm_hmma<1><<<NPERSIST, 128, GEMM_SMEM>>>(
        xa_hi, xa_lo, wa_hi, wa_lo, b_attn, nullptr, qkv_hi, qkv_lo,
        BT_ROWS, 3072, 1024);

    attn_hmma<<<148, 256, ATT_SMEM>>>(qkv_hi, qkv_lo, mask, att_hi, att_lo);

    gemm_hmma<0><<<NPERSIST, 128, GEMM_SMEM>>>(
        att_hi, att_lo, wp_hi, wp_lo, b_proj, out, nullptr, nullptr,
        BT_ROWS, 1024, 1024);
}

// round 8
// speedup vs baseline: 1.0167x; 1.0167x over previous
#include <cuda_runtime.h>
#include <cuda_fp16.h>
#include <cstdint>

#define T_SEQ 2048
#define D_MODEL 1024
#define BT_ROWS 4096            // B*T

// ---------------------------------------------------------------------------
// Scratch (device globals; no allocations anywhere).  All splits are f16 now.
// ---------------------------------------------------------------------------
__device__ __half g_qkv_hi[(size_t)BT_ROWS * 3072];
__device__ __half g_qkv_lo[(size_t)BT_ROWS * 3072];
__device__ __half g_att_hi[(size_t)BT_ROWS * 1024];
__device__ __half g_att_lo[(size_t)BT_ROWS * 1024];
__device__ __half g_xa_hi[(size_t)BT_ROWS * 1024];
__device__ __half g_xa_lo[(size_t)BT_ROWS * 1024];
__device__ __half g_wa_hi[(size_t)3072 * 1024];  // w_attn^T [N,K]
__device__ __half g_wa_lo[(size_t)3072 * 1024];
__device__ __half g_wp_hi[(size_t)1024 * 1024];  // w_proj^T [N,K]
__device__ __half g_wp_lo[(size_t)1024 * 1024];

// ---------------------------------------------------------------------------
// Helpers (plain sm_80-era PTX only)
// ---------------------------------------------------------------------------
__device__ __forceinline__ uint32_t smem_u32(const void* p) {
    uint32_t a;
    asm("{ .reg .u64 t; cvta.to.shared.u64 t, %1; cvt.u32.u64 %0, t; }"
        : "=r"(a) : "l"(p));
    return a;
}

__device__ __forceinline__ void cpa16(uint32_t s, const void* g) {
    asm volatile("cp.async.cg.shared.global [%0], [%1], 16;" :: "r"(s), "l"(g));
}

__device__ __forceinline__ void ldsm4(uint32_t* r, uint32_t a) {
    asm volatile("ldmatrix.sync.aligned.m8n8.x4.shared.b16 {%0,%1,%2,%3}, [%4];"
                 : "=r"(r[0]), "=r"(r[1]), "=r"(r[2]), "=r"(r[3]) : "r"(a));
}

__device__ __forceinline__ void ldsm4t(uint32_t* r, uint32_t a) {
    asm volatile("ldmatrix.sync.aligned.m8n8.x4.trans.shared.b16 {%0,%1,%2,%3}, [%4];"
                 : "=r"(r[0]), "=r"(r[1]), "=r"(r[2]), "=r"(r[3]) : "r"(a));
}

// f16 x f16 -> f32 accumulate (precision-critical hi*hi term)
__device__ __forceinline__ void mma_f32(float* d, const uint32_t* a,
                                        const uint32_t* b) {
    asm volatile(
        "mma.sync.aligned.m16n8k16.row.col.f32.f16.f16.f32 "
        "{%0,%1,%2,%3}, {%4,%5,%6,%7}, {%8,%9}, {%0,%1,%2,%3};"
        : "+f"(d[0]), "+f"(d[1]), "+f"(d[2]), "+f"(d[3])
        : "r"(a[0]), "r"(a[1]), "r"(a[2]), "r"(a[3]), "r"(b[0]), "r"(b[1]));
}

// f16 x f16 -> f16 accumulate (lo cross-terms; potentially double-rate)
__device__ __forceinline__ void mma_f16(uint32_t* d, const uint32_t* a,
                                        const uint32_t* b) {
    asm volatile(
        "mma.sync.aligned.m16n8k16.row.col.f16.f16.f16.f16 "
        "{%0,%1}, {%2,%3,%4,%5}, {%6,%7}, {%0,%1};"
        : "+r"(d[0]), "+r"(d[1])
        : "r"(a[0]), "r"(a[1]), "r"(a[2]), "r"(a[3]), "r"(b[0]), "r"(b[1]));
}

// split a pair of fp32 into packed f16x2 hi and lo
__device__ __forceinline__ void split2(float a, float b, uint32_t& hi, uint32_t& lo) {
    __half2 h, l;
    h.x = __float2half(a);
    h.y = __float2half(b);
    l.x = __float2half(a - __half2float(h.x));
    l.y = __float2half(b - __half2float(h.y));
    hi = *(uint32_t*)&h;
    lo = *(uint32_t*)&l;
}

// ---------------------------------------------------------------------------
// Split kernels: fp32 -> f16 hi + f16 lo
// ---------------------------------------------------------------------------
__global__ void split_mat(const float* __restrict__ in,
                          __half* __restrict__ hi,
                          __half* __restrict__ lo, int n) {
    int i = (blockIdx.x * blockDim.x + threadIdx.x) * 4;
    if (i >= n) return;
    float4 v = *(const float4*)(in + i);
    uint32_t h0, h1, l0, l1;
    split2(v.x, v.y, h0, l0);
    split2(v.z, v.w, h1, l1);
    ((uint32_t*)(hi + i))[0] = h0;
    ((uint32_t*)(hi + i))[1] = h1;
    ((uint32_t*)(lo + i))[0] = l0;
    ((uint32_t*)(lo + i))[1] = l1;
}

// w:[Kd,Nd] row-major -> out hi/lo:[Nd,Kd] (transposed), split to f16
__global__ void split_wT(const float* __restrict__ w,
                         __half* __restrict__ hi,
                         __half* __restrict__ lo, int Kd, int Nd) {
    __shared__ float t[32][33];
    int k0 = blockIdx.y * 32, n0 = blockIdx.x * 32;
    int tx = threadIdx.x, ty = threadIdx.y;   // block (32,8)
#pragma unroll
    for (int j = 0; j < 32; j += 8)
        t[ty + j][tx] = w[(size_t)(k0 + ty + j) * Nd + n0 + tx];
    __syncthreads();
#pragma unroll
    for (int j = 0; j < 32; j += 8) {
        float v = t[tx][ty + j];
        __half h = __float2half(v);
        size_t o = (size_t)(n0 + ty + j) * Kd + k0 + tx;
        hi[o] = h;
        lo[o] = __float2half(v - __half2float(h));
    }
}

// ---------------------------------------------------------------------------
// HMMA f16-split GEMM: C[M,N] = A[M,K] @ B^T[N,K] + bias
// 128x128 CTA tile, 128 threads / 4 warps, warp tile 64x64, BK=32,
// 2-stage cp.async pipeline.
// hi*hi -> f32 accum; Ah*Bl + Al*Bh -> chained f16 accum (merged at epilogue).
// ---------------------------------------------------------------------------
#define GBK 32
#define ROWB 80
#define TILE_B (128 * ROWB)
#define STAGE_B (4 * TILE_B)
#define GEMM_SMEM (2 * STAGE_B)

template <int SPLIT_OUT>
__global__ __launch_bounds__(128) void gemm_hmma(
    const __half* __restrict__ Ahi, const __half* __restrict__ Alo,
    const __half* __restrict__ Bhi, const __half* __restrict__ Blo,
    const float* __restrict__ bias, float* __restrict__ C,
    __half* __restrict__ Chi, __half* __restrict__ Clo,
    int N, int K)
{
    extern __shared__ char smc[];
    const uint32_t sb = smem_u32(smc);
    const int tid = threadIdx.x, lane = tid & 31, wid = tid >> 5;
    const int bm = blockIdx.y * 128, bn = blockIdx.x * 128;
    const int mbw = (wid & 1) * 64;
    const int nbw = (wid >> 1) * 64;

    float acc[4][8][4];
    uint32_t accL[4][8][2];
#pragma unroll
    for (int m = 0; m < 4; m++)
#pragma unroll
        for (int n = 0; n < 8; n++) {
#pragma unroll
            for (int j = 0; j < 4; j++) acc[m][n][j] = 0.f;
            accL[m][n][0] = 0u; accL[m][n][1] = 0u;
        }

    const uint32_t aoff =
        (uint32_t)(mbw + (lane & 15)) * ROWB + (uint32_t)(lane >> 4) * 16;
    const uint32_t boff =
        (uint32_t)(nbw + (lane >> 4) * 8 + (lane & 7)) * ROWB +
        (uint32_t)((lane >> 3) & 1) * 16;

    auto load_stage = [&](int s, int kt) {
        const uint32_t st = sb + s * STAGE_B;
        const int kc = kt * GBK;
        const __half* gp[4] = {Ahi, Alo, Bhi, Blo};
#pragma unroll
        for (int tile = 0; tile < 4; tile++) {
            const int rbase = (tile < 2) ? bm : bn;
            const uint32_t td = st + tile * TILE_B;
#pragma unroll
            for (int i = 0; i < 2; i++) {
                int p = tid + i * 128;
                int row = p >> 1, hf = p & 1;
                const __half* g =
                    gp[tile] + (size_t)(rbase + row) * K + kc + hf * 16;
                uint32_t sd = td + row * ROWB + hf * 32;
                cpa16(sd, g);
                cpa16(sd + 16, g + 8);
            }
        }
        asm volatile("cp.async.commit_group;" ::: "memory");
    };

    const int KT = K / GBK;
    load_stage(0, 0);
    load_stage(1, 1);

    for (int kt = 0; kt < KT; kt++) {
        const int s = kt & 1;
        if (kt + 1 < KT)
            asm volatile("cp.async.wait_group 1;" ::: "memory");
        else
            asm volatile("cp.async.wait_group 0;" ::: "memory");
        __syncthreads();

        const uint32_t st = sb + s * STAGE_B;
        const uint32_t stAh = st, stAl = st + TILE_B;
        const uint32_t stBh = st + 2 * TILE_B, stBl = st + 3 * TILE_B;

#pragma unroll
        for (int ks = 0; ks < 2; ks++) {
            const uint32_t ko = ks * 32;
            uint32_t bh[4][4], ah[4][4], xl[4][4];
#pragma unroll
            for (int p = 0; p < 4; p++)
                ldsm4(bh[p], stBh + boff + p * 16 * ROWB + ko);
#pragma unroll
            for (int m = 0; m < 4; m++)
                ldsm4(ah[m], stAh + aoff + m * 16 * ROWB + ko);
            // hi*hi -> f32
#pragma unroll
            for (int n = 0; n < 8; n++)
#pragma unroll
                for (int m = 0; m < 4; m++)
                    mma_f32(acc[m][n], ah[m], &bh[n >> 1][(n & 1) * 2]);
            // Ah*Bl -> f16
#pragma unroll
            for (int p = 0; p < 4; p++)
                ldsm4(xl[p], stBl + boff + p * 16 * ROWB + ko);
#pragma unroll
            for (int n = 0; n < 8; n++)
#pragma unroll
                for (int m = 0; m < 4; m++)
                    mma_f16(accL[m][n], ah[m], &xl[n >> 1][(n & 1) * 2]);
            // Al*Bh -> f16 (xl reused for Al)
#pragma unroll
            for (int m = 0; m < 4; m++)
                ldsm4(xl[m], stAl + aoff + m * 16 * ROWB + ko);
#pragma unroll
            for (int n = 0; n < 8; n++)
#pragma unroll
                for (int m = 0; m < 4; m++)
                    mma_f16(accL[m][n], xl[m], &bh[n >> 1][(n & 1) * 2]);
        }
        __syncthreads();
        if (kt + 2 < KT) load_stage(s, kt + 2);
    }

    // Epilogue: merge f16 lo-accumulators, add bias, store
    const int rql = lane >> 2, cql = (lane & 3) * 2;
#pragma unroll
    for (int m = 0; m < 4; m++) {
        const int row = bm + mbw + m * 16 + rql;
#pragma unroll
        for (int n = 0; n < 8; n++) {
            const int col = bn + nbw + n * 8 + cql;
            const float bx = bias[col], by = bias[col + 1];
            __half2 lo0 = *(__half2*)&accL[m][n][0];
            __half2 lo1 = *(__half2*)&accL[m][n][1];
            float v0 = acc[m][n][0] + __half2float(lo0.x) + bx;
            float v1 = acc[m][n][1] + __half2float(lo0.y) + by;
            float v2 = acc[m][n][2] + __half2float(lo1.x) + bx;
            float v3 = acc[m][n][3] + __half2float(lo1.y) + by;
            if (SPLIT_OUT) {
                uint32_t h01, l01, h23, l23;
                split2(v0, v1, h01, l01);
                split2(v2, v3, h23, l23);
                *(uint32_t*)(Chi + (size_t)row * N + col) = h01;
                *(uint32_t*)(Clo + (size_t)row * N + col) = l01;
                *(uint32_t*)(Chi + (size_t)(row + 8) * N + col) = h23;
                *(uint32_t*)(Clo + (size_t)(row + 8) * N + col) = l23;
            } else {
                *(float2*)(C + (size_t)row * N + col) = make_float2(v0, v1);
                *(float2*)(C + (size_t)(row + 8) * N + col) = make_float2(v2, v3);
            }
        }
    }
}

// ---------------------------------------------------------------------------
// HMMA flash attention, f16 hi/lo split.
// hi*hi terms -> f32 accum; lo cross-terms -> f16 accum merged per kt tile.
// ---------------------------------------------------------------------------
#define AROW 144
#define ATT_QBYTES (128 * AROW)          // 18432
#define ATT_KVTILE (64 * AROW)           // 9216
#define ATT_STAGE (4 * ATT_KVTILE + 256) // 37120
#define ATT_SMEM (2 * ATT_QBYTES + 2 * ATT_STAGE)

__global__ __launch_bounds__(256) void attn_hmma(
    const __half* __restrict__ qkv_hi,
    const __half* __restrict__ qkv_lo,
    const float* __restrict__ mask,
    __half* __restrict__ out_hi,
    __half* __restrict__ out_lo)
{
    extern __shared__ char smc[];
    const uint32_t sb = smem_u32(smc);
    const int tid = threadIdx.x, lane = tid & 31, w = tid >> 5;
    const int qt = blockIdx.x * 128;
    const int h = blockIdx.y, b = blockIdx.z;

#pragma unroll
    for (int i = 0; i < 8; i++) {
        int idx = tid + i * 256;
        int half_ = idx >> 10;
        int rem = idx & 1023;
        int row = rem >> 3, c = rem & 7;
        const __half* g = (half_ ? qkv_lo : qkv_hi) +
            (size_t)(b * T_SEQ + qt + row) * 3072 + h * 64 + c * 8;
        cpa16(sb + half_ * ATT_QBYTES + row * AROW + c * 16, g);
    }

    const uint32_t stg0 = sb + 2 * ATT_QBYTES;

    auto load_kv = [&](int s, int kt) {
        const uint32_t st = stg0 + s * ATT_STAGE;
#pragma unroll
        for (int i = 0; i < 8; i++) {
            int idx = tid + i * 256;
            int tile = idx >> 9;
            int rem = idx & 511;
            int row = rem >> 3, c = rem & 7;
            int coff = ((tile < 2) ? 1024 : 2048) + h * 64;
            const __half* g = ((tile & 1) ? qkv_lo : qkv_hi) +
                (size_t)(b * T_SEQ + kt * 64 + row) * 3072 + coff + c * 8;
            cpa16(st + tile * ATT_KVTILE + row * AROW + c * 16, g);
        }
        if (tid < 16)
            cpa16(st + 4 * ATT_KVTILE + tid * 16,
                  mask + (size_t)b * T_SEQ + kt * 64 + tid * 4);
        asm volatile("cp.async.commit_group;" ::: "memory");
    };

    load_kv(0, 0);
    asm volatile("cp.async.commit_group;" ::: "memory");
    load_kv(1, 1);

    const uint32_t aoffQ = (uint32_t)(w * 16 + (lane & 15)) * AROW +
                           (uint32_t)(lane >> 4) * 16;
    const uint32_t boffK = (uint32_t)((lane >> 4) * 8 + (lane & 7)) * AROW +
                           (uint32_t)((lane >> 3) & 1) * 16;
    const uint32_t voffV = (uint32_t)(lane & 15) * AROW +
                           (uint32_t)(lane >> 4) * 16;

    float mst0 = -1e30f, mst1 = -1e30f, lst0 = 0.f, lst1 = 0.f;
    float O[8][4];
#pragma unroll
    for (int n = 0; n < 8; n++)
#pragma unroll
        for (int j = 0; j < 4; j++) O[n][j] = 0.f;

    const int NKV = T_SEQ / 64;
    for (int kt = 0; kt < NKV; kt++) {
        const int s = kt & 1;
        if (kt + 1 < NKV)
            asm volatile("cp.async.wait_group 1;" ::: "memory");
        else
            asm volatile("cp.async.wait_group 0;" ::: "memory");
        __syncthreads();

        const uint32_t st = stg0 + s * ATT_STAGE;
        const float* mskp = (const float*)(smc + 2 * ATT_QBYTES +
                                           s * ATT_STAGE + 4 * ATT_KVTILE);

        // ---- S = Q K^T: hi*hi f32 + lo cross-terms f16 ----
        float S[8][4];
        uint32_t SL[8][2];
#pragma unroll
        for (int n = 0; n < 8; n++) {
#pragma unroll
            for (int j = 0; j < 4; j++) S[n][j] = 0.f;
            SL[n][0] = 0u; SL[n][1] = 0u;
        }

#pragma unroll
        for (int kg = 0; kg < 4; kg++) {
            uint32_t qh[4], ql[4];
            ldsm4(qh, sb + aoffQ + kg * 32);
            ldsm4(ql, sb + ATT_QBYTES + aoffQ + kg * 32);
#pragma unroll
            for (int nb = 0; nb < 4; nb++) {
                uint32_t kh[4], kl[4];
                ldsm4(kh, st + boffK + nb * 16 * AROW + kg * 32);
                ldsm4(kl, st + ATT_KVTILE + boffK + nb * 16 * AROW + kg * 32);
                mma_f32(S[2 * nb],     qh, &kh[0]);
                mma_f32(S[2 * nb + 1], qh, &kh[2]);
                mma_f16(SL[2 * nb],     qh, &kl[0]);
                mma_f16(SL[2 * nb + 1], qh, &kl[2]);
                mma_f16(SL[2 * nb],     ql, &kh[0]);
                mma_f16(SL[2 * nb + 1], ql, &kh[2]);
            }
        }
        // merge lo terms
#pragma unroll
        for (int n = 0; n < 8; n++) {
            __half2 lo0 = *(__half2*)&SL[n][0];
            __half2 lo1 = *(__half2*)&SL[n][1];
            S[n][0] += __half2float(lo0.x);
            S[n][1] += __half2float(lo0.y);
            S[n][2] += __half2float(lo1.x);
            S[n][3] += __half2float(lo1.y);
        }

        // ---- scale + double mask + online softmax ----
        float mx0 = -1e30f, mx1 = -1e30f;
#pragma unroll
        for (int n = 0; n < 8; n++) {
            float2 mk = *(const float2*)(mskp + n * 8 + (lane & 3) * 2);
            float m0 = 2.f * mk.x, m1 = 2.f * mk.y;
            S[n][0] = fmaf(S[n][0], 0.125f, m0);
            S[n][1] = fmaf(S[n][1], 0.125f, m1);
            S[n][2] = fmaf(S[n][2], 0.125f, m0);
            S[n][3] = fmaf(S[n][3], 0.125f, m1);
            mx0 = fmaxf(mx0, fmaxf(S[n][0], S[n][1]));
            mx1 = fmaxf(mx1, fmaxf(S[n][2], S[n][3]));
        }
        mx0 = fmaxf(mx0, __shfl_xor_sync(0xffffffffu, mx0, 1));
        mx0 = fmaxf(mx0, __shfl_xor_sync(0xffffffffu, mx0, 2));
        mx1 = fmaxf(mx1, __shfl_xor_sync(0xffffffffu, mx1, 1));
        mx1 = fmaxf(mx1, __shfl_xor_sync(0xffffffffu, mx1, 2));

        const float mn0 = fmaxf(mst0, mx0), mn1 = fmaxf(mst1, mx1);
        const float cr0 = __expf(mst0 - mn0), cr1 = __expf(mst1 - mn1);
        mst0 = mn0; mst1 = mn1;

        float rs0 = 0.f, rs1 = 0.f;
#pragma unroll
        for (int n = 0; n < 8; n++) {
            S[n][0] = __expf(S[n][0] - mn0);
            S[n][1] = __expf(S[n][1] - mn0);
            S[n][2] = __expf(S[n][2] - mn1);
            S[n][3] = __expf(S[n][3] - mn1);
            rs0 += S[n][0] + S[n][1];
            rs1 += S[n][2] + S[n][3];
        }
        rs0 += __shfl_xor_sync(0xffffffffu, rs0, 1);
        rs0 += __shfl_xor_sync(0xffffffffu, rs0, 2);
        rs1 += __shfl_xor_sync(0xffffffffu, rs1, 1);
        rs1 += __shfl_xor_sync(0xffffffffu, rs1, 2);
        lst0 = lst0 * cr0 + rs0;
        lst1 = lst1 * cr1 + rs1;

#pragma unroll
        for (int n = 0; n < 8; n++) {
            O[n][0] *= cr0; O[n][1] *= cr0;
            O[n][2] *= cr1; O[n][3] *= cr1;
        }

        // ---- O += P V: hi*hi f32 + lo cross-terms f16 (per-kt merge) ----
        uint32_t OL[8][2];
#pragma unroll
        for (int n = 0; n < 8; n++) { OL[n][0] = 0u; OL[n][1] = 0u; }

#pragma unroll
        for (int kg = 0; kg < 4; kg++) {
            uint32_t ph[4], pl[4];
            split2(S[2 * kg][0],     S[2 * kg][1],     ph[0], pl[0]);
            split2(S[2 * kg][2],     S[2 * kg][3],     ph[1], pl[1]);
            split2(S[2 * kg + 1][0], S[2 * kg + 1][1], ph[2], pl[2]);
            split2(S[2 * kg + 1][2], S[2 * kg + 1][3], ph[3], pl[3]);
#pragma unroll
            for (int nb = 0; nb < 4; nb++) {
                uint32_t vh[4], vl[4];
                ldsm4t(vh, st + 2 * ATT_KVTILE + voffV + kg * 16 * AROW + nb * 32);
                ldsm4t(vl, st + 3 * ATT_KVTILE + voffV + kg * 16 * AROW + nb * 32);
                mma_f32(O[2 * nb],     ph, &vh[0]);
                mma_f32(O[2 * nb + 1], ph, &vh[2]);
                mma_f16(OL[2 * nb],     ph, &vl[0]);
                mma_f16(OL[2 * nb + 1], ph, &vl[2]);
                mma_f16(OL[2 * nb],     pl, &vh[0]);
                mma_f16(OL[2 * nb + 1], pl, &vh[2]);
            }
        }
#pragma unroll
        for (int n = 0; n < 8; n++) {
            __half2 lo0 = *(__half2*)&OL[n][0];
            __half2 lo1 = *(__half2*)&OL[n][1];
            O[n][0] += __half2float(lo0.x);
            O[n][1] += __half2float(lo0.y);
            O[n][2] += __half2float(lo1.x);
            O[n][3] += __half2float(lo1.y);
        }

        __syncthreads();
        if (kt + 2 < NKV) load_kv(s, kt + 2);
    }

    const float inv0 = 1.f / lst0, inv1 = 1.f / lst1;
    const int row0 = b * T_SEQ + qt + w * 16 + (lane >> 2);
    const int colb = h * 64 + (lane & 3) * 2;
#pragma unroll
    for (int n = 0; n < 8; n++) {
        uint32_t h01, l01, h23, l23;
        split2(O[n][0] * inv0, O[n][1] * inv0, h01, l01);
        split2(O[n][2] * inv1, O[n][3] * inv1, h23, l23);
        const size_t o0 = (size_t)row0 * D_MODEL + colb + n * 8;
        const size_t o1 = (size_t)(row0 + 8) * D_MODEL + colb + n * 8;
        *(uint32_t*)(out_hi + o0) = h01;
        *(uint32_t*)(out_lo + o0) = l01;
        *(uint32_t*)(out_hi + o1) = h23;
        *(uint32_t*)(out_lo + o1) = l23;
    }
}

// ---------------------------------------------------------------------------
extern "C" void kernel_launch(void* const* d_in, const int* in_sizes, int n_in,
                              void* d_out, int out_size)
{
    const float* x      = (const float*)d_in[0];
    const float* mask   = (const float*)d_in[1];
    const float* w_attn = (const float*)d_in[2];
    const float* b_attn = (const float*)d_in[3];
    const float* w_proj = (const float*)d_in[4];
    const float* b_proj = (const float*)d_in[5];
    float* out = (float*)d_out;

    __half *qkv_hi, *qkv_lo, *att_hi, *att_lo;
    __half *xa_hi, *xa_lo, *wa_hi, *wa_lo, *wp_hi, *wp_lo;
    cudaGetSymbolAddress((void**)&qkv_hi, g_qkv_hi);
    cudaGetSymbolAddress((void**)&qkv_lo, g_qkv_lo);
    cudaGetSymbolAddress((void**)&att_hi, g_att_hi);
    cudaGetSymbolAddress((void**)&att_lo, g_att_lo);
    cudaGetSymbolAddress((void**)&xa_hi, g_xa_hi);
    cudaGetSymbolAddress((void**)&xa_lo, g_xa_lo);
    cudaGetSymbolAddress((void**)&wa_hi, g_wa_hi);
    cudaGetSymbolAddress((void**)&wa_lo, g_wa_lo);
    cudaGetSymbolAddress((void**)&wp_hi, g_wp_hi);
    cudaGetSymbolAddress((void**)&wp_lo, g_wp_lo);

    cudaFuncSetAttribute(gemm_hmma<0>,
                         cudaFuncAttributeMaxDynamicSharedMemorySize, GEMM_SMEM);
    cudaFuncSetAttribute(gemm_hmma<1>,
                         cudaFuncAttributeMaxDynamicSharedMemorySize, GEMM_SMEM);
    cudaFuncSetAttribute(attn_hmma,
                         cudaFuncAttributeMaxDynamicSharedMemorySize, ATT_SMEM);

    const int nx = BT_ROWS * 1024;

    split_mat<<<nx / 4 / 256, 256>>>(x, xa_hi, xa_lo, nx);
    split_wT<<<dim3(3072 / 32, 1024 / 32), dim3(32, 8)>>>(w_attn, wa_hi, wa_lo, 1024, 3072);
    split_wT<<<dim3(1024 / 32, 1024 / 32), dim3(32, 8)>>>(w_proj, wp_hi, wp_lo, 1024, 1024);

    gemm_hmma<1><<<dim3(3072 / 128, BT_ROWS / 128), 128, GEMM_SMEM>>>(
        xa_hi, xa_lo, wa_hi, wa_lo, b_attn, nullptr, qkv_hi, qkv_lo, 3072, 1024);

    attn_hmma<<<dim3(T_SEQ / 128, 16, 2), 256, ATT_SMEM>>>(
        qkv_hi, qkv_lo, mask, att_hi, att_lo);

    gemm_hmma<0><<<dim3(1024 / 128, BT_ROWS / 128), 128, GEMM_SMEM>>>(
        att_hi, att_lo, wp_hi, wp_lo, b_proj, out, nullptr, nullptr, 1024, 1024);
}

// round 9
// speedup vs baseline: 1.2783x; 1.2573x over previous
#include <cuda_runtime.h>
#include <cuda_fp16.h>
#include <cstdint>

#define T_SEQ 2048
#define D_MODEL 1024
#define BT_ROWS 4096            // B*T

// ---------------------------------------------------------------------------
// Scratch (device globals; no allocations anywhere).  All splits are f16.
// ---------------------------------------------------------------------------
__device__ __half g_qkv_hi[(size_t)BT_ROWS * 3072];
__device__ __half g_qkv_lo[(size_t)BT_ROWS * 3072];
__device__ __half g_att_hi[(size_t)BT_ROWS * 1024];
__device__ __half g_att_lo[(size_t)BT_ROWS * 1024];
__device__ __half g_xa_hi[(size_t)BT_ROWS * 1024];
__device__ __half g_xa_lo[(size_t)BT_ROWS * 1024];
__device__ __half g_wa_hi[(size_t)3072 * 1024];  // w_attn^T [N,K]
__device__ __half g_wa_lo[(size_t)3072 * 1024];
__device__ __half g_wp_hi[(size_t)1024 * 1024];  // w_proj^T [N,K]
__device__ __half g_wp_lo[(size_t)1024 * 1024];

// ---------------------------------------------------------------------------
// Helpers (plain sm_80-era PTX only)
// ---------------------------------------------------------------------------
__device__ __forceinline__ uint32_t smem_u32(const void* p) {
    uint32_t a;
    asm("{ .reg .u64 t; cvta.to.shared.u64 t, %1; cvt.u32.u64 %0, t; }"
        : "=r"(a) : "l"(p));
    return a;
}

__device__ __forceinline__ void cpa16(uint32_t s, const void* g) {
    asm volatile("cp.async.cg.shared.global [%0], [%1], 16;" :: "r"(s), "l"(g));
}

__device__ __forceinline__ void ldsm4(uint32_t* r, uint32_t a) {
    asm volatile("ldmatrix.sync.aligned.m8n8.x4.shared.b16 {%0,%1,%2,%3}, [%4];"
                 : "=r"(r[0]), "=r"(r[1]), "=r"(r[2]), "=r"(r[3]) : "r"(a));
}

__device__ __forceinline__ void ldsm4t(uint32_t* r, uint32_t a) {
    asm volatile("ldmatrix.sync.aligned.m8n8.x4.trans.shared.b16 {%0,%1,%2,%3}, [%4];"
                 : "=r"(r[0]), "=r"(r[1]), "=r"(r[2]), "=r"(r[3]) : "r"(a));
}

// f16 x f16 -> f32 accumulate
__device__ __forceinline__ void mma_f32(float* d, const uint32_t* a,
                                        const uint32_t* b) {
    asm volatile(
        "mma.sync.aligned.m16n8k16.row.col.f32.f16.f16.f32 "
        "{%0,%1,%2,%3}, {%4,%5,%6,%7}, {%8,%9}, {%0,%1,%2,%3};"
        : "+f"(d[0]), "+f"(d[1]), "+f"(d[2]), "+f"(d[3])
        : "r"(a[0]), "r"(a[1]), "r"(a[2]), "r"(a[3]), "r"(b[0]), "r"(b[1]));
}

// f16 x f16 -> f16 accumulate (GEMM lo cross-terms)
__device__ __forceinline__ void mma_f16(uint32_t* d, const uint32_t* a,
                                        const uint32_t* b) {
    asm volatile(
        "mma.sync.aligned.m16n8k16.row.col.f16.f16.f16.f16 "
        "{%0,%1}, {%2,%3,%4,%5}, {%6,%7}, {%0,%1};"
        : "+r"(d[0]), "+r"(d[1])
        : "r"(a[0]), "r"(a[1]), "r"(a[2]), "r"(a[3]), "r"(b[0]), "r"(b[1]));
}

// split a pair of fp32 into packed f16x2 hi and lo
__device__ __forceinline__ void split2(float a, float b, uint32_t& hi, uint32_t& lo) {
    __half2 h, l;
    h.x = __float2half(a);
    h.y = __float2half(b);
    l.x = __float2half(a - __half2float(h.x));
    l.y = __float2half(b - __half2float(h.y));
    hi = *(uint32_t*)&h;
    lo = *(uint32_t*)&l;
}

// pack a pair of fp32 -> f16x2 (single rounding, no lo)
__device__ __forceinline__ uint32_t pack2(float a, float b) {
    __half2 h;
    h.x = __float2half(a);
    h.y = __float2half(b);
    return *(uint32_t*)&h;
}

// ---------------------------------------------------------------------------
// Split kernels: fp32 -> f16 hi + f16 lo
// ---------------------------------------------------------------------------
__global__ void split_mat(const float* __restrict__ in,
                          __half* __restrict__ hi,
                          __half* __restrict__ lo, int n) {
    int i = (blockIdx.x * blockDim.x + threadIdx.x) * 4;
    if (i >= n) return;
    float4 v = *(const float4*)(in + i);
    uint32_t h0, h1, l0, l1;
    split2(v.x, v.y, h0, l0);
    split2(v.z, v.w, h1, l1);
    ((uint32_t*)(hi + i))[0] = h0;
    ((uint32_t*)(hi + i))[1] = h1;
    ((uint32_t*)(lo + i))[0] = l0;
    ((uint32_t*)(lo + i))[1] = l1;
}

// w:[Kd,Nd] row-major -> out hi/lo:[Nd,Kd] (transposed), split to f16
__global__ void split_wT(const float* __restrict__ w,
                         __half* __restrict__ hi,
                         __half* __restrict__ lo, int Kd, int Nd) {
    __shared__ float t[32][33];
    int k0 = blockIdx.y * 32, n0 = blockIdx.x * 32;
    int tx = threadIdx.x, ty = threadIdx.y;   // block (32,8)
#pragma unroll
    for (int j = 0; j < 32; j += 8)
        t[ty + j][tx] = w[(size_t)(k0 + ty + j) * Nd + n0 + tx];
    __syncthreads();
#pragma unroll
    for (int j = 0; j < 32; j += 8) {
        float v = t[tx][ty + j];
        __half h = __float2half(v);
        size_t o = (size_t)(n0 + ty + j) * Kd + k0 + tx;
        hi[o] = h;
        lo[o] = __float2half(v - __half2float(h));
    }
}

// ---------------------------------------------------------------------------
// HMMA f16-split GEMM (unchanged from round 8; proven at ~272us for QKV).
// ---------------------------------------------------------------------------
#define GBK 32
#define ROWB 80
#define TILE_B (128 * ROWB)
#define STAGE_B (4 * TILE_B)
#define GEMM_SMEM (2 * STAGE_B)

template <int SPLIT_OUT>
__global__ __launch_bounds__(128) void gemm_hmma(
    const __half* __restrict__ Ahi, const __half* __restrict__ Alo,
    const __half* __restrict__ Bhi, const __half* __restrict__ Blo,
    const float* __restrict__ bias, float* __restrict__ C,
    __half* __restrict__ Chi, __half* __restrict__ Clo,
    int N, int K)
{
    extern __shared__ char smc[];
    const uint32_t sb = smem_u32(smc);
    const int tid = threadIdx.x, lane = tid & 31, wid = tid >> 5;
    const int bm = blockIdx.y * 128, bn = blockIdx.x * 128;
    const int mbw = (wid & 1) * 64;
    const int nbw = (wid >> 1) * 64;

    float acc[4][8][4];
    uint32_t accL[4][8][2];
#pragma unroll
    for (int m = 0; m < 4; m++)
#pragma unroll
        for (int n = 0; n < 8; n++) {
#pragma unroll
            for (int j = 0; j < 4; j++) acc[m][n][j] = 0.f;
            accL[m][n][0] = 0u; accL[m][n][1] = 0u;
        }

    const uint32_t aoff =
        (uint32_t)(mbw + (lane & 15)) * ROWB + (uint32_t)(lane >> 4) * 16;
    const uint32_t boff =
        (uint32_t)(nbw + (lane >> 4) * 8 + (lane & 7)) * ROWB +
        (uint32_t)((lane >> 3) & 1) * 16;

    auto load_stage = [&](int s, int kt) {
        const uint32_t st = sb + s * STAGE_B;
        const int kc = kt * GBK;
        const __half* gp[4] = {Ahi, Alo, Bhi, Blo};
#pragma unroll
        for (int tile = 0; tile < 4; tile++) {
            const int rbase = (tile < 2) ? bm : bn;
            const uint32_t td = st + tile * TILE_B;
#pragma unroll
            for (int i = 0; i < 2; i++) {
                int p = tid + i * 128;
                int row = p >> 1, hf = p & 1;
                const __half* g =
                    gp[tile] + (size_t)(rbase + row) * K + kc + hf * 16;
                uint32_t sd = td + row * ROWB + hf * 32;
                cpa16(sd, g);
                cpa16(sd + 16, g + 8);
            }
        }
        asm volatile("cp.async.commit_group;" ::: "memory");
    };

    const int KT = K / GBK;
    load_stage(0, 0);
    load_stage(1, 1);

    for (int kt = 0; kt < KT; kt++) {
        const int s = kt & 1;
        if (kt + 1 < KT)
            asm volatile("cp.async.wait_group 1;" ::: "memory");
        else
            asm volatile("cp.async.wait_group 0;" ::: "memory");
        __syncthreads();

        const uint32_t st = sb + s * STAGE_B;
        const uint32_t stAh = st, stAl = st + TILE_B;
        const uint32_t stBh = st + 2 * TILE_B, stBl = st + 3 * TILE_B;

#pragma unroll
        for (int ks = 0; ks < 2; ks++) {
            const uint32_t ko = ks * 32;
            uint32_t bh[4][4], ah[4][4], xl[4][4];
#pragma unroll
            for (int p = 0; p < 4; p++)
                ldsm4(bh[p], stBh + boff + p * 16 * ROWB + ko);
#pragma unroll
            for (int m = 0; m < 4; m++)
                ldsm4(ah[m], stAh + aoff + m * 16 * ROWB + ko);
#pragma unroll
            for (int n = 0; n < 8; n++)
#pragma unroll
                for (int m = 0; m < 4; m++)
                    mma_f32(acc[m][n], ah[m], &bh[n >> 1][(n & 1) * 2]);
#pragma unroll
            for (int p = 0; p < 4; p++)
                ldsm4(xl[p], stBl + boff + p * 16 * ROWB + ko);
#pragma unroll
            for (int n = 0; n < 8; n++)
#pragma unroll
                for (int m = 0; m < 4; m++)
                    mma_f16(accL[m][n], ah[m], &xl[n >> 1][(n & 1) * 2]);
#pragma unroll
            for (int m = 0; m < 4; m++)
                ldsm4(xl[m], stAl + aoff + m * 16 * ROWB + ko);
#pragma unroll
            for (int n = 0; n < 8; n++)
#pragma unroll
                for (int m = 0; m < 4; m++)
                    mma_f16(accL[m][n], xl[m], &bh[n >> 1][(n & 1) * 2]);
        }
        __syncthreads();
        if (kt + 2 < KT) load_stage(s, kt + 2);
    }

    const int rql = lane >> 2, cql = (lane & 3) * 2;
#pragma unroll
    for (int m = 0; m < 4; m++) {
        const int row = bm + mbw + m * 16 + rql;
#pragma unroll
        for (int n = 0; n < 8; n++) {
            const int col = bn + nbw + n * 8 + cql;
            const float bx = bias[col], by = bias[col + 1];
            __half2 lo0 = *(__half2*)&accL[m][n][0];
            __half2 lo1 = *(__half2*)&accL[m][n][1];
            float v0 = acc[m][n][0] + __half2float(lo0.x) + bx;
            float v1 = acc[m][n][1] + __half2float(lo0.y) + by;
            float v2 = acc[m][n][2] + __half2float(lo1.x) + bx;
            float v3 = acc[m][n][3] + __half2float(lo1.y) + by;
            if (SPLIT_OUT) {
                uint32_t h01, l01, h23, l23;
                split2(v0, v1, h01, l01);
                split2(v2, v3, h23, l23);
                *(uint32_t*)(Chi + (size_t)row * N + col) = h01;
                *(uint32_t*)(Clo + (size_t)row * N + col) = l01;
                *(uint32_t*)(Chi + (size_t)(row + 8) * N + col) = h23;
                *(uint32_t*)(Clo + (size_t)(row + 8) * N + col) = l23;
            } else {
                *(float2*)(C + (size_t)row * N + col) = make_float2(v0, v1);
                *(float2*)(C + (size_t)(row + 8) * N + col) = make_float2(v2, v3);
            }
        }
    }
}

// ---------------------------------------------------------------------------
// HMMA flash attention, reduced-term f16:
//   S = Qh*Kh + Qh*Kl    (ql*kh dropped — absorbed as ~2e-4 logit noise)
//   O += P16 * Vh        (single-term PV; P,V single f16)
// All surviving MMAs accumulate in f32.  Smem: Qh + 2 stages x (Kh,Kl,Vh,mask).
// ---------------------------------------------------------------------------
#define AROW 144
#define ATT_QBYTES (128 * AROW)          // 18432
#define ATT_KVTILE (64 * AROW)           // 9216
#define ATT_STAGE (3 * ATT_KVTILE + 256) // 27904
#define ATT_SMEM (ATT_QBYTES + 2 * ATT_STAGE)   // 74240

__global__ __launch_bounds__(256) void attn_hmma(
    const __half* __restrict__ qkv_hi,
    const __half* __restrict__ qkv_lo,
    const float* __restrict__ mask,
    __half* __restrict__ out_hi,
    __half* __restrict__ out_lo)
{
    extern __shared__ char smc[];
    const uint32_t sb = smem_u32(smc);
    const int tid = threadIdx.x, lane = tid & 31, w = tid >> 5;
    const int qt = blockIdx.x * 128;
    const int h = blockIdx.y, b = blockIdx.z;

    // ---- Q load: hi only (128 rows x 64 cols f16 = 1024 16B chunks) ----
#pragma unroll
    for (int i = 0; i < 4; i++) {
        int idx = tid + i * 256;
        int row = idx >> 3, c = idx & 7;
        const __half* g = qkv_hi +
            (size_t)(b * T_SEQ + qt + row) * 3072 + h * 64 + c * 8;
        cpa16(sb + row * AROW + c * 16, g);
    }

    const uint32_t stg0 = sb + ATT_QBYTES;

    auto load_kv = [&](int s, int kt) {
        const uint32_t st = stg0 + s * ATT_STAGE;
        // 3 tiles: 0=Kh 1=Kl 2=Vh, 512 chunks each = 1536 total
#pragma unroll
        for (int i = 0; i < 6; i++) {
            int idx = tid + i * 256;
            int tile = idx >> 9;
            int rem = idx & 511;
            int row = rem >> 3, c = rem & 7;
            const __half* base = (tile == 1) ? qkv_lo : qkv_hi;
            int coff = ((tile < 2) ? 1024 : 2048) + h * 64;
            const __half* g = base +
                (size_t)(b * T_SEQ + kt * 64 + row) * 3072 + coff + c * 8;
            cpa16(st + tile * ATT_KVTILE + row * AROW + c * 16, g);
        }
        if (tid < 16)
            cpa16(st + 3 * ATT_KVTILE + tid * 16,
                  mask + (size_t)b * T_SEQ + kt * 64 + tid * 4);
        asm volatile("cp.async.commit_group;" ::: "memory");
    };

    load_kv(0, 0);
    asm volatile("cp.async.commit_group;" ::: "memory");
    load_kv(1, 1);

    const uint32_t aoffQ = (uint32_t)(w * 16 + (lane & 15)) * AROW +
                           (uint32_t)(lane >> 4) * 16;
    const uint32_t boffK = (uint32_t)((lane >> 4) * 8 + (lane & 7)) * AROW +
                           (uint32_t)((lane >> 3) & 1) * 16;
    const uint32_t voffV = (uint32_t)(lane & 15) * AROW +
                           (uint32_t)(lane >> 4) * 16;

    float mst0 = -1e30f, mst1 = -1e30f, lst0 = 0.f, lst1 = 0.f;
    float O[8][4];
#pragma unroll
    for (int n = 0; n < 8; n++)
#pragma unroll
        for (int j = 0; j < 4; j++) O[n][j] = 0.f;

    const int NKV = T_SEQ / 64;
    for (int kt = 0; kt < NKV; kt++) {
        const int s = kt & 1;
        if (kt + 1 < NKV)
            asm volatile("cp.async.wait_group 1;" ::: "memory");
        else
            asm volatile("cp.async.wait_group 0;" ::: "memory");
        __syncthreads();

        const uint32_t st = stg0 + s * ATT_STAGE;
        const float* mskp = (const float*)(smc + ATT_QBYTES +
                                           s * ATT_STAGE + 3 * ATT_KVTILE);

        // ---- S = Qh*Kh + Qh*Kl (f32 accum) ----
        float S[8][4];
#pragma unroll
        for (int n = 0; n < 8; n++)
#pragma unroll
            for (int j = 0; j < 4; j++) S[n][j] = 0.f;

#pragma unroll
        for (int kg = 0; kg < 4; kg++) {
            uint32_t qh[4];
            ldsm4(qh, sb + aoffQ + kg * 32);
#pragma unroll
            for (int nb = 0; nb < 4; nb++) {
                uint32_t kh[4], kl[4];
                ldsm4(kh, st + boffK + nb * 16 * AROW + kg * 32);
                ldsm4(kl, st + ATT_KVTILE + boffK + nb * 16 * AROW + kg * 32);
                mma_f32(S[2 * nb],     qh, &kh[0]);
                mma_f32(S[2 * nb + 1], qh, &kh[2]);
                mma_f32(S[2 * nb],     qh, &kl[0]);
                mma_f32(S[2 * nb + 1], qh, &kl[2]);
            }
        }

        // ---- scale + double mask + online softmax ----
        float mx0 = -1e30f, mx1 = -1e30f;
#pragma unroll
        for (int n = 0; n < 8; n++) {
            float2 mk = *(const float2*)(mskp + n * 8 + (lane & 3) * 2);
            float m0 = 2.f * mk.x, m1 = 2.f * mk.y;
            S[n][0] = fmaf(S[n][0], 0.125f, m0);
            S[n][1] = fmaf(S[n][1], 0.125f, m1);
            S[n][2] = fmaf(S[n][2], 0.125f, m0);
            S[n][3] = fmaf(S[n][3], 0.125f, m1);
            mx0 = fmaxf(mx0, fmaxf(S[n][0], S[n][1]));
            mx1 = fmaxf(mx1, fmaxf(S[n][2], S[n][3]));
        }
        mx0 = fmaxf(mx0, __shfl_xor_sync(0xffffffffu, mx0, 1));
        mx0 = fmaxf(mx0, __shfl_xor_sync(0xffffffffu, mx0, 2));
        mx1 = fmaxf(mx1, __shfl_xor_sync(0xffffffffu, mx1, 1));
        mx1 = fmaxf(mx1, __shfl_xor_sync(0xffffffffu, mx1, 2));

        const float mn0 = fmaxf(mst0, mx0), mn1 = fmaxf(mst1, mx1);
        const float cr0 = __expf(mst0 - mn0), cr1 = __expf(mst1 - mn1);
        mst0 = mn0; mst1 = mn1;

        float rs0 = 0.f, rs1 = 0.f;
#pragma unroll
        for (int n = 0; n < 8; n++) {
            S[n][0] = __expf(S[n][0] - mn0);
            S[n][1] = __expf(S[n][1] - mn0);
            S[n][2] = __expf(S[n][2] - mn1);
            S[n][3] = __expf(S[n][3] - mn1);
            rs0 += S[n][0] + S[n][1];
            rs1 += S[n][2] + S[n][3];
        }
        rs0 += __shfl_xor_sync(0xffffffffu, rs0, 1);
        rs0 += __shfl_xor_sync(0xffffffffu, rs0, 2);
        rs1 += __shfl_xor_sync(0xffffffffu, rs1, 1);
        rs1 += __shfl_xor_sync(0xffffffffu, rs1, 2);
        lst0 = lst0 * cr0 + rs0;
        lst1 = lst1 * cr1 + rs1;

#pragma unroll
        for (int n = 0; n < 8; n++) {
            O[n][0] *= cr0; O[n][1] *= cr0;
            O[n][2] *= cr1; O[n][3] *= cr1;
        }

        // ---- O += P16 * Vh (single term, f32 accum) ----
#pragma unroll
        for (int kg = 0; kg < 4; kg++) {
            uint32_t ph[4];
            ph[0] = pack2(S[2 * kg][0],     S[2 * kg][1]);
            ph[1] = pack2(S[2 * kg][2],     S[2 * kg][3]);
            ph[2] = pack2(S[2 * kg + 1][0], S[2 * kg + 1][1]);
            ph[3] = pack2(S[2 * kg + 1][2], S[2 * kg + 1][3]);
#pragma unroll
            for (int nb = 0; nb < 4; nb++) {
                uint32_t vh[4];
                ldsm4t(vh, st + 2 * ATT_KVTILE + voffV + kg * 16 * AROW + nb * 32);
                mma_f32(O[2 * nb],     ph, &vh[0]);
                mma_f32(O[2 * nb + 1], ph, &vh[2]);
            }
        }

        __syncthreads();
        if (kt + 2 < NKV) load_kv(s, kt + 2);
    }

    const float inv0 = 1.f / lst0, inv1 = 1.f / lst1;
    const int row0 = b * T_SEQ + qt + w * 16 + (lane >> 2);
    const int colb = h * 64 + (lane & 3) * 2;
#pragma unroll
    for (int n = 0; n < 8; n++) {
        uint32_t h01, l01, h23, l23;
        split2(O[n][0] * inv0, O[n][1] * inv0, h01, l01);
        split2(O[n][2] * inv1, O[n][3] * inv1, h23, l23);
        const size_t o0 = (size_t)row0 * D_MODEL + colb + n * 8;
        const size_t o1 = (size_t)(row0 + 8) * D_MODEL + colb + n * 8;
        *(uint32_t*)(out_hi + o0) = h01;
        *(uint32_t*)(out_lo + o0) = l01;
        *(uint32_t*)(out_hi + o1) = h23;
        *(uint32_t*)(out_lo + o1) = l23;
    }
}

// ---------------------------------------------------------------------------
extern "C" void kernel_launch(void* const* d_in, const int* in_sizes, int n_in,
                              void* d_out, int out_size)
{
    const float* x      = (const float*)d_in[0];
    const float* mask   = (const float*)d_in[1];
    const float* w_attn = (const float*)d_in[2];
    const float* b_attn = (const float*)d_in[3];
    const float* w_proj = (const float*)d_in[4];
    const float* b_proj = (const float*)d_in[5];
    float* out = (float*)d_out;

    __half *qkv_hi, *qkv_lo, *att_hi, *att_lo;
    __half *xa_hi, *xa_lo, *wa_hi, *wa_lo, *wp_hi, *wp_lo;
    cudaGetSymbolAddress((void**)&qkv_hi, g_qkv_hi);
    cudaGetSymbolAddress((void**)&qkv_lo, g_qkv_lo);
    cudaGetSymbolAddress((void**)&att_hi, g_att_hi);
    cudaGetSymbolAddress((void**)&att_lo, g_att_lo);
    cudaGetSymbolAddress((void**)&xa_hi, g_xa_hi);
    cudaGetSymbolAddress((void**)&xa_lo, g_xa_lo);
    cudaGetSymbolAddress((void**)&wa_hi, g_wa_hi);
    cudaGetSymbolAddress((void**)&wa_lo, g_wa_lo);
    cudaGetSymbolAddress((void**)&wp_hi, g_wp_hi);
    cudaGetSymbolAddress((void**)&wp_lo, g_wp_lo);

    cudaFuncSetAttribute(gemm_hmma<0>,
                         cudaFuncAttributeMaxDynamicSharedMemorySize, GEMM_SMEM);
    cudaFuncSetAttribute(gemm_hmma<1>,
                         cudaFuncAttributeMaxDynamicSharedMemorySize, GEMM_SMEM);
    cudaFuncSetAttribute(attn_hmma,
                         cudaFuncAttributeMaxDynamicSharedMemorySize, ATT_SMEM);

    const int nx = BT_ROWS * 1024;

    split_mat<<<nx / 4 / 256, 256>>>(x, xa_hi, xa_lo, nx);
    split_wT<<<dim3(3072 / 32, 1024 / 32), dim3(32, 8)>>>(w_attn, wa_hi, wa_lo, 1024, 3072);
    split_wT<<<dim3(1024 / 32, 1024 / 32), dim3(32, 8)>>>(w_proj, wp_hi, wp_lo, 1024, 1024);

    gemm_hmma<1><<<dim3(3072 / 128, BT_ROWS / 128), 128, GEMM_SMEM>>>(
        xa_hi, xa_lo, wa_hi, wa_lo, b_attn, nullptr, qkv_hi, qkv_lo, 3072, 1024);

    attn_hmma<<<dim3(T_SEQ / 128, 16, 2), 256, ATT_SMEM>>>(
        qkv_hi, qkv_lo, mask, att_hi, att_lo);

    gemm_hmma<0><<<dim3(1024 / 128, BT_ROWS / 128), 128, GEMM_SMEM>>>(
        att_hi, att_lo, wp_hi, wp_lo, b_proj, out, nullptr, nullptr, 1024, 1024);
}

// round 10
// speedup vs baseline: 1.4967x; 1.1709x over previous
#include <cuda_runtime.h>
#include <cuda_fp16.h>
#include <cstdint>

#define T_SEQ 2048
#define D_MODEL 1024
#define BT_ROWS 4096            // B*T

// ---------------------------------------------------------------------------
// Scratch (device globals; no allocations anywhere).
// ---------------------------------------------------------------------------
__device__ __half g_qkv_hi[(size_t)BT_ROWS * 3072];
__device__ __half g_qkv_lo[(size_t)BT_ROWS * 3072];
__device__ __half g_att_hi[(size_t)BT_ROWS * 1024];
__device__ __half g_xa_hi[(size_t)BT_ROWS * 1024];
__device__ __half g_wa_hi[(size_t)3072 * 1024];  // w_attn^T [N,K]
__device__ __half g_wa_lo[(size_t)3072 * 1024];
__device__ __half g_wp_hi[(size_t)1024 * 1024];  // w_proj^T [N,K]
__device__ __half g_wp_lo[(size_t)1024 * 1024];

// ---------------------------------------------------------------------------
// Helpers (plain sm_80-era PTX only)
// ---------------------------------------------------------------------------
__device__ __forceinline__ uint32_t smem_u32(const void* p) {
    uint32_t a;
    asm("{ .reg .u64 t; cvta.to.shared.u64 t, %1; cvt.u32.u64 %0, t; }"
        : "=r"(a) : "l"(p));
    return a;
}

__device__ __forceinline__ void cpa16(uint32_t s, const void* g) {
    asm volatile("cp.async.cg.shared.global [%0], [%1], 16;" :: "r"(s), "l"(g));
}

__device__ __forceinline__ void ldsm4(uint32_t* r, uint32_t a) {
    asm volatile("ldmatrix.sync.aligned.m8n8.x4.shared.b16 {%0,%1,%2,%3}, [%4];"
                 : "=r"(r[0]), "=r"(r[1]), "=r"(r[2]), "=r"(r[3]) : "r"(a));
}

__device__ __forceinline__ void ldsm4t(uint32_t* r, uint32_t a) {
    asm volatile("ldmatrix.sync.aligned.m8n8.x4.trans.shared.b16 {%0,%1,%2,%3}, [%4];"
                 : "=r"(r[0]), "=r"(r[1]), "=r"(r[2]), "=r"(r[3]) : "r"(a));
}

// f16 x f16 -> f32 accumulate
__device__ __forceinline__ void mma_f32(float* d, const uint32_t* a,
                                        const uint32_t* b) {
    asm volatile(
        "mma.sync.aligned.m16n8k16.row.col.f32.f16.f16.f32 "
        "{%0,%1,%2,%3}, {%4,%5,%6,%7}, {%8,%9}, {%0,%1,%2,%3};"
        : "+f"(d[0]), "+f"(d[1]), "+f"(d[2]), "+f"(d[3])
        : "r"(a[0]), "r"(a[1]), "r"(a[2]), "r"(a[3]), "r"(b[0]), "r"(b[1]));
}

// f16 x f16 -> f16 accumulate (GEMM lo cross-term)
__device__ __forceinline__ void mma_f16(uint32_t* d, const uint32_t* a,
                                        const uint32_t* b) {
    asm volatile(
        "mma.sync.aligned.m16n8k16.row.col.f16.f16.f16.f16 "
        "{%0,%1}, {%2,%3,%4,%5}, {%6,%7}, {%0,%1};"
        : "+r"(d[0]), "+r"(d[1])
        : "r"(a[0]), "r"(a[1]), "r"(a[2]), "r"(a[3]), "r"(b[0]), "r"(b[1]));
}

// split a pair of fp32 into packed f16x2 hi and lo
__device__ __forceinline__ void split2(float a, float b, uint32_t& hi, uint32_t& lo) {
    __half2 h, l;
    h.x = __float2half(a);
    h.y = __float2half(b);
    l.x = __float2half(a - __half2float(h.x));
    l.y = __float2half(b - __half2float(h.y));
    hi = *(uint32_t*)&h;
    lo = *(uint32_t*)&l;
}

// pack a pair of fp32 -> f16x2 (single rounding)
__device__ __forceinline__ uint32_t pack2(float a, float b) {
    __half2 h;
    h.x = __float2half(a);
    h.y = __float2half(b);
    return *(uint32_t*)&h;
}

// ---------------------------------------------------------------------------
// Conversions
// ---------------------------------------------------------------------------
// fp32 -> f16 (hi only), for x
__global__ void cvt_mat(const float* __restrict__ in,
                        __half* __restrict__ hi, int n) {
    int i = (blockIdx.x * blockDim.x + threadIdx.x) * 4;
    if (i >= n) return;
    float4 v = *(const float4*)(in + i);
    ((uint32_t*)(hi + i))[0] = pack2(v.x, v.y);
    ((uint32_t*)(hi + i))[1] = pack2(v.z, v.w);
}

// w:[Kd,Nd] row-major -> out hi/lo:[Nd,Kd] (transposed), split to f16
__global__ void split_wT(const float* __restrict__ w,
                         __half* __restrict__ hi,
                         __half* __restrict__ lo, int Kd, int Nd) {
    __shared__ float t[32][33];
    int k0 = blockIdx.y * 32, n0 = blockIdx.x * 32;
    int tx = threadIdx.x, ty = threadIdx.y;   // block (32,8)
#pragma unroll
    for (int j = 0; j < 32; j += 8)
        t[ty + j][tx] = w[(size_t)(k0 + ty + j) * Nd + n0 + tx];
    __syncthreads();
#pragma unroll
    for (int j = 0; j < 32; j += 8) {
        float v = t[tx][ty + j];
        __half h = __float2half(v);
        size_t o = (size_t)(n0 + ty + j) * Kd + k0 + tx;
        hi[o] = h;
        lo[o] = __float2half(v - __half2float(h));
    }
}

// ---------------------------------------------------------------------------
// HMMA 2-term GEMM: C = Ah @ (Bh + Bl)^T + bias  (A-lo term dropped; ~2e-4)
// 128x128 CTA tile, 4 warps of 64x64, BK=32, 2-stage cp.async pipeline.
// hi*hi -> f32 accum; Ah*Bl -> chained f16 accum, merged at epilogue.
// ---------------------------------------------------------------------------
#define GBK 32
#define ROWB 80
#define TILE_B (128 * ROWB)
#define STAGE_B (3 * TILE_B)          // Ah, Bh, Bl
#define GEMM_SMEM (2 * STAGE_B)       // 61440

template <int SPLIT_OUT>
__global__ __launch_bounds__(128) void gemm_hmma(
    const __half* __restrict__ Ahi,
    const __half* __restrict__ Bhi, const __half* __restrict__ Blo,
    const float* __restrict__ bias, float* __restrict__ C,
    __half* __restrict__ Chi, __half* __restrict__ Clo,
    int N, int K)
{
    extern __shared__ char smc[];
    const uint32_t sb = smem_u32(smc);
    const int tid = threadIdx.x, lane = tid & 31, wid = tid >> 5;
    const int bm = blockIdx.y * 128, bn = blockIdx.x * 128;
    const int mbw = (wid & 1) * 64;
    const int nbw = (wid >> 1) * 64;

    float acc[4][8][4];
    uint32_t accL[4][8][2];
#pragma unroll
    for (int m = 0; m < 4; m++)
#pragma unroll
        for (int n = 0; n < 8; n++) {
#pragma unroll
            for (int j = 0; j < 4; j++) acc[m][n][j] = 0.f;
            accL[m][n][0] = 0u; accL[m][n][1] = 0u;
        }

    const uint32_t aoff =
        (uint32_t)(mbw + (lane & 15)) * ROWB + (uint32_t)(lane >> 4) * 16;
    const uint32_t boff =
        (uint32_t)(nbw + (lane >> 4) * 8 + (lane & 7)) * ROWB +
        (uint32_t)((lane >> 3) & 1) * 16;

    auto load_stage = [&](int s, int kt) {
        const uint32_t st = sb + s * STAGE_B;
        const int kc = kt * GBK;
        const __half* gp[3] = {Ahi, Bhi, Blo};
#pragma unroll
        for (int tile = 0; tile < 3; tile++) {
            const int rbase = (tile == 0) ? bm : bn;
            const uint32_t td = st + tile * TILE_B;
#pragma unroll
            for (int i = 0; i < 2; i++) {
                int p = tid + i * 128;
                int row = p >> 1, hf = p & 1;
                const __half* g =
                    gp[tile] + (size_t)(rbase + row) * K + kc + hf * 16;
                uint32_t sd = td + row * ROWB + hf * 32;
                cpa16(sd, g);
                cpa16(sd + 16, g + 8);
            }
        }
        asm volatile("cp.async.commit_group;" ::: "memory");
    };

    const int KT = K / GBK;
    load_stage(0, 0);
    load_stage(1, 1);

    for (int kt = 0; kt < KT; kt++) {
        const int s = kt & 1;
        if (kt + 1 < KT)
            asm volatile("cp.async.wait_group 1;" ::: "memory");
        else
            asm volatile("cp.async.wait_group 0;" ::: "memory");
        __syncthreads();

        const uint32_t st = sb + s * STAGE_B;
        const uint32_t stAh = st;
        const uint32_t stBh = st + TILE_B, stBl = st + 2 * TILE_B;

#pragma unroll
        for (int ks = 0; ks < 2; ks++) {
            const uint32_t ko = ks * 32;
            uint32_t bh[4][4], ah[4][4], bl[4][4];
#pragma unroll
            for (int p = 0; p < 4; p++)
                ldsm4(bh[p], stBh + boff + p * 16 * ROWB + ko);
#pragma unroll
            for (int m = 0; m < 4; m++)
                ldsm4(ah[m], stAh + aoff + m * 16 * ROWB + ko);
#pragma unroll
            for (int n = 0; n < 8; n++)
#pragma unroll
                for (int m = 0; m < 4; m++)
                    mma_f32(acc[m][n], ah[m], &bh[n >> 1][(n & 1) * 2]);
#pragma unroll
            for (int p = 0; p < 4; p++)
                ldsm4(bl[p], stBl + boff + p * 16 * ROWB + ko);
#pragma unroll
            for (int n = 0; n < 8; n++)
#pragma unroll
                for (int m = 0; m < 4; m++)
                    mma_f16(accL[m][n], ah[m], &bl[n >> 1][(n & 1) * 2]);
        }
        __syncthreads();
        if (kt + 2 < KT) load_stage(s, kt + 2);
    }

    // Epilogue: merge f16 lo-accumulator, add bias, store
    const int rql = lane >> 2, cql = (lane & 3) * 2;
#pragma unroll
    for (int m = 0; m < 4; m++) {
        const int row = bm + mbw + m * 16 + rql;
#pragma unroll
        for (int n = 0; n < 8; n++) {
            const int col = bn + nbw + n * 8 + cql;
            const float bx = bias[col], by = bias[col + 1];
            __half2 lo0 = *(__half2*)&accL[m][n][0];
            __half2 lo1 = *(__half2*)&accL[m][n][1];
            float v0 = acc[m][n][0] + __half2float(lo0.x) + bx;
            float v1 = acc[m][n][1] + __half2float(lo0.y) + by;
            float v2 = acc[m][n][2] + __half2float(lo1.x) + bx;
            float v3 = acc[m][n][3] + __half2float(lo1.y) + by;
            if (SPLIT_OUT) {
                uint32_t h01, l01, h23, l23;
                split2(v0, v1, h01, l01);
                split2(v2, v3, h23, l23);
                *(uint32_t*)(Chi + (size_t)row * N + col) = h01;
                *(uint32_t*)(Clo + (size_t)row * N + col) = l01;
                *(uint32_t*)(Chi + (size_t)(row + 8) * N + col) = h23;
                *(uint32_t*)(Clo + (size_t)(row + 8) * N + col) = l23;
            } else {
                *(float2*)(C + (size_t)row * N + col) = make_float2(v0, v1);
                *(float2*)(C + (size_t)(row + 8) * N + col) = make_float2(v2, v3);
            }
        }
    }
}

// ---------------------------------------------------------------------------
// HMMA flash attention, reduced-term f16 (R9 inner loop):
//   S = Qh*Kh + Qh*Kl ;  O += P16 * Vh ;  output hi only (proj is 2-term).
// ---------------------------------------------------------------------------
#define AROW 144
#define ATT_QBYTES (128 * AROW)          // 18432
#define ATT_KVTILE (64 * AROW)           // 9216
#define ATT_STAGE (3 * ATT_KVTILE + 256) // 27904
#define ATT_SMEM (ATT_QBYTES + 2 * ATT_STAGE)   // 74240

__global__ __launch_bounds__(256) void attn_hmma(
    const __half* __restrict__ qkv_hi,
    const __half* __restrict__ qkv_lo,
    const float* __restrict__ mask,
    __half* __restrict__ out_hi)
{
    extern __shared__ char smc[];
    const uint32_t sb = smem_u32(smc);
    const int tid = threadIdx.x, lane = tid & 31, w = tid >> 5;
    const int qt = blockIdx.x * 128;
    const int h = blockIdx.y, b = blockIdx.z;

    // ---- Q load: hi only ----
#pragma unroll
    for (int i = 0; i < 4; i++) {
        int idx = tid + i * 256;
        int row = idx >> 3, c = idx & 7;
        const __half* g = qkv_hi +
            (size_t)(b * T_SEQ + qt + row) * 3072 + h * 64 + c * 8;
        cpa16(sb + row * AROW + c * 16, g);
    }

    const uint32_t stg0 = sb + ATT_QBYTES;

    auto load_kv = [&](int s, int kt) {
        const uint32_t st = stg0 + s * ATT_STAGE;
#pragma unroll
        for (int i = 0; i < 6; i++) {
            int idx = tid + i * 256;
            int tile = idx >> 9;
            int rem = idx & 511;
            int row = rem >> 3, c = rem & 7;
            const __half* base = (tile == 1) ? qkv_lo : qkv_hi;
            int coff = ((tile < 2) ? 1024 : 2048) + h * 64;
            const __half* g = base +
                (size_t)(b * T_SEQ + kt * 64 + row) * 3072 + coff + c * 8;
            cpa16(st + tile * ATT_KVTILE + row * AROW + c * 16, g);
        }
        if (tid < 16)
            cpa16(st + 3 * ATT_KVTILE + tid * 16,
                  mask + (size_t)b * T_SEQ + kt * 64 + tid * 4);
        asm volatile("cp.async.commit_group;" ::: "memory");
    };

    load_kv(0, 0);
    asm volatile("cp.async.commit_group;" ::: "memory");
    load_kv(1, 1);

    const uint32_t aoffQ = (uint32_t)(w * 16 + (lane & 15)) * AROW +
                           (uint32_t)(lane >> 4) * 16;
    const uint32_t boffK = (uint32_t)((lane >> 4) * 8 + (lane & 7)) * AROW +
                           (uint32_t)((lane >> 3) & 1) * 16;
    const uint32_t voffV = (uint32_t)(lane & 15) * AROW +
                           (uint32_t)(lane >> 4) * 16;

    float mst0 = -1e30f, mst1 = -1e30f, lst0 = 0.f, lst1 = 0.f;
    float O[8][4];
#pragma unroll
    for (int n = 0; n < 8; n++)
#pragma unroll
        for (int j = 0; j < 4; j++) O[n][j] = 0.f;

    const int NKV = T_SEQ / 64;
    for (int kt = 0; kt < NKV; kt++) {
        const int s = kt & 1;
        if (kt + 1 < NKV)
            asm volatile("cp.async.wait_group 1;" ::: "memory");
        else
            asm volatile("cp.async.wait_group 0;" ::: "memory");
        __syncthreads();

        const uint32_t st = stg0 + s * ATT_STAGE;
        const float* mskp = (const float*)(smc + ATT_QBYTES +
                                           s * ATT_STAGE + 3 * ATT_KVTILE);

        float S[8][4];
#pragma unroll
        for (int n = 0; n < 8; n++)
#pragma unroll
            for (int j = 0; j < 4; j++) S[n][j] = 0.f;

#pragma unroll
        for (int kg = 0; kg < 4; kg++) {
            uint32_t qh[4];
            ldsm4(qh, sb + aoffQ + kg * 32);
#pragma unroll
            for (int nb = 0; nb < 4; nb++) {
                uint32_t kh[4], kl[4];
                ldsm4(kh, st + boffK + nb * 16 * AROW + kg * 32);
                ldsm4(kl, st + ATT_KVTILE + boffK + nb * 16 * AROW + kg * 32);
                mma_f32(S[2 * nb],     qh, &kh[0]);
                mma_f32(S[2 * nb + 1], qh, &kh[2]);
                mma_f32(S[2 * nb],     qh, &kl[0]);
                mma_f32(S[2 * nb + 1], qh, &kl[2]);
            }
        }

        float mx0 = -1e30f, mx1 = -1e30f;
#pragma unroll
        for (int n = 0; n < 8; n++) {
            float2 mk = *(const float2*)(mskp + n * 8 + (lane & 3) * 2);
            float m0 = 2.f * mk.x, m1 = 2.f * mk.y;
            S[n][0] = fmaf(S[n][0], 0.125f, m0);
            S[n][1] = fmaf(S[n][1], 0.125f, m1);
            S[n][2] = fmaf(S[n][2], 0.125f, m0);
            S[n][3] = fmaf(S[n][3], 0.125f, m1);
            mx0 = fmaxf(mx0, fmaxf(S[n][0], S[n][1]));
            mx1 = fmaxf(mx1, fmaxf(S[n][2], S[n][3]));
        }
        mx0 = fmaxf(mx0, __shfl_xor_sync(0xffffffffu, mx0, 1));
        mx0 = fmaxf(mx0, __shfl_xor_sync(0xffffffffu, mx0, 2));
        mx1 = fmaxf(mx1, __shfl_xor_sync(0xffffffffu, mx1, 1));
        mx1 = fmaxf(mx1, __shfl_xor_sync(0xffffffffu, mx1, 2));

        const float mn0 = fmaxf(mst0, mx0), mn1 = fmaxf(mst1, mx1);
        const float cr0 = __expf(mst0 - mn0), cr1 = __expf(mst1 - mn1);
        mst0 = mn0; mst1 = mn1;

        float rs0 = 0.f, rs1 = 0.f;
#pragma unroll
        for (int n = 0; n < 8; n++) {
            S[n][0] = __expf(S[n][0] - mn0);
            S[n][1] = __expf(S[n][1] - mn0);
            S[n][2] = __expf(S[n][2] - mn1);
            S[n][3] = __expf(S[n][3] - mn1);
            rs0 += S[n][0] + S[n][1];
            rs1 += S[n][2] + S[n][3];
        }
        rs0 += __shfl_xor_sync(0xffffffffu, rs0, 1);
        rs0 += __shfl_xor_sync(0xffffffffu, rs0, 2);
        rs1 += __shfl_xor_sync(0xffffffffu, rs1, 1);
        rs1 += __shfl_xor_sync(0xffffffffu, rs1, 2);
        lst0 = lst0 * cr0 + rs0;
        lst1 = lst1 * cr1 + rs1;

#pragma unroll
        for (int n = 0; n < 8; n++) {
            O[n][0] *= cr0; O[n][1] *= cr0;
            O[n][2] *= cr1; O[n][3] *= cr1;
        }

#pragma unroll
        for (int kg = 0; kg < 4; kg++) {
            uint32_t ph[4];
            ph[0] = pack2(S[2 * kg][0],     S[2 * kg][1]);
            ph[1] = pack2(S[2 * kg][2],     S[2 * kg][3]);
            ph[2] = pack2(S[2 * kg + 1][0], S[2 * kg + 1][1]);
            ph[3] = pack2(S[2 * kg + 1][2], S[2 * kg + 1][3]);
#pragma unroll
            for (int nb = 0; nb < 4; nb++) {
                uint32_t vh[4];
                ldsm4t(vh, st + 2 * ATT_KVTILE + voffV + kg * 16 * AROW + nb * 32);
                mma_f32(O[2 * nb],     ph, &vh[0]);
                mma_f32(O[2 * nb + 1], ph, &vh[2]);
            }
        }

        __syncthreads();
        if (kt + 2 < NKV) load_kv(s, kt + 2);
    }

    const float inv0 = 1.f / lst0, inv1 = 1.f / lst1;
    const int row0 = b * T_SEQ + qt + w * 16 + (lane >> 2);
    const int colb = h * 64 + (lane & 3) * 2;
#pragma unroll
    for (int n = 0; n < 8; n++) {
        const size_t o0 = (size_t)row0 * D_MODEL + colb + n * 8;
        const size_t o1 = (size_t)(row0 + 8) * D_MODEL + colb + n * 8;
        *(uint32_t*)(out_hi + o0) = pack2(O[n][0] * inv0, O[n][1] * inv0);
        *(uint32_t*)(out_hi + o1) = pack2(O[n][2] * inv1, O[n][3] * inv1);
    }
}

// ---------------------------------------------------------------------------
extern "C" void kernel_launch(void* const* d_in, const int* in_sizes, int n_in,
                              void* d_out, int out_size)
{
    const float* x      = (const float*)d_in[0];
    const float* mask   = (const float*)d_in[1];
    const float* w_attn = (const float*)d_in[2];
    const float* b_attn = (const float*)d_in[3];
    const float* w_proj = (const float*)d_in[4];
    const float* b_proj = (const float*)d_in[5];
    float* out = (float*)d_out;

    __half *qkv_hi, *qkv_lo, *att_hi;
    __half *xa_hi, *wa_hi, *wa_lo, *wp_hi, *wp_lo;
    cudaGetSymbolAddress((void**)&qkv_hi, g_qkv_hi);
    cudaGetSymbolAddress((void**)&qkv_lo, g_qkv_lo);
    cudaGetSymbolAddress((void**)&att_hi, g_att_hi);
    cudaGetSymbolAddress((void**)&xa_hi, g_xa_hi);
    cudaGetSymbolAddress((void**)&wa_hi, g_wa_hi);
    cudaGetSymbolAddress((void**)&wa_lo, g_wa_lo);
    cudaGetSymbolAddress((void**)&wp_hi, g_wp_hi);
    cudaGetSymbolAddress((void**)&wp_lo, g_wp_lo);

    cudaFuncSetAttribute(gemm_hmma<0>,
                         cudaFuncAttributeMaxDynamicSharedMemorySize, GEMM_SMEM);
    cudaFuncSetAttribute(gemm_hmma<1>,
                         cudaFuncAttributeMaxDynamicSharedMemorySize, GEMM_SMEM);
    cudaFuncSetAttribute(attn_hmma,
                         cudaFuncAttributeMaxDynamicSharedMemorySize, ATT_SMEM);

    const int nx = BT_ROWS * 1024;

    // 1) conversions: x -> f16 hi; weights -> f16 hi/lo transposed
    cvt_mat<<<nx / 4 / 256, 256>>>(x, xa_hi, nx);
    split_wT<<<dim3(3072 / 32, 1024 / 32), dim3(32, 8)>>>(w_attn, wa_hi, wa_lo, 1024, 3072);
    split_wT<<<dim3(1024 / 32, 1024 / 32), dim3(32, 8)>>>(w_proj, wp_hi, wp_lo, 1024, 1024);

    // 2) qkv = xh @ (Wh + Wl) + b  -> f16 hi/lo (fused split epilogue)
    gemm_hmma<1><<<dim3(3072 / 128, BT_ROWS / 128), 128, GEMM_SMEM>>>(
        xa_hi, wa_hi, wa_lo, b_attn, nullptr, qkv_hi, qkv_lo, 3072, 1024);

    // 3) attention -> att hi only
    attn_hmma<<<dim3(T_SEQ / 128, 16, 2), 256, ATT_SMEM>>>(
        qkv_hi, qkv_lo, mask, att_hi);

    // 4) out = ah @ (Wph + Wpl) + b  (fp32 out)
    gemm_hmma<0><<<dim3(1024 / 128, BT_ROWS / 128), 128, GEMM_SMEM>>>(
        att_hi, wp_hi, wp_lo, b_proj, out, nullptr, nullptr, 1024, 1024);
}

// round 11
// speedup vs baseline: 1.5896x; 1.0620x over previous
#include <cuda_runtime.h>
#include <cuda_fp16.h>
#include <cstdint>

#define T_SEQ 2048
#define D_MODEL 1024
#define BT_ROWS 4096            // B*T

// ---------------------------------------------------------------------------
// Scratch (device globals; no allocations anywhere).
// ---------------------------------------------------------------------------
__device__ __half g_qkv_hi[(size_t)BT_ROWS * 3072];
__device__ __half g_qkv_lo[(size_t)BT_ROWS * 3072];
__device__ __half g_att_hi[(size_t)BT_ROWS * 1024];
__device__ __half g_xa_hi[(size_t)BT_ROWS * 1024];
__device__ __half g_wa_hi[(size_t)3072 * 1024];  // w_attn^T [N,K]
__device__ __half g_wa_lo[(size_t)3072 * 1024];
__device__ __half g_wp_hi[(size_t)1024 * 1024];  // w_proj^T [N,K]
__device__ __half g_wp_lo[(size_t)1024 * 1024];

// ---------------------------------------------------------------------------
// Helpers (plain sm_80-era PTX only)
// ---------------------------------------------------------------------------
__device__ __forceinline__ uint32_t smem_u32(const void* p) {
    uint32_t a;
    asm("{ .reg .u64 t; cvta.to.shared.u64 t, %1; cvt.u32.u64 %0, t; }"
        : "=r"(a) : "l"(p));
    return a;
}

__device__ __forceinline__ void cpa16(uint32_t s, const void* g) {
    asm volatile("cp.async.cg.shared.global [%0], [%1], 16;" :: "r"(s), "l"(g));
}

__device__ __forceinline__ void ldsm4(uint32_t* r, uint32_t a) {
    asm volatile("ldmatrix.sync.aligned.m8n8.x4.shared.b16 {%0,%1,%2,%3}, [%4];"
                 : "=r"(r[0]), "=r"(r[1]), "=r"(r[2]), "=r"(r[3]) : "r"(a));
}

__device__ __forceinline__ void ldsm4t(uint32_t* r, uint32_t a) {
    asm volatile("ldmatrix.sync.aligned.m8n8.x4.trans.shared.b16 {%0,%1,%2,%3}, [%4];"
                 : "=r"(r[0]), "=r"(r[1]), "=r"(r[2]), "=r"(r[3]) : "r"(a));
}

// f16 x f16 -> f32 accumulate
__device__ __forceinline__ void mma_f32(float* d, const uint32_t* a,
                                        const uint32_t* b) {
    asm volatile(
        "mma.sync.aligned.m16n8k16.row.col.f32.f16.f16.f32 "
        "{%0,%1,%2,%3}, {%4,%5,%6,%7}, {%8,%9}, {%0,%1,%2,%3};"
        : "+f"(d[0]), "+f"(d[1]), "+f"(d[2]), "+f"(d[3])
        : "r"(a[0]), "r"(a[1]), "r"(a[2]), "r"(a[3]), "r"(b[0]), "r"(b[1]));
}

// f16 x f16 -> f16 accumulate (GEMM lo cross-term)
__device__ __forceinline__ void mma_f16(uint32_t* d, const uint32_t* a,
                                        const uint32_t* b) {
    asm volatile(
        "mma.sync.aligned.m16n8k16.row.col.f16.f16.f16.f16 "
        "{%0,%1}, {%2,%3,%4,%5}, {%6,%7}, {%0,%1};"
        : "+r"(d[0]), "+r"(d[1])
        : "r"(a[0]), "r"(a[1]), "r"(a[2]), "r"(a[3]), "r"(b[0]), "r"(b[1]));
}

// split a pair of fp32 into packed f16x2 hi and lo
__device__ __forceinline__ void split2(float a, float b, uint32_t& hi, uint32_t& lo) {
    __half2 h, l;
    h.x = __float2half(a);
    h.y = __float2half(b);
    l.x = __float2half(a - __half2float(h.x));
    l.y = __float2half(b - __half2float(h.y));
    hi = *(uint32_t*)&h;
    lo = *(uint32_t*)&l;
}

// pack a pair of fp32 -> f16x2 (single rounding)
__device__ __forceinline__ uint32_t pack2(float a, float b) {
    __half2 h;
    h.x = __float2half(a);
    h.y = __float2half(b);
    return *(uint32_t*)&h;
}

// ---------------------------------------------------------------------------
// Conversions
// ---------------------------------------------------------------------------
__global__ void cvt_mat(const float* __restrict__ in,
                        __half* __restrict__ hi, int n) {
    int i = (blockIdx.x * blockDim.x + threadIdx.x) * 4;
    if (i >= n) return;
    float4 v = *(const float4*)(in + i);
    ((uint32_t*)(hi + i))[0] = pack2(v.x, v.y);
    ((uint32_t*)(hi + i))[1] = pack2(v.z, v.w);
}

// w:[Kd,Nd] row-major -> out hi/lo:[Nd,Kd] (transposed), split to f16
__global__ void split_wT(const float* __restrict__ w,
                         __half* __restrict__ hi,
                         __half* __restrict__ lo, int Kd, int Nd) {
    __shared__ float t[32][33];
    int k0 = blockIdx.y * 32, n0 = blockIdx.x * 32;
    int tx = threadIdx.x, ty = threadIdx.y;   // block (32,8)
#pragma unroll
    for (int j = 0; j < 32; j += 8)
        t[ty + j][tx] = w[(size_t)(k0 + ty + j) * Nd + n0 + tx];
    __syncthreads();
#pragma unroll
    for (int j = 0; j < 32; j += 8) {
        float v = t[tx][ty + j];
        __half h = __float2half(v);
        size_t o = (size_t)(n0 + ty + j) * Kd + k0 + tx;
        hi[o] = h;
        lo[o] = __float2half(v - __half2float(h));
    }
}

// ---------------------------------------------------------------------------
// HMMA 2-term GEMM: C = Ah @ (Bh + Bl)^T + bias
// 128x128 CTA tile, 4 warps of 64x64, BK=32, 3-stage cp.async pipeline with
// EARLY ISSUE (load kt+2 before computing kt -> ~2 iters of load latency slack).
// ---------------------------------------------------------------------------
#define GBK 32
#define ROWB 80
#define TILE_B (128 * ROWB)
#define STAGE_B (3 * TILE_B)          // Ah, Bh, Bl  (30720)
#define GEMM_SMEM (3 * STAGE_B)       // 92160 (3 stages)

template <int SPLIT_OUT>
__global__ __launch_bounds__(128) void gemm_hmma(
    const __half* __restrict__ Ahi,
    const __half* __restrict__ Bhi, const __half* __restrict__ Blo,
    const float* __restrict__ bias, float* __restrict__ C,
    __half* __restrict__ Chi, __half* __restrict__ Clo,
    int N, int K)
{
    extern __shared__ char smc[];
    const uint32_t sb = smem_u32(smc);
    const int tid = threadIdx.x, lane = tid & 31, wid = tid >> 5;
    const int bm = blockIdx.y * 128, bn = blockIdx.x * 128;
    const int mbw = (wid & 1) * 64;
    const int nbw = (wid >> 1) * 64;

    float acc[4][8][4];
    uint32_t accL[4][8][2];
#pragma unroll
    for (int m = 0; m < 4; m++)
#pragma unroll
        for (int n = 0; n < 8; n++) {
#pragma unroll
            for (int j = 0; j < 4; j++) acc[m][n][j] = 0.f;
            accL[m][n][0] = 0u; accL[m][n][1] = 0u;
        }

    const uint32_t aoff =
        (uint32_t)(mbw + (lane & 15)) * ROWB + (uint32_t)(lane >> 4) * 16;
    const uint32_t boff =
        (uint32_t)(nbw + (lane >> 4) * 8 + (lane & 7)) * ROWB +
        (uint32_t)((lane >> 3) & 1) * 16;

    auto load_stage = [&](int s, int kt) {
        const uint32_t st = sb + s * STAGE_B;
        const int kc = kt * GBK;
        const __half* gp[3] = {Ahi, Bhi, Blo};
#pragma unroll
        for (int tile = 0; tile < 3; tile++) {
            const int rbase = (tile == 0) ? bm : bn;
            const uint32_t td = st + tile * TILE_B;
#pragma unroll
            for (int i = 0; i < 2; i++) {
                int p = tid + i * 128;
                int row = p >> 1, hf = p & 1;
                const __half* g =
                    gp[tile] + (size_t)(rbase + row) * K + kc + hf * 16;
                uint32_t sd = td + row * ROWB + hf * 32;
                cpa16(sd, g);
                cpa16(sd + 16, g + 8);
            }
        }
        asm volatile("cp.async.commit_group;" ::: "memory");
    };

    const int KT = K / GBK;
    load_stage(0, 0);
    load_stage(1, 1);

    for (int kt = 0; kt < KT; kt++) {
        const int s = kt % 3;
        if (kt + 1 < KT)
            asm volatile("cp.async.wait_group 1;" ::: "memory");
        else
            asm volatile("cp.async.wait_group 0;" ::: "memory");
        __syncthreads();     // stage kt visible to all; stage (kt+2)%3 free

        if (kt + 2 < KT) load_stage((kt + 2) % 3, kt + 2);  // early issue

        const uint32_t st = sb + s * STAGE_B;
        const uint32_t stAh = st;
        const uint32_t stBh = st + TILE_B, stBl = st + 2 * TILE_B;

#pragma unroll
        for (int ks = 0; ks < 2; ks++) {
            const uint32_t ko = ks * 32;
            uint32_t bh[4][4], ah[4][4], bl[4][4];
#pragma unroll
            for (int p = 0; p < 4; p++)
                ldsm4(bh[p], stBh + boff + p * 16 * ROWB + ko);
#pragma unroll
            for (int m = 0; m < 4; m++)
                ldsm4(ah[m], stAh + aoff + m * 16 * ROWB + ko);
#pragma unroll
            for (int n = 0; n < 8; n++)
#pragma unroll
                for (int m = 0; m < 4; m++)
                    mma_f32(acc[m][n], ah[m], &bh[n >> 1][(n & 1) * 2]);
#pragma unroll
            for (int p = 0; p < 4; p++)
                ldsm4(bl[p], stBl + boff + p * 16 * ROWB + ko);
#pragma unroll
            for (int n = 0; n < 8; n++)
#pragma unroll
                for (int m = 0; m < 4; m++)
                    mma_f16(accL[m][n], ah[m], &bl[n >> 1][(n & 1) * 2]);
        }
        // no trailing sync: next iteration's top sync protects reuse
    }

    // Epilogue
    const int rql = lane >> 2, cql = (lane & 3) * 2;
#pragma unroll
    for (int m = 0; m < 4; m++) {
        const int row = bm + mbw + m * 16 + rql;
#pragma unroll
        for (int n = 0; n < 8; n++) {
            const int col = bn + nbw + n * 8 + cql;
            const float bx = bias[col], by = bias[col + 1];
            __half2 lo0 = *(__half2*)&accL[m][n][0];
            __half2 lo1 = *(__half2*)&accL[m][n][1];
            float v0 = acc[m][n][0] + __half2float(lo0.x) + bx;
            float v1 = acc[m][n][1] + __half2float(lo0.y) + by;
            float v2 = acc[m][n][2] + __half2float(lo1.x) + bx;
            float v3 = acc[m][n][3] + __half2float(lo1.y) + by;
            if (SPLIT_OUT) {
                uint32_t h01, l01, h23, l23;
                split2(v0, v1, h01, l01);
                split2(v2, v3, h23, l23);
                *(uint32_t*)(Chi + (size_t)row * N + col) = h01;
                *(uint32_t*)(Clo + (size_t)row * N + col) = l01;
                *(uint32_t*)(Chi + (size_t)(row + 8) * N + col) = h23;
                *(uint32_t*)(Clo + (size_t)(row + 8) * N + col) = l23;
            } else {
                *(float2*)(C + (size_t)row * N + col) = make_float2(v0, v1);
                *(float2*)(C + (size_t)(row + 8) * N + col) = make_float2(v2, v3);
            }
        }
    }
}

// ---------------------------------------------------------------------------
// HMMA flash attention (R10 math), 3-stage early-issue pipeline + hoisted
// Q fragments (Q is kt-invariant; ldsm once instead of every iteration).
//   S = Qh*Kh + Qh*Kl ;  O += P16 * Vh ;  output hi only.
// Smem: Q 18432 + 3 x 27904 = 102144.
// ---------------------------------------------------------------------------
#define AROW 144
#define ATT_QBYTES (128 * AROW)          // 18432
#define ATT_KVTILE (64 * AROW)           // 9216
#define ATT_STAGE (3 * ATT_KVTILE + 256) // 27904
#define ATT_SMEM (ATT_QBYTES + 3 * ATT_STAGE)   // 102144

__global__ __launch_bounds__(256) void attn_hmma(
    const __half* __restrict__ qkv_hi,
    const __half* __restrict__ qkv_lo,
    const float* __restrict__ mask,
    __half* __restrict__ out_hi)
{
    extern __shared__ char smc[];
    const uint32_t sb = smem_u32(smc);
    const int tid = threadIdx.x, lane = tid & 31, w = tid >> 5;
    const int qt = blockIdx.x * 128;
    const int h = blockIdx.y, b = blockIdx.z;

    // ---- Q load (hi only), committed with kv0 as one group ----
#pragma unroll
    for (int i = 0; i < 4; i++) {
        int idx = tid + i * 256;
        int row = idx >> 3, c = idx & 7;
        const __half* g = qkv_hi +
            (size_t)(b * T_SEQ + qt + row) * 3072 + h * 64 + c * 8;
        cpa16(sb + row * AROW + c * 16, g);
    }

    const uint32_t stg0 = sb + ATT_QBYTES;

    auto load_kv = [&](int s, int kt) {
        const uint32_t st = stg0 + s * ATT_STAGE;
#pragma unroll
        for (int i = 0; i < 6; i++) {
            int idx = tid + i * 256;
            int tile = idx >> 9;
            int rem = idx & 511;
            int row = rem >> 3, c = rem & 7;
            const __half* base = (tile == 1) ? qkv_lo : qkv_hi;
            int coff = ((tile < 2) ? 1024 : 2048) + h * 64;
            const __half* g = base +
                (size_t)(b * T_SEQ + kt * 64 + row) * 3072 + coff + c * 8;
            cpa16(st + tile * ATT_KVTILE + row * AROW + c * 16, g);
        }
        if (tid < 16)
            cpa16(st + 3 * ATT_KVTILE + tid * 16,
                  mask + (size_t)b * T_SEQ + kt * 64 + tid * 4);
        asm volatile("cp.async.commit_group;" ::: "memory");
    };

    load_kv(0, 0);    // group: Q + kv0
    load_kv(1, 1);    // group: kv1

    const uint32_t aoffQ = (uint32_t)(w * 16 + (lane & 15)) * AROW +
                           (uint32_t)(lane >> 4) * 16;
    const uint32_t boffK = (uint32_t)((lane >> 4) * 8 + (lane & 7)) * AROW +
                           (uint32_t)((lane >> 3) & 1) * 16;
    const uint32_t voffV = (uint32_t)(lane & 15) * AROW +
                           (uint32_t)(lane >> 4) * 16;

    uint32_t qf[4][4];   // hoisted Q fragments (filled at kt==0)
    float mst0 = -1e30f, mst1 = -1e30f, lst0 = 0.f, lst1 = 0.f;
    float O[8][4];
#pragma unroll
    for (int n = 0; n < 8; n++)
#pragma unroll
        for (int j = 0; j < 4; j++) O[n][j] = 0.f;

    const int NKV = T_SEQ / 64;
    for (int kt = 0; kt < NKV; kt++) {
        const int s = kt % 3;
        if (kt + 1 < NKV)
            asm volatile("cp.async.wait_group 1;" ::: "memory");
        else
            asm volatile("cp.async.wait_group 0;" ::: "memory");
        __syncthreads();

        if (kt == 0) {
#pragma unroll
            for (int kg = 0; kg < 4; kg++)
                ldsm4(qf[kg], sb + aoffQ + kg * 32);
        }
        if (kt + 2 < NKV) load_kv((kt + 2) % 3, kt + 2);  // early issue

        const uint32_t st = stg0 + s * ATT_STAGE;
        const float* mskp = (const float*)(smc + ATT_QBYTES +
                                           s * ATT_STAGE + 3 * ATT_KVTILE);

        // ---- S = Qh*Kh + Qh*Kl (f32 accum) ----
        float S[8][4];
#pragma unroll
        for (int n = 0; n < 8; n++)
#pragma unroll
            for (int j = 0; j < 4; j++) S[n][j] = 0.f;

#pragma unroll
        for (int kg = 0; kg < 4; kg++) {
#pragma unroll
            for (int nb = 0; nb < 4; nb++) {
                uint32_t kh[4], kl[4];
                ldsm4(kh, st + boffK + nb * 16 * AROW + kg * 32);
                ldsm4(kl, st + ATT_KVTILE + boffK + nb * 16 * AROW + kg * 32);
                mma_f32(S[2 * nb],     qf[kg], &kh[0]);
                mma_f32(S[2 * nb + 1], qf[kg], &kh[2]);
                mma_f32(S[2 * nb],     qf[kg], &kl[0]);
                mma_f32(S[2 * nb + 1], qf[kg], &kl[2]);
            }
        }

        // ---- scale + double mask + online softmax ----
        float mx0 = -1e30f, mx1 = -1e30f;
#pragma unroll
        for (int n = 0; n < 8; n++) {
            float2 mk = *(const float2*)(mskp + n * 8 + (lane & 3) * 2);
            float m0 = 2.f * mk.x, m1 = 2.f * mk.y;
            S[n][0] = fmaf(S[n][0], 0.125f, m0);
            S[n][1] = fmaf(S[n][1], 0.125f, m1);
            S[n][2] = fmaf(S[n][2], 0.125f, m0);
            S[n][3] = fmaf(S[n][3], 0.125f, m1);
            mx0 = fmaxf(mx0, fmaxf(S[n][0], S[n][1]));
            mx1 = fmaxf(mx1, fmaxf(S[n][2], S[n][3]));
        }
        mx0 = fmaxf(mx0, __shfl_xor_sync(0xffffffffu, mx0, 1));
        mx0 = fmaxf(mx0, __shfl_xor_sync(0xffffffffu, mx0, 2));
        mx1 = fmaxf(mx1, __shfl_xor_sync(0xffffffffu, mx1, 1));
        mx1 = fmaxf(mx1, __shfl_xor_sync(0xffffffffu, mx1, 2));

        const float mn0 = fmaxf(mst0, mx0), mn1 = fmaxf(mst1, mx1);
        const float cr0 = __expf(mst0 - mn0), cr1 = __expf(mst1 - mn1);
        mst0 = mn0; mst1 = mn1;

        float rs0 = 0.f, rs1 = 0.f;
#pragma unroll
        for (int n = 0; n < 8; n++) {
            S[n][0] = __expf(S[n][0] - mn0);
            S[n][1] = __expf(S[n][1] - mn0);
            S[n][2] = __expf(S[n][2] - mn1);
            S[n][3] = __expf(S[n][3] - mn1);
            rs0 += S[n][0] + S[n][1];
            rs1 += S[n][2] + S[n][3];
        }
        rs0 += __shfl_xor_sync(0xffffffffu, rs0, 1);
        rs0 += __shfl_xor_sync(0xffffffffu, rs0, 2);
        rs1 += __shfl_xor_sync(0xffffffffu, rs1, 1);
        rs1 += __shfl_xor_sync(0xffffffffu, rs1, 2);
        lst0 = lst0 * cr0 + rs0;
        lst1 = lst1 * cr1 + rs1;

#pragma unroll
        for (int n = 0; n < 8; n++) {
            O[n][0] *= cr0; O[n][1] *= cr0;
            O[n][2] *= cr1; O[n][3] *= cr1;
        }

        // ---- O += P16 * Vh (single term, f32 accum) ----
#pragma unroll
        for (int kg = 0; kg < 4; kg++) {
            uint32_t ph[4];
            ph[0] = pack2(S[2 * kg][0],     S[2 * kg][1]);
            ph[1] = pack2(S[2 * kg][2],     S[2 * kg][3]);
            ph[2] = pack2(S[2 * kg + 1][0], S[2 * kg + 1][1]);
            ph[3] = pack2(S[2 * kg + 1][2], S[2 * kg + 1][3]);
#pragma unroll
            for (int nb = 0; nb < 4; nb++) {
                uint32_t vh[4];
                ldsm4t(vh, st + 2 * ATT_KVTILE + voffV + kg * 16 * AROW + nb * 32);
                mma_f32(O[2 * nb],     ph, &vh[0]);
                mma_f32(O[2 * nb + 1], ph, &vh[2]);
            }
        }
        // no trailing sync: next iteration's top sync protects stage reuse
    }

    const float inv0 = 1.f / lst0, inv1 = 1.f / lst1;
    const int row0 = b * T_SEQ + qt + w * 16 + (lane >> 2);
    const int colb = h * 64 + (lane & 3) * 2;
#pragma unroll
    for (int n = 0; n < 8; n++) {
        const size_t o0 = (size_t)row0 * D_MODEL + colb + n * 8;
        const size_t o1 = (size_t)(row0 + 8) * D_MODEL + colb + n * 8;
        *(uint32_t*)(out_hi + o0) = pack2(O[n][0] * inv0, O[n][1] * inv0);
        *(uint32_t*)(out_hi + o1) = pack2(O[n][2] * inv1, O[n][3] * inv1);
    }
}

// ---------------------------------------------------------------------------
extern "C" void kernel_launch(void* const* d_in, const int* in_sizes, int n_in,
                              void* d_out, int out_size)
{
    const float* x      = (const float*)d_in[0];
    const float* mask   = (const float*)d_in[1];
    const float* w_attn = (const float*)d_in[2];
    const float* b_attn = (const float*)d_in[3];
    const float* w_proj = (const float*)d_in[4];
    const float* b_proj = (const float*)d_in[5];
    float* out = (float*)d_out;

    __half *qkv_hi, *qkv_lo, *att_hi;
    __half *xa_hi, *wa_hi, *wa_lo, *wp_hi, *wp_lo;
    cudaGetSymbolAddress((void**)&qkv_hi, g_qkv_hi);
    cudaGetSymbolAddress((void**)&qkv_lo, g_qkv_lo);
    cudaGetSymbolAddress((void**)&att_hi, g_att_hi);
    cudaGetSymbolAddress((void**)&xa_hi, g_xa_hi);
    cudaGetSymbolAddress((void**)&wa_hi, g_wa_hi);
    cudaGetSymbolAddress((void**)&wa_lo, g_wa_lo);
    cudaGetSymbolAddress((void**)&wp_hi, g_wp_hi);
    cudaGetSymbolAddress((void**)&wp_lo, g_wp_lo);

    cudaFuncSetAttribute(gemm_hmma<0>,
                         cudaFuncAttributeMaxDynamicSharedMemorySize, GEMM_SMEM);
    cudaFuncSetAttribute(gemm_hmma<1>,
                         cudaFuncAttributeMaxDynamicSharedMemorySize, GEMM_SMEM);
    cudaFuncSetAttribute(attn_hmma,
                         cudaFuncAttributeMaxDynamicSharedMemorySize, ATT_SMEM);

    const int nx = BT_ROWS * 1024;

    // 1) conversions
    cvt_mat<<<nx / 4 / 256, 256>>>(x, xa_hi, nx);
    split_wT<<<dim3(3072 / 32, 1024 / 32), dim3(32, 8)>>>(w_attn, wa_hi, wa_lo, 1024, 3072);
    split_wT<<<dim3(1024 / 32, 1024 / 32), dim3(32, 8)>>>(w_proj, wp_hi, wp_lo, 1024, 1024);

    // 2) qkv = xh @ (Wh + Wl) + b  -> f16 hi/lo
    gemm_hmma<1><<<dim3(3072 / 128, BT_ROWS / 128), 128, GEMM_SMEM>>>(
        xa_hi, wa_hi, wa_lo, b_attn, nullptr, qkv_hi, qkv_lo, 3072, 1024);

    // 3) attention -> att hi
    attn_hmma<<<dim3(T_SEQ / 128, 16, 2), 256, ATT_SMEM>>>(
        qkv_hi, qkv_lo, mask, att_hi);

    // 4) out = ah @ (Wph + Wpl) + b  (fp32 out)
    gemm_hmma<0><<<dim3(1024 / 128, BT_ROWS / 128), 128, GEMM_SMEM>>>(
        att_hi, wp_hi, wp_lo, b_proj, out, nullptr, nullptr, 1024, 1024);
}

// round 12
// speedup vs baseline: 1.8126x; 1.1403x over previous
#include <cuda_runtime.h>
#include <cuda_fp16.h>
#include <cstdint>

#define T_SEQ 2048
#define D_MODEL 1024
#define BT_ROWS 4096            // B*T

// ---------------------------------------------------------------------------
// Scratch (device globals; no allocations anywhere).
// ---------------------------------------------------------------------------
__device__ __half g_qkv_hi[(size_t)BT_ROWS * 3072];
__device__ __half g_att_hi[(size_t)BT_ROWS * 1024];
__device__ __half g_xa_hi[(size_t)BT_ROWS * 1024];
__device__ __half g_wa_hi[(size_t)3072 * 1024];  // w_attn^T [N,K]
__device__ __half g_wa_lo[(size_t)3072 * 1024];
__device__ __half g_wp_hi[(size_t)1024 * 1024];  // w_proj^T [N,K]
__device__ __half g_wp_lo[(size_t)1024 * 1024];

// ---------------------------------------------------------------------------
// Helpers (plain sm_80-era PTX only)
// ---------------------------------------------------------------------------
__device__ __forceinline__ uint32_t smem_u32(const void* p) {
    uint32_t a;
    asm("{ .reg .u64 t; cvta.to.shared.u64 t, %1; cvt.u32.u64 %0, t; }"
        : "=r"(a) : "l"(p));
    return a;
}

__device__ __forceinline__ void cpa16(uint32_t s, const void* g) {
    asm volatile("cp.async.cg.shared.global [%0], [%1], 16;" :: "r"(s), "l"(g));
}

__device__ __forceinline__ void ldsm4(uint32_t* r, uint32_t a) {
    asm volatile("ldmatrix.sync.aligned.m8n8.x4.shared.b16 {%0,%1,%2,%3}, [%4];"
                 : "=r"(r[0]), "=r"(r[1]), "=r"(r[2]), "=r"(r[3]) : "r"(a));
}

__device__ __forceinline__ void ldsm4t(uint32_t* r, uint32_t a) {
    asm volatile("ldmatrix.sync.aligned.m8n8.x4.trans.shared.b16 {%0,%1,%2,%3}, [%4];"
                 : "=r"(r[0]), "=r"(r[1]), "=r"(r[2]), "=r"(r[3]) : "r"(a));
}

// f16 x f16 -> f32 accumulate
__device__ __forceinline__ void mma_f32(float* d, const uint32_t* a,
                                        const uint32_t* b) {
    asm volatile(
        "mma.sync.aligned.m16n8k16.row.col.f32.f16.f16.f32 "
        "{%0,%1,%2,%3}, {%4,%5,%6,%7}, {%8,%9}, {%0,%1,%2,%3};"
        : "+f"(d[0]), "+f"(d[1]), "+f"(d[2]), "+f"(d[3])
        : "r"(a[0]), "r"(a[1]), "r"(a[2]), "r"(a[3]), "r"(b[0]), "r"(b[1]));
}

// f16 x f16 -> f16 accumulate (GEMM lo cross-term)
__device__ __forceinline__ void mma_f16(uint32_t* d, const uint32_t* a,
                                        const uint32_t* b) {
    asm volatile(
        "mma.sync.aligned.m16n8k16.row.col.f16.f16.f16.f16 "
        "{%0,%1}, {%2,%3,%4,%5}, {%6,%7}, {%0,%1};"
        : "+r"(d[0]), "+r"(d[1])
        : "r"(a[0]), "r"(a[1]), "r"(a[2]), "r"(a[3]), "r"(b[0]), "r"(b[1]));
}

// split a pair of fp32 into packed f16x2 hi and lo
__device__ __forceinline__ void split2(float a, float b, uint32_t& hi, uint32_t& lo) {
    __half2 h, l;
    h.x = __float2half(a);
    h.y = __float2half(b);
    l.x = __float2half(a - __half2float(h.x));
    l.y = __float2half(b - __half2float(h.y));
    hi = *(uint32_t*)&h;
    lo = *(uint32_t*)&l;
}

// pack a pair of fp32 -> f16x2 (single rounding)
__device__ __forceinline__ uint32_t pack2(float a, float b) {
    __half2 h;
    h.x = __float2half(a);
    h.y = __float2half(b);
    return *(uint32_t*)&h;
}

// ---------------------------------------------------------------------------
// Conversions
// ---------------------------------------------------------------------------
__global__ void cvt_mat(const float* __restrict__ in,
                        __half* __restrict__ hi, int n) {
    int i = (blockIdx.x * blockDim.x + threadIdx.x) * 4;
    if (i >= n) return;
    float4 v = *(const float4*)(in + i);
    ((uint32_t*)(hi + i))[0] = pack2(v.x, v.y);
    ((uint32_t*)(hi + i))[1] = pack2(v.z, v.w);
}

// w:[Kd,Nd] row-major -> out hi/lo:[Nd,Kd] (transposed), split to f16
__global__ void split_wT(const float* __restrict__ w,
                         __half* __restrict__ hi,
                         __half* __restrict__ lo, int Kd, int Nd) {
    __shared__ float t[32][33];
    int k0 = blockIdx.y * 32, n0 = blockIdx.x * 32;
    int tx = threadIdx.x, ty = threadIdx.y;   // block (32,8)
#pragma unroll
    for (int j = 0; j < 32; j += 8)
        t[ty + j][tx] = w[(size_t)(k0 + ty + j) * Nd + n0 + tx];
    __syncthreads();
#pragma unroll
    for (int j = 0; j < 32; j += 8) {
        float v = t[tx][ty + j];
        __half h = __float2half(v);
        size_t o = (size_t)(n0 + ty + j) * Kd + k0 + tx;
        hi[o] = h;
        lo[o] = __float2half(v - __half2float(h));
    }
}

// ---------------------------------------------------------------------------
// HMMA 2-term GEMM: C = Ah @ (Bh + Bl)^T + bias
// 128x128 CTA tile, 4 warps of 64x64, BK=32, 3-stage early-issue pipeline.
// CVT_OUT=1: write f16 hi only.  CVT_OUT=0: write fp32.
// ---------------------------------------------------------------------------
#define GBK 32
#define ROWB 80
#define TILE_B (128 * ROWB)
#define STAGE_B (3 * TILE_B)          // Ah, Bh, Bl  (30720)
#define GEMM_SMEM (3 * STAGE_B)       // 92160

template <int CVT_OUT>
__global__ __launch_bounds__(128) void gemm_hmma(
    const __half* __restrict__ Ahi,
    const __half* __restrict__ Bhi, const __half* __restrict__ Blo,
    const float* __restrict__ bias, float* __restrict__ C,
    __half* __restrict__ Chi,
    int N, int K)
{
    extern __shared__ char smc[];
    const uint32_t sb = smem_u32(smc);
    const int tid = threadIdx.x, lane = tid & 31, wid = tid >> 5;
    const int bm = blockIdx.y * 128, bn = blockIdx.x * 128;
    const int mbw = (wid & 1) * 64;
    const int nbw = (wid >> 1) * 64;

    float acc[4][8][4];
    uint32_t accL[4][8][2];
#pragma unroll
    for (int m = 0; m < 4; m++)
#pragma unroll
        for (int n = 0; n < 8; n++) {
#pragma unroll
            for (int j = 0; j < 4; j++) acc[m][n][j] = 0.f;
            accL[m][n][0] = 0u; accL[m][n][1] = 0u;
        }

    const uint32_t aoff =
        (uint32_t)(mbw + (lane & 15)) * ROWB + (uint32_t)(lane >> 4) * 16;
    const uint32_t boff =
        (uint32_t)(nbw + (lane >> 4) * 8 + (lane & 7)) * ROWB +
        (uint32_t)((lane >> 3) & 1) * 16;

    auto load_stage = [&](int s, int kt) {
        const uint32_t st = sb + s * STAGE_B;
        const int kc = kt * GBK;
        const __half* gp[3] = {Ahi, Bhi, Blo};
#pragma unroll
        for (int tile = 0; tile < 3; tile++) {
            const int rbase = (tile == 0) ? bm : bn;
            const uint32_t td = st + tile * TILE_B;
#pragma unroll
            for (int i = 0; i < 2; i++) {
                int p = tid + i * 128;
                int row = p >> 1, hf = p & 1;
                const __half* g =
                    gp[tile] + (size_t)(rbase + row) * K + kc + hf * 16;
                uint32_t sd = td + row * ROWB + hf * 32;
                cpa16(sd, g);
                cpa16(sd + 16, g + 8);
            }
        }
        asm volatile("cp.async.commit_group;" ::: "memory");
    };

    const int KT = K / GBK;
    load_stage(0, 0);
    load_stage(1, 1);

    for (int kt = 0; kt < KT; kt++) {
        const int s = kt % 3;
        if (kt + 1 < KT)
            asm volatile("cp.async.wait_group 1;" ::: "memory");
        else
            asm volatile("cp.async.wait_group 0;" ::: "memory");
        __syncthreads();

        if (kt + 2 < KT) load_stage((kt + 2) % 3, kt + 2);  // early issue

        const uint32_t st = sb + s * STAGE_B;
        const uint32_t stAh = st;
        const uint32_t stBh = st + TILE_B, stBl = st + 2 * TILE_B;

#pragma unroll
        for (int ks = 0; ks < 2; ks++) {
            const uint32_t ko = ks * 32;
            uint32_t bh[4][4], ah[4][4], bl[4][4];
#pragma unroll
            for (int p = 0; p < 4; p++)
                ldsm4(bh[p], stBh + boff + p * 16 * ROWB + ko);
#pragma unroll
            for (int m = 0; m < 4; m++)
                ldsm4(ah[m], stAh + aoff + m * 16 * ROWB + ko);
#pragma unroll
            for (int n = 0; n < 8; n++)
#pragma unroll
                for (int m = 0; m < 4; m++)
                    mma_f32(acc[m][n], ah[m], &bh[n >> 1][(n & 1) * 2]);
#pragma unroll
            for (int p = 0; p < 4; p++)
                ldsm4(bl[p], stBl + boff + p * 16 * ROWB + ko);
#pragma unroll
            for (int n = 0; n < 8; n++)
#pragma unroll
                for (int m = 0; m < 4; m++)
                    mma_f16(accL[m][n], ah[m], &bl[n >> 1][(n & 1) * 2]);
        }
    }

    // Epilogue
    const int rql = lane >> 2, cql = (lane & 3) * 2;
#pragma unroll
    for (int m = 0; m < 4; m++) {
        const int row = bm + mbw + m * 16 + rql;
#pragma unroll
        for (int n = 0; n < 8; n++) {
            const int col = bn + nbw + n * 8 + cql;
            const float bx = bias[col], by = bias[col + 1];
            __half2 lo0 = *(__half2*)&accL[m][n][0];
            __half2 lo1 = *(__half2*)&accL[m][n][1];
            float v0 = acc[m][n][0] + __half2float(lo0.x) + bx;
            float v1 = acc[m][n][1] + __half2float(lo0.y) + by;
            float v2 = acc[m][n][2] + __half2float(lo1.x) + bx;
            float v3 = acc[m][n][3] + __half2float(lo1.y) + by;
            if (CVT_OUT) {
                *(uint32_t*)(Chi + (size_t)row * N + col) = pack2(v0, v1);
                *(uint32_t*)(Chi + (size_t)(row + 8) * N + col) = pack2(v2, v3);
            } else {
                *(float2*)(C + (size_t)row * N + col) = make_float2(v0, v1);
                *(float2*)(C + (size_t)(row + 8) * N + col) = make_float2(v2, v3);
            }
        }
    }
}

// ---------------------------------------------------------------------------
// HMMA flash attention, single-precision f16 operands:
//   S = Qh*Kh ;  O += P16 * Vh   (all f32 accum)
// 3-stage early-issue pipeline, hoisted Q fragments.
// Smem: Q 18432 + 3 x (2*9216 + 256) = 74496.
// ---------------------------------------------------------------------------
#define AROW 144
#define ATT_QBYTES (128 * AROW)          // 18432
#define ATT_KVTILE (64 * AROW)           // 9216
#define ATT_STAGE (2 * ATT_KVTILE + 256) // 18688
#define ATT_SMEM (ATT_QBYTES + 3 * ATT_STAGE)   // 74496

__global__ __launch_bounds__(256) void attn_hmma(
    const __half* __restrict__ qkv_hi,
    const float* __restrict__ mask,
    __half* __restrict__ out_hi)
{
    extern __shared__ char smc[];
    const uint32_t sb = smem_u32(smc);
    const int tid = threadIdx.x, lane = tid & 31, w = tid >> 5;
    const int qt = blockIdx.x * 128;
    const int h = blockIdx.y, b = blockIdx.z;

    // ---- Q load (hi only), committed with kv0 as one group ----
#pragma unroll
    for (int i = 0; i < 4; i++) {
        int idx = tid + i * 256;
        int row = idx >> 3, c = idx & 7;
        const __half* g = qkv_hi +
            (size_t)(b * T_SEQ + qt + row) * 3072 + h * 64 + c * 8;
        cpa16(sb + row * AROW + c * 16, g);
    }

    const uint32_t stg0 = sb + ATT_QBYTES;

    auto load_kv = [&](int s, int kt) {
        const uint32_t st = stg0 + s * ATT_STAGE;
        // 2 tiles: 0=Kh 1=Vh, 512 chunks each
#pragma unroll
        for (int i = 0; i < 4; i++) {
            int idx = tid + i * 256;
            int tile = idx >> 9;
            int rem = idx & 511;
            int row = rem >> 3, c = rem & 7;
            int coff = ((tile == 0) ? 1024 : 2048) + h * 64;
            const __half* g = qkv_hi +
                (size_t)(b * T_SEQ + kt * 64 + row) * 3072 + coff + c * 8;
            cpa16(st + tile * ATT_KVTILE + row * AROW + c * 16, g);
        }
        if (tid < 16)
            cpa16(st + 2 * ATT_KVTILE + tid * 16,
                  mask + (size_t)b * T_SEQ + kt * 64 + tid * 4);
        asm volatile("cp.async.commit_group;" ::: "memory");
    };

    load_kv(0, 0);    // group: Q + kv0
    load_kv(1, 1);    // group: kv1

    const uint32_t aoffQ = (uint32_t)(w * 16 + (lane & 15)) * AROW +
                           (uint32_t)(lane >> 4) * 16;
    const uint32_t boffK = (uint32_t)((lane >> 4) * 8 + (lane & 7)) * AROW +
                           (uint32_t)((lane >> 3) & 1) * 16;
    const uint32_t voffV = (uint32_t)(lane & 15) * AROW +
                           (uint32_t)(lane >> 4) * 16;

    uint32_t qf[4][4];   // hoisted Q fragments (filled at kt==0)
    float mst0 = -1e30f, mst1 = -1e30f, lst0 = 0.f, lst1 = 0.f;
    float O[8][4];
#pragma unroll
    for (int n = 0; n < 8; n++)
#pragma unroll
        for (int j = 0; j < 4; j++) O[n][j] = 0.f;

    const int NKV = T_SEQ / 64;
    for (int kt = 0; kt < NKV; kt++) {
        const int s = kt % 3;
        if (kt + 1 < NKV)
            asm volatile("cp.async.wait_group 1;" ::: "memory");
        else
            asm volatile("cp.async.wait_group 0;" ::: "memory");
        __syncthreads();

        if (kt == 0) {
#pragma unroll
            for (int kg = 0; kg < 4; kg++)
                ldsm4(qf[kg], sb + aoffQ + kg * 32);
        }
        if (kt + 2 < NKV) load_kv((kt + 2) % 3, kt + 2);  // early issue

        const uint32_t st = stg0 + s * ATT_STAGE;
        const float* mskp = (const float*)(smc + ATT_QBYTES +
                                           s * ATT_STAGE + 2 * ATT_KVTILE);

        // ---- S = Qh*Kh (f32 accum) ----
        float S[8][4];
#pragma unroll
        for (int n = 0; n < 8; n++)
#pragma unroll
            for (int j = 0; j < 4; j++) S[n][j] = 0.f;

#pragma unroll
        for (int kg = 0; kg < 4; kg++) {
#pragma unroll
            for (int nb = 0; nb < 4; nb++) {
                uint32_t kh[4];
                ldsm4(kh, st + boffK + nb * 16 * AROW + kg * 32);
                mma_f32(S[2 * nb],     qf[kg], &kh[0]);
                mma_f32(S[2 * nb + 1], qf[kg], &kh[2]);
            }
        }

        // ---- scale + double mask + online softmax ----
        float mx0 = -1e30f, mx1 = -1e30f;
#pragma unroll
        for (int n = 0; n < 8; n++) {
            float2 mk = *(const float2*)(mskp + n * 8 + (lane & 3) * 2);
            float m0 = 2.f * mk.x, m1 = 2.f * mk.y;
            S[n][0] = fmaf(S[n][0], 0.125f, m0);
            S[n][1] = fmaf(S[n][1], 0.125f, m1);
            S[n][2] = fmaf(S[n][2], 0.125f, m0);
            S[n][3] = fmaf(S[n][3], 0.125f, m1);
            mx0 = fmaxf(mx0, fmaxf(S[n][0], S[n][1]));
            mx1 = fmaxf(mx1, fmaxf(S[n][2], S[n][3]));
        }
        mx0 = fmaxf(mx0, __shfl_xor_sync(0xffffffffu, mx0, 1));
        mx0 = fmaxf(mx0, __shfl_xor_sync(0xffffffffu, mx0, 2));
        mx1 = fmaxf(mx1, __shfl_xor_sync(0xffffffffu, mx1, 1));
        mx1 = fmaxf(mx1, __shfl_xor_sync(0xffffffffu, mx1, 2));

        const float mn0 = fmaxf(mst0, mx0), mn1 = fmaxf(mst1, mx1);
        const float cr0 = __expf(mst0 - mn0), cr1 = __expf(mst1 - mn1);
        mst0 = mn0; mst1 = mn1;

        float rs0 = 0.f, rs1 = 0.f;
#pragma unroll
        for (int n = 0; n < 8; n++) {
            S[n][0] = __expf(S[n][0] - mn0);
            S[n][1] = __expf(S[n][1] - mn0);
            S[n][2] = __expf(S[n][2] - mn1);
            S[n][3] = __expf(S[n][3] - mn1);
            rs0 += S[n][0] + S[n][1];
            rs1 += S[n][2] + S[n][3];
        }
        rs0 += __shfl_xor_sync(0xffffffffu, rs0, 1);
        rs0 += __shfl_xor_sync(0xffffffffu, rs0, 2);
        rs1 += __shfl_xor_sync(0xffffffffu, rs1, 1);
        rs1 += __shfl_xor_sync(0xffffffffu, rs1, 2);
        lst0 = lst0 * cr0 + rs0;
        lst1 = lst1 * cr1 + rs1;

#pragma unroll
        for (int n = 0; n < 8; n++) {
            O[n][0] *= cr0; O[n][1] *= cr0;
            O[n][2] *= cr1; O[n][3] *= cr1;
        }

        // ---- O += P16 * Vh (f32 accum) ----
#pragma unroll
        for (int kg = 0; kg < 4; kg++) {
            uint32_t ph[4];
            ph[0] = pack2(S[2 * kg][0],     S[2 * kg][1]);
            ph[1] = pack2(S[2 * kg][2],     S[2 * kg][3]);
            ph[2] = pack2(S[2 * kg + 1][0], S[2 * kg + 1][1]);
            ph[3] = pack2(S[2 * kg + 1][2], S[2 * kg + 1][3]);
#pragma unroll
            for (int nb = 0; nb < 4; nb++) {
                uint32_t vh[4];
                ldsm4t(vh, st + ATT_KVTILE + voffV + kg * 16 * AROW + nb * 32);
                mma_f32(O[2 * nb],     ph, &vh[0]);
                mma_f32(O[2 * nb + 1], ph, &vh[2]);
            }
        }
    }

    const float inv0 = 1.f / lst0, inv1 = 1.f / lst1;
    const int row0 = b * T_SEQ + qt + w * 16 + (lane >> 2);
    const int colb = h * 64 + (lane & 3) * 2;
#pragma unroll
    for (int n = 0; n < 8; n++) {
        const size_t o0 = (size_t)row0 * D_MODEL + colb + n * 8;
        const size_t o1 = (size_t)(row0 + 8) * D_MODEL + colb + n * 8;
        *(uint32_t*)(out_hi + o0) = pack2(O[n][0] * inv0, O[n][1] * inv0);
        *(uint32_t*)(out_hi + o1) = pack2(O[n][2] * inv1, O[n][3] * inv1);
    }
}

// ---------------------------------------------------------------------------
extern "C" void kernel_launch(void* const* d_in, const int* in_sizes, int n_in,
                              void* d_out, int out_size)
{
    const float* x      = (const float*)d_in[0];
    const float* mask   = (const float*)d_in[1];
    const float* w_attn = (const float*)d_in[2];
    const float* b_attn = (const float*)d_in[3];
    const float* w_proj = (const float*)d_in[4];
    const float* b_proj = (const float*)d_in[5];
    float* out = (float*)d_out;

    __half *qkv_hi, *att_hi;
    __half *xa_hi, *wa_hi, *wa_lo, *wp_hi, *wp_lo;
    cudaGetSymbolAddress((void**)&qkv_hi, g_qkv_hi);
    cudaGetSymbolAddress((void**)&att_hi, g_att_hi);
    cudaGetSymbolAddress((void**)&xa_hi, g_xa_hi);
    cudaGetSymbolAddress((void**)&wa_hi, g_wa_hi);
    cudaGetSymbolAddress((void**)&wa_lo, g_wa_lo);
    cudaGetSymbolAddress((void**)&wp_hi, g_wp_hi);
    cudaGetSymbolAddress((void**)&wp_lo, g_wp_lo);

    cudaFuncSetAttribute(gemm_hmma<0>,
                         cudaFuncAttributeMaxDynamicSharedMemorySize, GEMM_SMEM);
    cudaFuncSetAttribute(gemm_hmma<1>,
                         cudaFuncAttributeMaxDynamicSharedMemorySize, GEMM_SMEM);
    cudaFuncSetAttribute(attn_hmma,
                         cudaFuncAttributeMaxDynamicSharedMemorySize, ATT_SMEM);

    const int nx = BT_ROWS * 1024;

    // 1) conversions
    cvt_mat<<<nx / 4 / 256, 256>>>(x, xa_hi, nx);
    split_wT<<<dim3(3072 / 32, 1024 / 32), dim3(32, 8)>>>(w_attn, wa_hi, wa_lo, 1024, 3072);
    split_wT<<<dim3(1024 / 32, 1024 / 32), dim3(32, 8)>>>(w_proj, wp_hi, wp_lo, 1024, 1024);

    // 2) qkv = xh @ (Wh + Wl) + b  -> f16 hi
    gemm_hmma<1><<<dim3(3072 / 128, BT_ROWS / 128), 128, GEMM_SMEM>>>(
        xa_hi, wa_hi, wa_lo, b_attn, nullptr, qkv_hi, 3072, 1024);

    // 3) attention -> att hi
    attn_hmma<<<dim3(T_SEQ / 128, 16, 2), 256, ATT_SMEM>>>(
        qkv_hi, mask, att_hi);

    // 4) out = ah @ (Wph + Wpl) + b  (fp32 out)
    gemm_hmma<0><<<dim3(1024 / 128, BT_ROWS / 128), 128, GEMM_SMEM>>>(
        att_hi, wp_hi, wp_lo, b_proj, out, nullptr, 1024, 1024);
}

// round 13
// speedup vs baseline: 2.2374x; 1.2343x over previous
#include <cuda_runtime.h>
#include <cuda_fp16.h>
#include <cstdint>

#define T_SEQ 2048
#define D_MODEL 1024
#define BT_ROWS 4096            // B*T

// ---------------------------------------------------------------------------
// Scratch (device globals; no allocations anywhere).
// ---------------------------------------------------------------------------
__device__ __half g_qkv_hi[(size_t)BT_ROWS * 3072];
__device__ __half g_att_hi[(size_t)BT_ROWS * 1024];
__device__ __half g_xa_hi[(size_t)BT_ROWS * 1024];
__device__ __half g_wa_hi[(size_t)3072 * 1024];  // w_attn^T [N,K]
__device__ __half g_wp_hi[(size_t)1024 * 1024];  // w_proj^T [N,K]
__device__ __half g_wp_lo[(size_t)1024 * 1024];

// ---------------------------------------------------------------------------
// Helpers (plain sm_80-era PTX only)
// ---------------------------------------------------------------------------
__device__ __forceinline__ uint32_t smem_u32(const void* p) {
    uint32_t a;
    asm("{ .reg .u64 t; cvta.to.shared.u64 t, %1; cvt.u32.u64 %0, t; }"
        : "=r"(a) : "l"(p));
    return a;
}

__device__ __forceinline__ void cpa16(uint32_t s, const void* g) {
    asm volatile("cp.async.cg.shared.global [%0], [%1], 16;" :: "r"(s), "l"(g));
}

__device__ __forceinline__ void ldsm4(uint32_t* r, uint32_t a) {
    asm volatile("ldmatrix.sync.aligned.m8n8.x4.shared.b16 {%0,%1,%2,%3}, [%4];"
                 : "=r"(r[0]), "=r"(r[1]), "=r"(r[2]), "=r"(r[3]) : "r"(a));
}

__device__ __forceinline__ void ldsm4t(uint32_t* r, uint32_t a) {
    asm volatile("ldmatrix.sync.aligned.m8n8.x4.trans.shared.b16 {%0,%1,%2,%3}, [%4];"
                 : "=r"(r[0]), "=r"(r[1]), "=r"(r[2]), "=r"(r[3]) : "r"(a));
}

// f16 x f16 -> f32 accumulate
__device__ __forceinline__ void mma_f32(float* d, const uint32_t* a,
                                        const uint32_t* b) {
    asm volatile(
        "mma.sync.aligned.m16n8k16.row.col.f32.f16.f16.f32 "
        "{%0,%1,%2,%3}, {%4,%5,%6,%7}, {%8,%9}, {%0,%1,%2,%3};"
        : "+f"(d[0]), "+f"(d[1]), "+f"(d[2]), "+f"(d[3])
        : "r"(a[0]), "r"(a[1]), "r"(a[2]), "r"(a[3]), "r"(b[0]), "r"(b[1]));
}

// f16 x f16 -> f16 accumulate (GEMM lo cross-term)
__device__ __forceinline__ void mma_f16(uint32_t* d, const uint32_t* a,
                                        const uint32_t* b) {
    asm volatile(
        "mma.sync.aligned.m16n8k16.row.col.f16.f16.f16.f16 "
        "{%0,%1}, {%2,%3,%4,%5}, {%6,%7}, {%0,%1};"
        : "+r"(d[0]), "+r"(d[1])
        : "r"(a[0]), "r"(a[1]), "r"(a[2]), "r"(a[3]), "r"(b[0]), "r"(b[1]));
}

// split a pair of fp32 into packed f16x2 hi and lo
__device__ __forceinline__ void split2(float a, float b, uint32_t& hi, uint32_t& lo) {
    __half2 h, l;
    h.x = __float2half(a);
    h.y = __float2half(b);
    l.x = __float2half(a - __half2float(h.x));
    l.y = __float2half(b - __half2float(h.y));
    hi = *(uint32_t*)&h;
    lo = *(uint32_t*)&l;
}

// pack a pair of fp32 -> f16x2 (single rounding)
__device__ __forceinline__ uint32_t pack2(float a, float b) {
    __half2 h;
    h.x = __float2half(a);
    h.y = __float2half(b);
    return *(uint32_t*)&h;
}

// ---------------------------------------------------------------------------
// Conversions
// ---------------------------------------------------------------------------
__global__ void cvt_mat(const float* __restrict__ in,
                        __half* __restrict__ hi, int n) {
    int i = (blockIdx.x * blockDim.x + threadIdx.x) * 4;
    if (i >= n) return;
    float4 v = *(const float4*)(in + i);
    ((uint32_t*)(hi + i))[0] = pack2(v.x, v.y);
    ((uint32_t*)(hi + i))[1] = pack2(v.z, v.w);
}

// w:[Kd,Nd] row-major -> hi:[Nd,Kd] (transposed, f16, no lo)
__global__ void cvt_wT(const float* __restrict__ w,
                       __half* __restrict__ hi, int Kd, int Nd) {
    __shared__ float t[32][33];
    int k0 = blockIdx.y * 32, n0 = blockIdx.x * 32;
    int tx = threadIdx.x, ty = threadIdx.y;   // block (32,8)
#pragma unroll
    for (int j = 0; j < 32; j += 8)
        t[ty + j][tx] = w[(size_t)(k0 + ty + j) * Nd + n0 + tx];
    __syncthreads();
#pragma unroll
    for (int j = 0; j < 32; j += 8)
        hi[(size_t)(n0 + ty + j) * Kd + k0 + tx] = __float2half(t[tx][ty + j]);
}

// w:[Kd,Nd] row-major -> out hi/lo:[Nd,Kd] (transposed), split to f16
__global__ void split_wT(const float* __restrict__ w,
                         __half* __restrict__ hi,
                         __half* __restrict__ lo, int Kd, int Nd) {
    __shared__ float t[32][33];
    int k0 = blockIdx.y * 32, n0 = blockIdx.x * 32;
    int tx = threadIdx.x, ty = threadIdx.y;   // block (32,8)
#pragma unroll
    for (int j = 0; j < 32; j += 8)
        t[ty + j][tx] = w[(size_t)(k0 + ty + j) * Nd + n0 + tx];
    __syncthreads();
#pragma unroll
    for (int j = 0; j < 32; j += 8) {
        float v = t[tx][ty + j];
        __half h = __float2half(v);
        size_t o = (size_t)(n0 + ty + j) * Kd + k0 + tx;
        hi[o] = h;
        lo[o] = __float2half(v - __half2float(h));
    }
}

// ---------------------------------------------------------------------------
// HMMA GEMM: C = Ah @ (Bh [+ Bl])^T + bias
// 128x128 CTA tile, 4 warps of 64x64, BK=32, 3-stage early-issue pipeline.
// TERMS=1: hi*hi only.  TERMS=2: + Ah*Bl in f16 accum.
// CVT_OUT=1: write f16 hi only.  CVT_OUT=0: write fp32.
// ---------------------------------------------------------------------------
#define GBK 32
#define ROWB 80
#define TILE_B (128 * ROWB)

template <int TERMS, int CVT_OUT>
__global__ __launch_bounds__(128) void gemm_hmma(
    const __half* __restrict__ Ahi,
    const __half* __restrict__ Bhi, const __half* __restrict__ Blo,
    const float* __restrict__ bias, float* __restrict__ C,
    __half* __restrict__ Chi,
    int N, int K)
{
    constexpr uint32_t STAGE = (1 + TERMS) * TILE_B;
    extern __shared__ char smc[];
    const uint32_t sb = smem_u32(smc);
    const int tid = threadIdx.x, lane = tid & 31, wid = tid >> 5;
    const int bm = blockIdx.y * 128, bn = blockIdx.x * 128;
    const int mbw = (wid & 1) * 64;
    const int nbw = (wid >> 1) * 64;

    float acc[4][8][4];
    uint32_t accL[4][8][2];
#pragma unroll
    for (int m = 0; m < 4; m++)
#pragma unroll
        for (int n = 0; n < 8; n++) {
#pragma unroll
            for (int j = 0; j < 4; j++) acc[m][n][j] = 0.f;
            accL[m][n][0] = 0u; accL[m][n][1] = 0u;
        }

    const uint32_t aoff =
        (uint32_t)(mbw + (lane & 15)) * ROWB + (uint32_t)(lane >> 4) * 16;
    const uint32_t boff =
        (uint32_t)(nbw + (lane >> 4) * 8 + (lane & 7)) * ROWB +
        (uint32_t)((lane >> 3) & 1) * 16;

    auto load_stage = [&](int s, int kt) {
        const uint32_t st = sb + s * STAGE;
        const int kc = kt * GBK;
        const __half* gp[3] = {Ahi, Bhi, Blo};
#pragma unroll
        for (int tile = 0; tile < 1 + TERMS; tile++) {
            const int rbase = (tile == 0) ? bm : bn;
            const uint32_t td = st + tile * TILE_B;
#pragma unroll
            for (int i = 0; i < 2; i++) {
                int p = tid + i * 128;
                int row = p >> 1, hf = p & 1;
                const __half* g =
                    gp[tile] + (size_t)(rbase + row) * K + kc + hf * 16;
                uint32_t sd = td + row * ROWB + hf * 32;
                cpa16(sd, g);
                cpa16(sd + 16, g + 8);
            }
        }
        asm volatile("cp.async.commit_group;" ::: "memory");
    };

    const int KT = K / GBK;
    load_stage(0, 0);
    load_stage(1, 1);

    for (int kt = 0; kt < KT; kt++) {
        const int s = kt % 3;
        if (kt + 1 < KT)
            asm volatile("cp.async.wait_group 1;" ::: "memory");
        else
            asm volatile("cp.async.wait_group 0;" ::: "memory");
        __syncthreads();

        if (kt + 2 < KT) load_stage((kt + 2) % 3, kt + 2);  // early issue

        const uint32_t st = sb + s * STAGE;
        const uint32_t stAh = st;
        const uint32_t stBh = st + TILE_B, stBl = st + 2 * TILE_B;

#pragma unroll
        for (int ks = 0; ks < 2; ks++) {
            const uint32_t ko = ks * 32;
            uint32_t bh[4][4], ah[4][4];
#pragma unroll
            for (int p = 0; p < 4; p++)
                ldsm4(bh[p], stBh + boff + p * 16 * ROWB + ko);
#pragma unroll
            for (int m = 0; m < 4; m++)
                ldsm4(ah[m], stAh + aoff + m * 16 * ROWB + ko);
#pragma unroll
            for (int n = 0; n < 8; n++)
#pragma unroll
                for (int m = 0; m < 4; m++)
                    mma_f32(acc[m][n], ah[m], &bh[n >> 1][(n & 1) * 2]);
            if (TERMS == 2) {
                uint32_t bl[4][4];
#pragma unroll
                for (int p = 0; p < 4; p++)
                    ldsm4(bl[p], stBl + boff + p * 16 * ROWB + ko);
#pragma unroll
                for (int n = 0; n < 8; n++)
#pragma unroll
                    for (int m = 0; m < 4; m++)
                        mma_f16(accL[m][n], ah[m], &bl[n >> 1][(n & 1) * 2]);
            }
        }
    }

    // Epilogue
    const int rql = lane >> 2, cql = (lane & 3) * 2;
#pragma unroll
    for (int m = 0; m < 4; m++) {
        const int row = bm + mbw + m * 16 + rql;
#pragma unroll
        for (int n = 0; n < 8; n++) {
            const int col = bn + nbw + n * 8 + cql;
            const float bx = bias[col], by = bias[col + 1];
            float v0 = acc[m][n][0] + bx;
            float v1 = acc[m][n][1] + by;
            float v2 = acc[m][n][2] + bx;
            float v3 = acc[m][n][3] + by;
            if (TERMS == 2) {
                __half2 lo0 = *(__half2*)&accL[m][n][0];
                __half2 lo1 = *(__half2*)&accL[m][n][1];
                v0 += __half2float(lo0.x);
                v1 += __half2float(lo0.y);
                v2 += __half2float(lo1.x);
                v3 += __half2float(lo1.y);
            }
            if (CVT_OUT) {
                *(uint32_t*)(Chi + (size_t)row * N + col) = pack2(v0, v1);
                *(uint32_t*)(Chi + (size_t)(row + 8) * N + col) = pack2(v2, v3);
            } else {
                *(float2*)(C + (size_t)row * N + col) = make_float2(v0, v1);
                *(float2*)(C + (size_t)(row + 8) * N + col) = make_float2(v2, v3);
            }
        }
    }
}

// ---------------------------------------------------------------------------
// HMMA flash attention (unchanged from R12):
//   S = Qh*Kh ;  O += P16 * Vh   (f32 accum)
// 3-stage early-issue pipeline, hoisted Q fragments.
// ---------------------------------------------------------------------------
#define AROW 144
#define ATT_QBYTES (128 * AROW)          // 18432
#define ATT_KVTILE (64 * AROW)           // 9216
#define ATT_STAGE (2 * ATT_KVTILE + 256) // 18688
#define ATT_SMEM (ATT_QBYTES + 3 * ATT_STAGE)   // 74496

__global__ __launch_bounds__(256) void attn_hmma(
    const __half* __restrict__ qkv_hi,
    const float* __restrict__ mask,
    __half* __restrict__ out_hi)
{
    extern __shared__ char smc[];
    const uint32_t sb = smem_u32(smc);
    const int tid = threadIdx.x, lane = tid & 31, w = tid >> 5;
    const int qt = blockIdx.x * 128;
    const int h = blockIdx.y, b = blockIdx.z;

#pragma unroll
    for (int i = 0; i < 4; i++) {
        int idx = tid + i * 256;
        int row = idx >> 3, c = idx & 7;
        const __half* g = qkv_hi +
            (size_t)(b * T_SEQ + qt + row) * 3072 + h * 64 + c * 8;
        cpa16(sb + row * AROW + c * 16, g);
    }

    const uint32_t stg0 = sb + ATT_QBYTES;

    auto load_kv = [&](int s, int kt) {
        const uint32_t st = stg0 + s * ATT_STAGE;
#pragma unroll
        for (int i = 0; i < 4; i++) {
            int idx = tid + i * 256;
            int tile = idx >> 9;
            int rem = idx & 511;
            int row = rem >> 3, c = rem & 7;
            int coff = ((tile == 0) ? 1024 : 2048) + h * 64;
            const __half* g = qkv_hi +
                (size_t)(b * T_SEQ + kt * 64 + row) * 3072 + coff + c * 8;
            cpa16(st + tile * ATT_KVTILE + row * AROW + c * 16, g);
        }
        if (tid < 16)
            cpa16(st + 2 * ATT_KVTILE + tid * 16,
                  mask + (size_t)b * T_SEQ + kt * 64 + tid * 4);
        asm volatile("cp.async.commit_group;" ::: "memory");
    };

    load_kv(0, 0);
    load_kv(1, 1);

    const uint32_t aoffQ = (uint32_t)(w * 16 + (lane & 15)) * AROW +
                           (uint32_t)(lane >> 4) * 16;
    const uint32_t boffK = (uint32_t)((lane >> 4) * 8 + (lane & 7)) * AROW +
                           (uint32_t)((lane >> 3) & 1) * 16;
    const uint32_t voffV = (uint32_t)(lane & 15) * AROW +
                           (uint32_t)(lane >> 4) * 16;

    uint32_t qf[4][4];
    float mst0 = -1e30f, mst1 = -1e30f, lst0 = 0.f, lst1 = 0.f;
    float O[8][4];
#pragma unroll
    for (int n = 0; n < 8; n++)
#pragma unroll
        for (int j = 0; j < 4; j++) O[n][j] = 0.f;

    const int NKV = T_SEQ / 64;
    for (int kt = 0; kt < NKV; kt++) {
        const int s = kt % 3;
        if (kt + 1 < NKV)
            asm volatile("cp.async.wait_group 1;" ::: "memory");
        else
            asm volatile("cp.async.wait_group 0;" ::: "memory");
        __syncthreads();

        if (kt == 0) {
#pragma unroll
            for (int kg = 0; kg < 4; kg++)
                ldsm4(qf[kg], sb + aoffQ + kg * 32);
        }
        if (kt + 2 < NKV) load_kv((kt + 2) % 3, kt + 2);

        const uint32_t st = stg0 + s * ATT_STAGE;
        const float* mskp = (const float*)(smc + ATT_QBYTES +
                                           s * ATT_STAGE + 2 * ATT_KVTILE);

        float S[8][4];
#pragma unroll
        for (int n = 0; n < 8; n++)
#pragma unroll
            for (int j = 0; j < 4; j++) S[n][j] = 0.f;

#pragma unroll
        for (int kg = 0; kg < 4; kg++) {
#pragma unroll
            for (int nb = 0; nb < 4; nb++) {
                uint32_t kh[4];
                ldsm4(kh, st + boffK + nb * 16 * AROW + kg * 32);
                mma_f32(S[2 * nb],     qf[kg], &kh[0]);
                mma_f32(S[2 * nb + 1], qf[kg], &kh[2]);
            }
        }

        float mx0 = -1e30f, mx1 = -1e30f;
#pragma unroll
        for (int n = 0; n < 8; n++) {
            float2 mk = *(const float2*)(mskp + n * 8 + (lane & 3) * 2);
            float m0 = 2.f * mk.x, m1 = 2.f * mk.y;
            S[n][0] = fmaf(S[n][0], 0.125f, m0);
            S[n][1] = fmaf(S[n][1], 0.125f, m1);
            S[n][2] = fmaf(S[n][2], 0.125f, m0);
            S[n][3] = fmaf(S[n][3], 0.125f, m1);
            mx0 = fmaxf(mx0, fmaxf(S[n][0], S[n][1]));
            mx1 = fmaxf(mx1, fmaxf(S[n][2], S[n][3]));
        }
        mx0 = fmaxf(mx0, __shfl_xor_sync(0xffffffffu, mx0, 1));
        mx0 = fmaxf(mx0, __shfl_xor_sync(0xffffffffu, mx0, 2));
        mx1 = fmaxf(mx1, __shfl_xor_sync(0xffffffffu, mx1, 1));
        mx1 = fmaxf(mx1, __shfl_xor_sync(0xffffffffu, mx1, 2));

        const float mn0 = fmaxf(mst0, mx0), mn1 = fmaxf(mst1, mx1);
        const float cr0 = __expf(mst0 - mn0), cr1 = __expf(mst1 - mn1);
        mst0 = mn0; mst1 = mn1;

        float rs0 = 0.f, rs1 = 0.f;
#pragma unroll
        for (int n = 0; n < 8; n++) {
            S[n][0] = __expf(S[n][0] - mn0);
            S[n][1] = __expf(S[n][1] - mn0);
            S[n][2] = __expf(S[n][2] - mn1);
            S[n][3] = __expf(S[n][3] - mn1);
            rs0 += S[n][0] + S[n][1];
            rs1 += S[n][2] + S[n][3];
        }
        rs0 += __shfl_xor_sync(0xffffffffu, rs0, 1);
        rs0 += __shfl_xor_sync(0xffffffffu, rs0, 2);
        rs1 += __shfl_xor_sync(0xffffffffu, rs1, 1);
        rs1 += __shfl_xor_sync(0xffffffffu, rs1, 2);
        lst0 = lst0 * cr0 + rs0;
        lst1 = lst1 * cr1 + rs1;

#pragma unroll
        for (int n = 0; n < 8; n++) {
            O[n][0] *= cr0; O[n][1] *= cr0;
            O[n][2] *= cr1; O[n][3] *= cr1;
        }

#pragma unroll
        for (int kg = 0; kg < 4; kg++) {
            uint32_t ph[4];
            ph[0] = pack2(S[2 * kg][0],     S[2 * kg][1]);
            ph[1] = pack2(S[2 * kg][2],     S[2 * kg][3]);
            ph[2] = pack2(S[2 * kg + 1][0], S[2 * kg + 1][1]);
            ph[3] = pack2(S[2 * kg + 1][2], S[2 * kg + 1][3]);
#pragma unroll
            for (int nb = 0; nb < 4; nb++) {
                uint32_t vh[4];
                ldsm4t(vh, st + ATT_KVTILE + voffV + kg * 16 * AROW + nb * 32);
                mma_f32(O[2 * nb],     ph, &vh[0]);
                mma_f32(O[2 * nb + 1], ph, &vh[2]);
            }
        }
    }

    const float inv0 = 1.f / lst0, inv1 = 1.f / lst1;
    const int row0 = b * T_SEQ + qt + w * 16 + (lane >> 2);
    const int colb = h * 64 + (lane & 3) * 2;
#pragma unroll
    for (int n = 0; n < 8; n++) {
        const size_t o0 = (size_t)row0 * D_MODEL + colb + n * 8;
        const size_t o1 = (size_t)(row0 + 8) * D_MODEL + colb + n * 8;
        *(uint32_t*)(out_hi + o0) = pack2(O[n][0] * inv0, O[n][1] * inv0);
        *(uint32_t*)(out_hi + o1) = pack2(O[n][2] * inv1, O[n][3] * inv1);
    }
}

// ---------------------------------------------------------------------------
extern "C" void kernel_launch(void* const* d_in, const int* in_sizes, int n_in,
                              void* d_out, int out_size)
{
    const float* x      = (const float*)d_in[0];
    const float* mask   = (const float*)d_in[1];
    const float* w_attn = (const float*)d_in[2];
    const float* b_attn = (const float*)d_in[3];
    const float* w_proj = (const float*)d_in[4];
    const float* b_proj = (const float*)d_in[5];
    float* out = (float*)d_out;

    __half *qkv_hi, *att_hi;
    __half *xa_hi, *wa_hi, *wp_hi, *wp_lo;
    cudaGetSymbolAddress((void**)&qkv_hi, g_qkv_hi);
    cudaGetSymbolAddress((void**)&att_hi, g_att_hi);
    cudaGetSymbolAddress((void**)&xa_hi, g_xa_hi);
    cudaGetSymbolAddress((void**)&wa_hi, g_wa_hi);
    cudaGetSymbolAddress((void**)&wp_hi, g_wp_hi);
    cudaGetSymbolAddress((void**)&wp_lo, g_wp_lo);

    const int SMEM_1T = 3 * 2 * TILE_B;   // 61440
    const int SMEM_2T = 3 * 3 * TILE_B;   // 92160
    cudaFuncSetAttribute((const void*)gemm_hmma<1, 1>,
                         cudaFuncAttributeMaxDynamicSharedMemorySize, SMEM_1T);
    cudaFuncSetAttribute((const void*)gemm_hmma<2, 0>,
                         cudaFuncAttributeMaxDynamicSharedMemorySize, SMEM_2T);
    cudaFuncSetAttribute((const void*)attn_hmma,
                         cudaFuncAttributeMaxDynamicSharedMemorySize, ATT_SMEM);

    const int nx = BT_ROWS * 1024;

    // 1) conversions
    cvt_mat<<<nx / 4 / 256, 256>>>(x, xa_hi, nx);
    cvt_wT<<<dim3(3072 / 32, 1024 / 32), dim3(32, 8)>>>(w_attn, wa_hi, 1024, 3072);
    split_wT<<<dim3(1024 / 32, 1024 / 32), dim3(32, 8)>>>(w_proj, wp_hi, wp_lo, 1024, 1024);

    // 2) qkv = xh @ Wh + b  -> f16 (1-term)
    gemm_hmma<1, 1><<<dim3(3072 / 128, BT_ROWS / 128), 128, SMEM_1T>>>(
        xa_hi, wa_hi, nullptr, b_attn, nullptr, qkv_hi, 3072, 1024);

    // 3) attention -> att hi
    attn_hmma<<<dim3(T_SEQ / 128, 16, 2), 256, ATT_SMEM>>>(
        qkv_hi, mask, att_hi);

    // 4) out = ah @ (Wph + Wpl) + b  (fp32 out, 2-term)
    gemm_hmma<2, 0><<<dim3(1024 / 128, BT_ROWS / 128), 128, SMEM_2T>>>(
        att_hi, wp_hi, wp_lo, b_proj, out, nullptr, 1024, 1024);
}

// round 14
// speedup vs baseline: 2.3100x; 1.0325x over previous
#include <cuda_runtime.h>
#include <cuda_fp16.h>
#include <cstdint>

#define T_SEQ 2048
#define D_MODEL 1024
#define BT_ROWS 4096            // B*T

// ---------------------------------------------------------------------------
// Scratch (device globals; no allocations anywhere).
// ---------------------------------------------------------------------------
__device__ __half g_qkv_hi[(size_t)BT_ROWS * 3072];
__device__ __half g_att_hi[(size_t)BT_ROWS * 1024];
__device__ __half g_xa_hi[(size_t)BT_ROWS * 1024];
__device__ __half g_wa_hi[(size_t)3072 * 1024];  // w_attn^T [N,K]
__device__ __half g_wp_hi[(size_t)1024 * 1024];  // w_proj^T [N,K]
__device__ __half g_wp_lo[(size_t)1024 * 1024];

// ---------------------------------------------------------------------------
// Helpers (plain sm_80-era PTX only)
// ---------------------------------------------------------------------------
__device__ __forceinline__ uint32_t smem_u32(const void* p) {
    uint32_t a;
    asm("{ .reg .u64 t; cvta.to.shared.u64 t, %1; cvt.u32.u64 %0, t; }"
        : "=r"(a) : "l"(p));
    return a;
}

__device__ __forceinline__ void cpa16(uint32_t s, const void* g) {
    asm volatile("cp.async.cg.shared.global [%0], [%1], 16;" :: "r"(s), "l"(g));
}

__device__ __forceinline__ void ldsm4(uint32_t* r, uint32_t a) {
    asm volatile("ldmatrix.sync.aligned.m8n8.x4.shared.b16 {%0,%1,%2,%3}, [%4];"
                 : "=r"(r[0]), "=r"(r[1]), "=r"(r[2]), "=r"(r[3]) : "r"(a));
}

__device__ __forceinline__ void ldsm4t(uint32_t* r, uint32_t a) {
    asm volatile("ldmatrix.sync.aligned.m8n8.x4.trans.shared.b16 {%0,%1,%2,%3}, [%4];"
                 : "=r"(r[0]), "=r"(r[1]), "=r"(r[2]), "=r"(r[3]) : "r"(a));
}

// f16 x f16 -> f32 accumulate
__device__ __forceinline__ void mma_f32(float* d, const uint32_t* a,
                                        const uint32_t* b) {
    asm volatile(
        "mma.sync.aligned.m16n8k16.row.col.f32.f16.f16.f32 "
        "{%0,%1,%2,%3}, {%4,%5,%6,%7}, {%8,%9}, {%0,%1,%2,%3};"
        : "+f"(d[0]), "+f"(d[1]), "+f"(d[2]), "+f"(d[3])
        : "r"(a[0]), "r"(a[1]), "r"(a[2]), "r"(a[3]), "r"(b[0]), "r"(b[1]));
}

// f16 x f16 -> f16 accumulate (GEMM lo cross-term)
__device__ __forceinline__ void mma_f16(uint32_t* d, const uint32_t* a,
                                        const uint32_t* b) {
    asm volatile(
        "mma.sync.aligned.m16n8k16.row.col.f16.f16.f16.f16 "
        "{%0,%1}, {%2,%3,%4,%5}, {%6,%7}, {%0,%1};"
        : "+r"(d[0]), "+r"(d[1])
        : "r"(a[0]), "r"(a[1]), "r"(a[2]), "r"(a[3]), "r"(b[0]), "r"(b[1]));
}

// pack a pair of fp32 -> f16x2 (single rounding)
__device__ __forceinline__ uint32_t pack2(float a, float b) {
    __half2 h;
    h.x = __float2half(a);
    h.y = __float2half(b);
    return *(uint32_t*)&h;
}

// ---------------------------------------------------------------------------
// Conversions
// ---------------------------------------------------------------------------
__global__ void cvt_mat(const float* __restrict__ in,
                        __half* __restrict__ hi, int n) {
    int i = (blockIdx.x * blockDim.x + threadIdx.x) * 4;
    if (i >= n) return;
    float4 v = *(const float4*)(in + i);
    ((uint32_t*)(hi + i))[0] = pack2(v.x, v.y);
    ((uint32_t*)(hi + i))[1] = pack2(v.z, v.w);
}

// w:[Kd,Nd] row-major -> hi:[Nd,Kd] (transposed, f16, no lo)
__global__ void cvt_wT(const float* __restrict__ w,
                       __half* __restrict__ hi, int Kd, int Nd) {
    __shared__ float t[32][33];
    int k0 = blockIdx.y * 32, n0 = blockIdx.x * 32;
    int tx = threadIdx.x, ty = threadIdx.y;   // block (32,8)
#pragma unroll
    for (int j = 0; j < 32; j += 8)
        t[ty + j][tx] = w[(size_t)(k0 + ty + j) * Nd + n0 + tx];
    __syncthreads();
#pragma unroll
    for (int j = 0; j < 32; j += 8)
        hi[(size_t)(n0 + ty + j) * Kd + k0 + tx] = __float2half(t[tx][ty + j]);
}

// w:[Kd,Nd] row-major -> out hi/lo:[Nd,Kd] (transposed), split to f16
__global__ void split_wT(const float* __restrict__ w,
                         __half* __restrict__ hi,
                         __half* __restrict__ lo, int Kd, int Nd) {
    __shared__ float t[32][33];
    int k0 = blockIdx.y * 32, n0 = blockIdx.x * 32;
    int tx = threadIdx.x, ty = threadIdx.y;   // block (32,8)
#pragma unroll
    for (int j = 0; j < 32; j += 8)
        t[ty + j][tx] = w[(size_t)(k0 + ty + j) * Nd + n0 + tx];
    __syncthreads();
#pragma unroll
    for (int j = 0; j < 32; j += 8) {
        float v = t[tx][ty + j];
        __half h = __float2half(v);
        size_t o = (size_t)(n0 + ty + j) * Kd + k0 + tx;
        hi[o] = h;
        lo[o] = __float2half(v - __half2float(h));
    }
}

// ---------------------------------------------------------------------------
// HMMA GEMM: C = Ah @ (Bh [+ Bl])^T + bias
// 128x128 CTA tile, BK=32, 3-stage early-issue pipeline.
// NWARP=4: warp tile 64x64 (proven for 2-term).
// NWARP=8: warp tile 32x64 (for 1-term; 2x warps to hide LDSM latency).
// TERMS=1: hi*hi only.  TERMS=2: + Ah*Bl in f16 accum.
// CVT_OUT=1: write f16 hi only.  CVT_OUT=0: write fp32.
// ---------------------------------------------------------------------------
#define GBK 32
#define ROWB 80
#define TILE_B (128 * ROWB)

template <int TERMS, int CVT_OUT, int NWARP>
__global__ __launch_bounds__(NWARP * 32) void gemm_hmma(
    const __half* __restrict__ Ahi,
    const __half* __restrict__ Bhi, const __half* __restrict__ Blo,
    const float* __restrict__ bias, float* __restrict__ C,
    __half* __restrict__ Chi,
    int N, int K)
{
    constexpr uint32_t STAGE = (1 + TERMS) * TILE_B;
    constexpr int NT = NWARP * 32;
    constexpr int MI = (NWARP == 4) ? 4 : 2;   // m16 fragments per warp

    extern __shared__ char smc[];
    const uint32_t sb = smem_u32(smc);
    const int tid = threadIdx.x, lane = tid & 31, wid = tid >> 5;
    const int bm = blockIdx.y * 128, bn = blockIdx.x * 128;
    const int mbw = (NWARP == 4) ? (wid & 1) * 64 : (wid & 3) * 32;
    const int nbw = (NWARP == 4) ? (wid >> 1) * 64 : (wid >> 2) * 64;

    float acc[MI][8][4];
    uint32_t accL[MI][8][2];
#pragma unroll
    for (int m = 0; m < MI; m++)
#pragma unroll
        for (int n = 0; n < 8; n++) {
#pragma unroll
            for (int j = 0; j < 4; j++) acc[m][n][j] = 0.f;
            accL[m][n][0] = 0u; accL[m][n][1] = 0u;
        }

    const uint32_t aoff =
        (uint32_t)(mbw + (lane & 15)) * ROWB + (uint32_t)(lane >> 4) * 16;
    const uint32_t boff =
        (uint32_t)(nbw + (lane >> 4) * 8 + (lane & 7)) * ROWB +
        (uint32_t)((lane >> 3) & 1) * 16;

    auto load_stage = [&](int s, int kt) {
        const uint32_t st = sb + s * STAGE;
        const int kc = kt * GBK;
        const __half* gp[3] = {Ahi, Bhi, Blo};
        // (1+TERMS)*512 chunks of 16B; each tile: 128 rows x 4 chunks
#pragma unroll
        for (int c = 0; c < (1 + TERMS) * 512 / NT; c++) {
            int idx = tid + c * NT;
            int tile = idx >> 9;
            int rem = idx & 511;
            int row = rem >> 2, q = rem & 3;
            const int rbase = (tile == 0) ? bm : bn;
            const __half* g =
                gp[tile] + (size_t)(rbase + row) * K + kc + q * 8;
            cpa16(st + tile * TILE_B + row * ROWB + q * 16, g);
        }
        asm volatile("cp.async.commit_group;" ::: "memory");
    };

    const int KT = K / GBK;
    load_stage(0, 0);
    load_stage(1, 1);

    for (int kt = 0; kt < KT; kt++) {
        const int s = kt % 3;
        if (kt + 1 < KT)
            asm volatile("cp.async.wait_group 1;" ::: "memory");
        else
            asm volatile("cp.async.wait_group 0;" ::: "memory");
        __syncthreads();

        if (kt + 2 < KT) load_stage((kt + 2) % 3, kt + 2);  // early issue

        const uint32_t st = sb + s * STAGE;
        const uint32_t stAh = st;
        const uint32_t stBh = st + TILE_B, stBl = st + 2 * TILE_B;

#pragma unroll
        for (int ks = 0; ks < 2; ks++) {
            const uint32_t ko = ks * 32;
            uint32_t bh[4][4], ah[MI][4];
#pragma unroll
            for (int p = 0; p < 4; p++)
                ldsm4(bh[p], stBh + boff + p * 16 * ROWB + ko);
#pragma unroll
            for (int m = 0; m < MI; m++)
                ldsm4(ah[m], stAh + aoff + m * 16 * ROWB + ko);
#pragma unroll
            for (int n = 0; n < 8; n++)
#pragma unroll
                for (int m = 0; m < MI; m++)
                    mma_f32(acc[m][n], ah[m], &bh[n >> 1][(n & 1) * 2]);
            if (TERMS == 2) {
                uint32_t bl[4][4];
#pragma unroll
                for (int p = 0; p < 4; p++)
                    ldsm4(bl[p], stBl + boff + p * 16 * ROWB + ko);
#pragma unroll
                for (int n = 0; n < 8; n++)
#pragma unroll
                    for (int m = 0; m < MI; m++)
                        mma_f16(accL[m][n], ah[m], &bl[n >> 1][(n & 1) * 2]);
            }
        }
    }

    // Epilogue
    const int rql = lane >> 2, cql = (lane & 3) * 2;
#pragma unroll
    for (int m = 0; m < MI; m++) {
        const int row = bm + mbw + m * 16 + rql;
#pragma unroll
        for (int n = 0; n < 8; n++) {
            const int col = bn + nbw + n * 8 + cql;
            const float bx = bias[col], by = bias[col + 1];
            float v0 = acc[m][n][0] + bx;
            float v1 = acc[m][n][1] + by;
            float v2 = acc[m][n][2] + bx;
            float v3 = acc[m][n][3] + by;
            if (TERMS == 2) {
                __half2 lo0 = *(__half2*)&accL[m][n][0];
                __half2 lo1 = *(__half2*)&accL[m][n][1];
                v0 += __half2float(lo0.x);
                v1 += __half2float(lo0.y);
                v2 += __half2float(lo1.x);
                v3 += __half2float(lo1.y);
            }
            if (CVT_OUT) {
                *(uint32_t*)(Chi + (size_t)row * N + col) = pack2(v0, v1);
                *(uint32_t*)(Chi + (size_t)(row + 8) * N + col) = pack2(v2, v3);
            } else {
                *(float2*)(C + (size_t)row * N + col) = make_float2(v0, v1);
                *(float2*)(C + (size_t)(row + 8) * N + col) = make_float2(v2, v3);
            }
        }
    }
}

// ---------------------------------------------------------------------------
// HMMA flash attention (unchanged from R13):
//   S = Qh*Kh ;  O += P16 * Vh   (f32 accum)
// 3-stage early-issue pipeline, hoisted Q fragments.
// ---------------------------------------------------------------------------
#define AROW 144
#define ATT_QBYTES (128 * AROW)          // 18432
#define ATT_KVTILE (64 * AROW)           // 9216
#define ATT_STAGE (2 * ATT_KVTILE + 256) // 18688
#define ATT_SMEM (ATT_QBYTES + 3 * ATT_STAGE)   // 74496

__global__ __launch_bounds__(256) void attn_hmma(
    const __half* __restrict__ qkv_hi,
    const float* __restrict__ mask,
    __half* __restrict__ out_hi)
{
    extern __shared__ char smc[];
    const uint32_t sb = smem_u32(smc);
    const int tid = threadIdx.x, lane = tid & 31, w = tid >> 5;
    const int qt = blockIdx.x * 128;
    const int h = blockIdx.y, b = blockIdx.z;

#pragma unroll
    for (int i = 0; i < 4; i++) {
        int idx = tid + i * 256;
        int row = idx >> 3, c = idx & 7;
        const __half* g = qkv_hi +
            (size_t)(b * T_SEQ + qt + row) * 3072 + h * 64 + c * 8;
        cpa16(sb + row * AROW + c * 16, g);
    }

    const uint32_t stg0 = sb + ATT_QBYTES;

    auto load_kv = [&](int s, int kt) {
        const uint32_t st = stg0 + s * ATT_STAGE;
#pragma unroll
        for (int i = 0; i < 4; i++) {
            int idx = tid + i * 256;
            int tile = idx >> 9;
            int rem = idx & 511;
            int row = rem >> 3, c = rem & 7;
            int coff = ((tile == 0) ? 1024 : 2048) + h * 64;
            const __half* g = qkv_hi +
                (size_t)(b * T_SEQ + kt * 64 + row) * 3072 + coff + c * 8;
            cpa16(st + tile * ATT_KVTILE + row * AROW + c * 16, g);
        }
        if (tid < 16)
            cpa16(st + 2 * ATT_KVTILE + tid * 16,
                  mask + (size_t)b * T_SEQ + kt * 64 + tid * 4);
        asm volatile("cp.async.commit_group;" ::: "memory");
    };

    load_kv(0, 0);
    load_kv(1, 1);

    const uint32_t aoffQ = (uint32_t)(w * 16 + (lane & 15)) * AROW +
                           (uint32_t)(lane >> 4) * 16;
    const uint32_t boffK = (uint32_t)((lane >> 4) * 8 + (lane & 7)) * AROW +
                           (uint32_t)((lane >> 3) & 1) * 16;
    const uint32_t voffV = (uint32_t)(lane & 15) * AROW +
                           (uint32_t)(lane >> 4) * 16;

    uint32_t qf[4][4];
    float mst0 = -1e30f, mst1 = -1e30f, lst0 = 0.f, lst1 = 0.f;
    float O[8][4];
#pragma unroll
    for (int n = 0; n < 8; n++)
#pragma unroll
        for (int j = 0; j < 4; j++) O[n][j] = 0.f;

    const int NKV = T_SEQ / 64;
    for (int kt = 0; kt < NKV; kt++) {
        const int s = kt % 3;
        if (kt + 1 < NKV)
            asm volatile("cp.async.wait_group 1;" ::: "memory");
        else
            asm volatile("cp.async.wait_group 0;" ::: "memory");
        __syncthreads();

        if (kt == 0) {
#pragma unroll
            for (int kg = 0; kg < 4; kg++)
                ldsm4(qf[kg], sb + aoffQ + kg * 32);
        }
        if (kt + 2 < NKV) load_kv((kt + 2) % 3, kt + 2);

        const uint32_t st = stg0 + s * ATT_STAGE;
        const float* mskp = (const float*)(smc + ATT_QBYTES +
                                           s * ATT_STAGE + 2 * ATT_KVTILE);

        float S[8][4];
#pragma unroll
        for (int n = 0; n < 8; n++)
#pragma unroll
            for (int j = 0; j < 4; j++) S[n][j] = 0.f;

#pragma unroll
        for (int kg = 0; kg < 4; kg++) {
#pragma unroll
            for (int nb = 0; nb < 4; nb++) {
                uint32_t kh[4];
                ldsm4(kh, st + boffK + nb * 16 * AROW + kg * 32);
                mma_f32(S[2 * nb],     qf[kg], &kh[0]);
                mma_f32(S[2 * nb + 1], qf[kg], &kh[2]);
            }
        }

        float mx0 = -1e30f, mx1 = -1e30f;
#pragma unroll
        for (int n = 0; n < 8; n++) {
            float2 mk = *(const float2*)(mskp + n * 8 + (lane & 3) * 2);
            float m0 = 2.f * mk.x, m1 = 2.f * mk.y;
            S[n][0] = fmaf(S[n][0], 0.125f, m0);
            S[n][1] = fmaf(S[n][1], 0.125f, m1);
            S[n][2] = fmaf(S[n][2], 0.125f, m0);
            S[n][3] = fmaf(S[n][3], 0.125f, m1);
            mx0 = fmaxf(mx0, fmaxf(S[n][0], S[n][1]));
            mx1 = fmaxf(mx1, fmaxf(S[n][2], S[n][3]));
        }
        mx0 = fmaxf(mx0, __shfl_xor_sync(0xffffffffu, mx0, 1));
        mx0 = fmaxf(mx0, __shfl_xor_sync(0xffffffffu, mx0, 2));
        mx1 = fmaxf(mx1, __shfl_xor_sync(0xffffffffu, mx1, 1));
        mx1 = fmaxf(mx1, __shfl_xor_sync(0xffffffffu, mx1, 2));

        const float mn0 = fmaxf(mst0, mx0), mn1 = fmaxf(mst1, mx1);
        const float cr0 = __expf(mst0 - mn0), cr1 = __expf(mst1 - mn1);
        mst0 = mn0; mst1 = mn1;

        float rs0 = 0.f, rs1 = 0.f;
#pragma unroll
        for (int n = 0; n < 8; n++) {
            S[n][0] = __expf(S[n][0] - mn0);
            S[n][1] = __expf(S[n][1] - mn0);
            S[n][2] = __expf(S[n][2] - mn1);
            S[n][3] = __expf(S[n][3] - mn1);
            rs0 += S[n][0] + S[n][1];
            rs1 += S[n][2] + S[n][3];
        }
        rs0 += __shfl_xor_sync(0xffffffffu, rs0, 1);
        rs0 += __shfl_xor_sync(0xffffffffu, rs0, 2);
        rs1 += __shfl_xor_sync(0xffffffffu, rs1, 1);
        rs1 += __shfl_xor_sync(0xffffffffu, rs1, 2);
        lst0 = lst0 * cr0 + rs0;
        lst1 = lst1 * cr1 + rs1;

#pragma unroll
        for (int n = 0; n < 8; n++) {
            O[n][0] *= cr0; O[n][1] *= cr0;
            O[n][2] *= cr1; O[n][3] *= cr1;
        }

#pragma unroll
        for (int kg = 0; kg < 4; kg++) {
            uint32_t ph[4];
            ph[0] = pack2(S[2 * kg][0],     S[2 * kg][1]);
            ph[1] = pack2(S[2 * kg][2],     S[2 * kg][3]);
            ph[2] = pack2(S[2 * kg + 1][0], S[2 * kg + 1][1]);
            ph[3] = pack2(S[2 * kg + 1][2], S[2 * kg + 1][3]);
#pragma unroll
            for (int nb = 0; nb < 4; nb++) {
                uint32_t vh[4];
                ldsm4t(vh, st + ATT_KVTILE + voffV + kg * 16 * AROW + nb * 32);
                mma_f32(O[2 * nb],     ph, &vh[0]);
                mma_f32(O[2 * nb + 1], ph, &vh[2]);
            }
        }
    }

    const float inv0 = 1.f / lst0, inv1 = 1.f / lst1;
    const int row0 = b * T_SEQ + qt + w * 16 + (lane >> 2);
    const int colb = h * 64 + (lane & 3) * 2;
#pragma unroll
    for (int n = 0; n < 8; n++) {
        const size_t o0 = (size_t)row0 * D_MODEL + colb + n * 8;
        const size_t o1 = (size_t)(row0 + 8) * D_MODEL + colb + n * 8;
        *(uint32_t*)(out_hi + o0) = pack2(O[n][0] * inv0, O[n][1] * inv0);
        *(uint32_t*)(out_hi + o1) = pack2(O[n][2] * inv1, O[n][3] * inv1);
    }
}

// ---------------------------------------------------------------------------
extern "C" void kernel_launch(void* const* d_in, const int* in_sizes, int n_in,
                              void* d_out, int out_size)
{
    const float* x      = (const float*)d_in[0];
    const float* mask   = (const float*)d_in[1];
    const float* w_attn = (const float*)d_in[2];
    const float* b_attn = (const float*)d_in[3];
    const float* w_proj = (const float*)d_in[4];
    const float* b_proj = (const float*)d_in[5];
    float* out = (float*)d_out;

    __half *qkv_hi, *att_hi;
    __half *xa_hi, *wa_hi, *wp_hi, *wp_lo;
    cudaGetSymbolAddress((void**)&qkv_hi, g_qkv_hi);
    cudaGetSymbolAddress((void**)&att_hi, g_att_hi);
    cudaGetSymbolAddress((void**)&xa_hi, g_xa_hi);
    cudaGetSymbolAddress((void**)&wa_hi, g_wa_hi);
    cudaGetSymbolAddress((void**)&wp_hi, g_wp_hi);
    cudaGetSymbolAddress((void**)&wp_lo, g_wp_lo);

    const int SMEM_1T = 3 * 2 * TILE_B;   // 61440
    const int SMEM_2T = 3 * 3 * TILE_B;   // 92160
    cudaFuncSetAttribute((const void*)gemm_hmma<1, 1, 8>,
                         cudaFuncAttributeMaxDynamicSharedMemorySize, SMEM_1T);
    cudaFuncSetAttribute((const void*)gemm_hmma<2, 0, 4>,
                         cudaFuncAttributeMaxDynamicSharedMemorySize, SMEM_2T);
    cudaFuncSetAttribute((const void*)attn_hmma,
                         cudaFuncAttributeMaxDynamicSharedMemorySize, ATT_SMEM);

    const int nx = BT_ROWS * 1024;

    // 1) conversions
    cvt_mat<<<nx / 4 / 256, 256>>>(x, xa_hi, nx);
    cvt_wT<<<dim3(3072 / 32, 1024 / 32), dim3(32, 8)>>>(w_attn, wa_hi, 1024, 3072);
    split_wT<<<dim3(1024 / 32, 1024 / 32), dim3(32, 8)>>>(w_proj, wp_hi, wp_lo, 1024, 1024);

    // 2) qkv = xh @ Wh + b  -> f16 (1-term, 8 warps)
    gemm_hmma<1, 1, 8><<<dim3(3072 / 128, BT_ROWS / 128), 256, SMEM_1T>>>(
        xa_hi, wa_hi, nullptr, b_attn, nullptr, qkv_hi, 3072, 1024);

    // 3) attention -> att hi
    attn_hmma<<<dim3(T_SEQ / 128, 16, 2), 256, ATT_SMEM>>>(
        qkv_hi, mask, att_hi);

    // 4) out = ah @ (Wph + Wpl) + b  (fp32 out, 2-term, 4 warps)
    gemm_hmma<2, 0, 4><<<dim3(1024 / 128, BT_ROWS / 128), 128, SMEM_2T>>>(
        att_hi, wp_hi, wp_lo, b_proj, out, nullptr, 1024, 1024);
}

// round 15
// speedup vs baseline: 2.3551x; 1.0195x over previous
#include <cuda_runtime.h>
#include <cuda_fp16.h>
#include <cstdint>

#define T_SEQ 2048
#define D_MODEL 1024
#define BT_ROWS 4096            // B*T

// ---------------------------------------------------------------------------
// Scratch (device globals; no allocations anywhere).
// ---------------------------------------------------------------------------
__device__ __half g_qkv_hi[(size_t)BT_ROWS * 3072];
__device__ __half g_att_hi[(size_t)BT_ROWS * 1024];
__device__ __half g_xa_hi[(size_t)BT_ROWS * 1024];
__device__ __half g_wa_hi[(size_t)3072 * 1024];  // w_attn^T [N,K]
__device__ __half g_wp_hi[(size_t)1024 * 1024];  // w_proj^T [N,K]
__device__ __half g_wp_lo[(size_t)1024 * 1024];

// ---------------------------------------------------------------------------
// Helpers (plain sm_80-era PTX only)
// ---------------------------------------------------------------------------
__device__ __forceinline__ uint32_t smem_u32(const void* p) {
    uint32_t a;
    asm("{ .reg .u64 t; cvta.to.shared.u64 t, %1; cvt.u32.u64 %0, t; }"
        : "=r"(a) : "l"(p));
    return a;
}

__device__ __forceinline__ void cpa16(uint32_t s, const void* g) {
    asm volatile("cp.async.cg.shared.global [%0], [%1], 16;" :: "r"(s), "l"(g));
}

__device__ __forceinline__ void ldsm4(uint32_t* r, uint32_t a) {
    asm volatile("ldmatrix.sync.aligned.m8n8.x4.shared.b16 {%0,%1,%2,%3}, [%4];"
                 : "=r"(r[0]), "=r"(r[1]), "=r"(r[2]), "=r"(r[3]) : "r"(a));
}

__device__ __forceinline__ void ldsm4t(uint32_t* r, uint32_t a) {
    asm volatile("ldmatrix.sync.aligned.m8n8.x4.trans.shared.b16 {%0,%1,%2,%3}, [%4];"
                 : "=r"(r[0]), "=r"(r[1]), "=r"(r[2]), "=r"(r[3]) : "r"(a));
}

// f16 x f16 -> f32 accumulate
__device__ __forceinline__ void mma_f32(float* d, const uint32_t* a,
                                        const uint32_t* b) {
    asm volatile(
        "mma.sync.aligned.m16n8k16.row.col.f32.f16.f16.f32 "
        "{%0,%1,%2,%3}, {%4,%5,%6,%7}, {%8,%9}, {%0,%1,%2,%3};"
        : "+f"(d[0]), "+f"(d[1]), "+f"(d[2]), "+f"(d[3])
        : "r"(a[0]), "r"(a[1]), "r"(a[2]), "r"(a[3]), "r"(b[0]), "r"(b[1]));
}

// f16 x f16 -> f16 accumulate (GEMM lo cross-term)
__device__ __forceinline__ void mma_f16(uint32_t* d, const uint32_t* a,
                                        const uint32_t* b) {
    asm volatile(
        "mma.sync.aligned.m16n8k16.row.col.f16.f16.f16.f16 "
        "{%0,%1}, {%2,%3,%4,%5}, {%6,%7}, {%0,%1};"
        : "+r"(d[0]), "+r"(d[1])
        : "r"(a[0]), "r"(a[1]), "r"(a[2]), "r"(a[3]), "r"(b[0]), "r"(b[1]));
}

// pack a pair of fp32 -> f16x2 (single rounding)
__device__ __forceinline__ uint32_t pack2(float a, float b) {
    __half2 h;
    h.x = __float2half(a);
    h.y = __float2half(b);
    return *(uint32_t*)&h;
}

// ---------------------------------------------------------------------------
// Fused preparation kernel: one launch does all three conversions.
//   blocks [0, 4096)            : x fp32 -> f16            (256 thr, 4 elem/thr)
//   blocks [4096, 4096+3072)    : w_attn [1024,3072] -> wa_hi^T [3072,1024]
//   blocks [7168, 7168+1024)    : w_proj [1024,1024] -> wp_hi/lo^T
// ---------------------------------------------------------------------------
#define PREP_X_BLOCKS    (BT_ROWS * D_MODEL / 4 / 256)   // 4096
#define PREP_WA_BLOCKS   ((3072 / 32) * (1024 / 32))     // 3072
#define PREP_WP_BLOCKS   ((1024 / 32) * (1024 / 32))     // 1024
#define PREP_BLOCKS      (PREP_X_BLOCKS + PREP_WA_BLOCKS + PREP_WP_BLOCKS)

__global__ __launch_bounds__(256) void prep_all(
    const float* __restrict__ x,      __half* __restrict__ xa,
    const float* __restrict__ wa,     __half* __restrict__ wah,
    const float* __restrict__ wp,     __half* __restrict__ wph,
    __half* __restrict__ wpl)
{
    __shared__ float t[32][33];
    const int bid = blockIdx.x, tid = threadIdx.x;

    if (bid < PREP_X_BLOCKS) {
        // x fp32 -> f16
        int i = (bid * 256 + tid) * 4;
        float4 v = *(const float4*)(x + i);
        ((uint32_t*)(xa + i))[0] = pack2(v.x, v.y);
        ((uint32_t*)(xa + i))[1] = pack2(v.z, v.w);
        return;
    }

    const int tx = tid & 31, ty = tid >> 5;   // (32, 8) geometry

    if (bid < PREP_X_BLOCKS + PREP_WA_BLOCKS) {
        // w_attn transpose-convert: [Kd=1024, Nd=3072] -> [Nd, Kd] f16
        const int bb = bid - PREP_X_BLOCKS;
        const int n0 = (bb % (3072 / 32)) * 32;
        const int k0 = (bb / (3072 / 32)) * 32;
#pragma unroll
        for (int j = 0; j < 32; j += 8)
            t[ty + j][tx] = wa[(size_t)(k0 + ty + j) * 3072 + n0 + tx];
        __syncthreads();
#pragma unroll
        for (int j = 0; j < 32; j += 8)
            wah[(size_t)(n0 + ty + j) * 1024 + k0 + tx] =
                __float2half(t[tx][ty + j]);
        return;
    }

    // w_proj transpose-split: [1024, 1024] -> hi/lo [1024, 1024]
    {
        const int bb = bid - PREP_X_BLOCKS - PREP_WA_BLOCKS;
        const int n0 = (bb % (1024 / 32)) * 32;
        const int k0 = (bb / (1024 / 32)) * 32;
#pragma unroll
        for (int j = 0; j < 32; j += 8)
            t[ty + j][tx] = wp[(size_t)(k0 + ty + j) * 1024 + n0 + tx];
        __syncthreads();
#pragma unroll
        for (int j = 0; j < 32; j += 8) {
            float v = t[tx][ty + j];
            __half h = __float2half(v);
            size_t o = (size_t)(n0 + ty + j) * 1024 + k0 + tx;
            wph[o] = h;
            wpl[o] = __float2half(v - __half2float(h));
        }
    }
}

// ---------------------------------------------------------------------------
// HMMA GEMM: C = Ah @ (Bh [+ Bl])^T + bias   (identical to R14)
// 128x128 CTA tile, BK=32, 3-stage early-issue pipeline.
// NWARP=4: warp tile 64x64 (2-term proj).  NWARP=8: warp tile 32x64 (1-term).
// ---------------------------------------------------------------------------
#define GBK 32
#define ROWB 80
#define TILE_B (128 * ROWB)

template <int TERMS, int CVT_OUT, int NWARP>
__global__ __launch_bounds__(NWARP * 32) void gemm_hmma(
    const __half* __restrict__ Ahi,
    const __half* __restrict__ Bhi, const __half* __restrict__ Blo,
    const float* __restrict__ bias, float* __restrict__ C,
    __half* __restrict__ Chi,
    int N, int K)
{
    constexpr uint32_t STAGE = (1 + TERMS) * TILE_B;
    constexpr int NT = NWARP * 32;
    constexpr int MI = (NWARP == 4) ? 4 : 2;

    extern __shared__ char smc[];
    const uint32_t sb = smem_u32(smc);
    const int tid = threadIdx.x, lane = tid & 31, wid = tid >> 5;
    const int bm = blockIdx.y * 128, bn = blockIdx.x * 128;
    const int mbw = (NWARP == 4) ? (wid & 1) * 64 : (wid & 3) * 32;
    const int nbw = (NWARP == 4) ? (wid >> 1) * 64 : (wid >> 2) * 64;

    float acc[MI][8][4];
    uint32_t accL[MI][8][2];
#pragma unroll
    for (int m = 0; m < MI; m++)
#pragma unroll
        for (int n = 0; n < 8; n++) {
#pragma unroll
            for (int j = 0; j < 4; j++) acc[m][n][j] = 0.f;
            accL[m][n][0] = 0u; accL[m][n][1] = 0u;
        }

    const uint32_t aoff =
        (uint32_t)(mbw + (lane & 15)) * ROWB + (uint32_t)(lane >> 4) * 16;
    const uint32_t boff =
        (uint32_t)(nbw + (lane >> 4) * 8 + (lane & 7)) * ROWB +
        (uint32_t)((lane >> 3) & 1) * 16;

    auto load_stage = [&](int s, int kt) {
        const uint32_t st = sb + s * STAGE;
        const int kc = kt * GBK;
        const __half* gp[3] = {Ahi, Bhi, Blo};
#pragma unroll
        for (int c = 0; c < (1 + TERMS) * 512 / NT; c++) {
            int idx = tid + c * NT;
            int tile = idx >> 9;
            int rem = idx & 511;
            int row = rem >> 2, q = rem & 3;
            const int rbase = (tile == 0) ? bm : bn;
            const __half* g =
                gp[tile] + (size_t)(rbase + row) * K + kc + q * 8;
            cpa16(st + tile * TILE_B + row * ROWB + q * 16, g);
        }
        asm volatile("cp.async.commit_group;" ::: "memory");
    };

    const int KT = K / GBK;
    load_stage(0, 0);
    load_stage(1, 1);

    for (int kt = 0; kt < KT; kt++) {
        const int s = kt % 3;
        if (kt + 1 < KT)
            asm volatile("cp.async.wait_group 1;" ::: "memory");
        else
            asm volatile("cp.async.wait_group 0;" ::: "memory");
        __syncthreads();

        if (kt + 2 < KT) load_stage((kt + 2) % 3, kt + 2);

        const uint32_t st = sb + s * STAGE;
        const uint32_t stAh = st;
        const uint32_t stBh = st + TILE_B, stBl = st + 2 * TILE_B;

#pragma unroll
        for (int ks = 0; ks < 2; ks++) {
            const uint32_t ko = ks * 32;
            uint32_t bh[4][4], ah[MI][4];
#pragma unroll
            for (int p = 0; p < 4; p++)
                ldsm4(bh[p], stBh + boff + p * 16 * ROWB + ko);
#pragma unroll
            for (int m = 0; m < MI; m++)
                ldsm4(ah[m], stAh + aoff + m * 16 * ROWB + ko);
#pragma unroll
            for (int n = 0; n < 8; n++)
#pragma unroll
                for (int m = 0; m < MI; m++)
                    mma_f32(acc[m][n], ah[m], &bh[n >> 1][(n & 1) * 2]);
            if (TERMS == 2) {
                uint32_t bl[4][4];
#pragma unroll
                for (int p = 0; p < 4; p++)
                    ldsm4(bl[p], stBl + boff + p * 16 * ROWB + ko);
#pragma unroll
                for (int n = 0; n < 8; n++)
#pragma unroll
                    for (int m = 0; m < MI; m++)
                        mma_f16(accL[m][n], ah[m], &bl[n >> 1][(n & 1) * 2]);
            }
        }
    }

    // Epilogue
    const int rql = lane >> 2, cql = (lane & 3) * 2;
#pragma unroll
    for (int m = 0; m < MI; m++) {
        const int row = bm + mbw + m * 16 + rql;
#pragma unroll
        for (int n = 0; n < 8; n++) {
            const int col = bn + nbw + n * 8 + cql;
            const float bx = bias[col], by = bias[col + 1];
            float v0 = acc[m][n][0] + bx;
            float v1 = acc[m][n][1] + by;
            float v2 = acc[m][n][2] + bx;
            float v3 = acc[m][n][3] + by;
            if (TERMS == 2) {
                __half2 lo0 = *(__half2*)&accL[m][n][0];
                __half2 lo1 = *(__half2*)&accL[m][n][1];
                v0 += __half2float(lo0.x);
                v1 += __half2float(lo0.y);
                v2 += __half2float(lo1.x);
                v3 += __half2float(lo1.y);
            }
            if (CVT_OUT) {
                *(uint32_t*)(Chi + (size_t)row * N + col) = pack2(v0, v1);
                *(uint32_t*)(Chi + (size_t)(row + 8) * N + col) = pack2(v2, v3);
            } else {
                *(float2*)(C + (size_t)row * N + col) = make_float2(v0, v1);
                *(float2*)(C + (size_t)(row + 8) * N + col) = make_float2(v2, v3);
            }
        }
    }
}

// ---------------------------------------------------------------------------
// HMMA flash attention (identical to R14):
//   S = Qh*Kh ;  O += P16 * Vh   (f32 accum)
// 3-stage early-issue pipeline, hoisted Q fragments.
// ---------------------------------------------------------------------------
#define AROW 144
#define ATT_QBYTES (128 * AROW)          // 18432
#define ATT_KVTILE (64 * AROW)           // 9216
#define ATT_STAGE (2 * ATT_KVTILE + 256) // 18688
#define ATT_SMEM (ATT_QBYTES + 3 * ATT_STAGE)   // 74496

__global__ __launch_bounds__(256) void attn_hmma(
    const __half* __restrict__ qkv_hi,
    const float* __restrict__ mask,
    __half* __restrict__ out_hi)
{
    extern __shared__ char smc[];
    const uint32_t sb = smem_u32(smc);
    const int tid = threadIdx.x, lane = tid & 31, w = tid >> 5;
    const int qt = blockIdx.x * 128;
    const int h = blockIdx.y, b = blockIdx.z;

#pragma unroll
    for (int i = 0; i < 4; i++) {
        int idx = tid + i * 256;
        int row = idx >> 3, c = idx & 7;
        const __half* g = qkv_hi +
            (size_t)(b * T_SEQ + qt + row) * 3072 + h * 64 + c * 8;
        cpa16(sb + row * AROW + c * 16, g);
    }

    const uint32_t stg0 = sb + ATT_QBYTES;

    auto load_kv = [&](int s, int kt) {
        const uint32_t st = stg0 + s * ATT_STAGE;
#pragma unroll
        for (int i = 0; i < 4; i++) {
            int idx = tid + i * 256;
            int tile = idx >> 9;
            int rem = idx & 511;
            int row = rem >> 3, c = rem & 7;
            int coff = ((tile == 0) ? 1024 : 2048) + h * 64;
            const __half* g = qkv_hi +
                (size_t)(b * T_SEQ + kt * 64 + row) * 3072 + coff + c * 8;
            cpa16(st + tile * ATT_KVTILE + row * AROW + c * 16, g);
        }
        if (tid < 16)
            cpa16(st + 2 * ATT_KVTILE + tid * 16,
                  mask + (size_t)b * T_SEQ + kt * 64 + tid * 4);
        asm volatile("cp.async.commit_group;" ::: "memory");
    };

    load_kv(0, 0);
    load_kv(1, 1);

    const uint32_t aoffQ = (uint32_t)(w * 16 + (lane & 15)) * AROW +
                           (uint32_t)(lane >> 4) * 16;
    const uint32_t boffK = (uint32_t)((lane >> 4) * 8 + (lane & 7)) * AROW +
                           (uint32_t)((lane >> 3) & 1) * 16;
    const uint32_t voffV = (uint32_t)(lane & 15) * AROW +
                           (uint32_t)(lane >> 4) * 16;

    uint32_t qf[4][4];
    float mst0 = -1e30f, mst1 = -1e30f, lst0 = 0.f, lst1 = 0.f;
    float O[8][4];
#pragma unroll
    for (int n = 0; n < 8; n++)
#pragma unroll
        for (int j = 0; j < 4; j++) O[n][j] = 0.f;

    const int NKV = T_SEQ / 64;
    for (int kt = 0; kt < NKV; kt++) {
        const int s = kt % 3;
        if (kt + 1 < NKV)
            asm volatile("cp.async.wait_group 1;" ::: "memory");
        else
            asm volatile("cp.async.wait_group 0;" ::: "memory");
        __syncthreads();

        if (kt == 0) {
#pragma unroll
            for (int kg = 0; kg < 4; kg++)
                ldsm4(qf[kg], sb + aoffQ + kg * 32);
        }
        if (kt + 2 < NKV) load_kv((kt + 2) % 3, kt + 2);

        const uint32_t st = stg0 + s * ATT_STAGE;
        const float* mskp = (const float*)(smc + ATT_QBYTES +
                                           s * ATT_STAGE + 2 * ATT_KVTILE);

        float S[8][4];
#pragma unroll
        for (int n = 0; n < 8; n++)
#pragma unroll
            for (int j = 0; j < 4; j++) S[n][j] = 0.f;

#pragma unroll
        for (int kg = 0; kg < 4; kg++) {
#pragma unroll
            for (int nb = 0; nb < 4; nb++) {
                uint32_t kh[4];
                ldsm4(kh, st + boffK + nb * 16 * AROW + kg * 32);
                mma_f32(S[2 * nb],     qf[kg], &kh[0]);
                mma_f32(S[2 * nb + 1], qf[kg], &kh[2]);
            }
        }

        float mx0 = -1e30f, mx1 = -1e30f;
#pragma unroll
        for (int n = 0; n < 8; n++) {
            float2 mk = *(const float2*)(mskp + n * 8 + (lane & 3) * 2);
            float m0 = 2.f * mk.x, m1 = 2.f * mk.y;
            S[n][0] = fmaf(S[n][0], 0.125f, m0);
            S[n][1] = fmaf(S[n][1], 0.125f, m1);
            S[n][2] = fmaf(S[n][2], 0.125f, m0);
            S[n][3] = fmaf(S[n][3], 0.125f, m1);
            mx0 = fmaxf(mx0, fmaxf(S[n][0], S[n][1]));
            mx1 = fmaxf(mx1, fmaxf(S[n][2], S[n][3]));
        }
        mx0 = fmaxf(mx0, __shfl_xor_sync(0xffffffffu, mx0, 1));
        mx0 = fmaxf(mx0, __shfl_xor_sync(0xffffffffu, mx0, 2));
        mx1 = fmaxf(mx1, __shfl_xor_sync(0xffffffffu, mx1, 1));
        mx1 = fmaxf(mx1, __shfl_xor_sync(0xffffffffu, mx1, 2));

        const float mn0 = fmaxf(mst0, mx0), mn1 = fmaxf(mst1, mx1);
        const float cr0 = __expf(mst0 - mn0), cr1 = __expf(mst1 - mn1);
        mst0 = mn0; mst1 = mn1;

        float rs0 = 0.f, rs1 = 0.f;
#pragma unroll
        for (int n = 0; n < 8; n++) {
            S[n][0] = __expf(S[n][0] - mn0);
            S[n][1] = __expf(S[n][1] - mn0);
            S[n][2] = __expf(S[n][2] - mn1);
            S[n][3] = __expf(S[n][3] - mn1);
            rs0 += S[n][0] + S[n][1];
            rs1 += S[n][2] + S[n][3];
        }
        rs0 += __shfl_xor_sync(0xffffffffu, rs0, 1);
        rs0 += __shfl_xor_sync(0xffffffffu, rs0, 2);
        rs1 += __shfl_xor_sync(0xffffffffu, rs1, 1);
        rs1 += __shfl_xor_sync(0xffffffffu, rs1, 2);
        lst0 = lst0 * cr0 + rs0;
        lst1 = lst1 * cr1 + rs1;

#pragma unroll
        for (int n = 0; n < 8; n++) {
            O[n][0] *= cr0; O[n][1] *= cr0;
            O[n][2] *= cr1; O[n][3] *= cr1;
        }

#pragma unroll
        for (int kg = 0; kg < 4; kg++) {
            uint32_t ph[4];
            ph[0] = pack2(S[2 * kg][0],     S[2 * kg][1]);
            ph[1] = pack2(S[2 * kg][2],     S[2 * kg][3]);
            ph[2] = pack2(S[2 * kg + 1][0], S[2 * kg + 1][1]);
            ph[3] = pack2(S[2 * kg + 1][2], S[2 * kg + 1][3]);
#pragma unroll
            for (int nb = 0; nb < 4; nb++) {
                uint32_t vh[4];
                ldsm4t(vh, st + ATT_KVTILE + voffV + kg * 16 * AROW + nb * 32);
                mma_f32(O[2 * nb],     ph, &vh[0]);
                mma_f32(O[2 * nb + 1], ph, &vh[2]);
            }
        }
    }

    const float inv0 = 1.f / lst0, inv1 = 1.f / lst1;
    const int row0 = b * T_SEQ + qt + w * 16 + (lane >> 2);
    const int colb = h * 64 + (lane & 3) * 2;
#pragma unroll
    for (int n = 0; n < 8; n++) {
        const size_t o0 = (size_t)row0 * D_MODEL + colb + n * 8;
        const size_t o1 = (size_t)(row0 + 8) * D_MODEL + colb + n * 8;
        *(uint32_t*)(out_hi + o0) = pack2(O[n][0] * inv0, O[n][1] * inv0);
        *(uint32_t*)(out_hi + o1) = pack2(O[n][2] * inv1, O[n][3] * inv1);
    }
}

// ---------------------------------------------------------------------------
extern "C" void kernel_launch(void* const* d_in, const int* in_sizes, int n_in,
                              void* d_out, int out_size)
{
    const float* x      = (const float*)d_in[0];
    const float* mask   = (const float*)d_in[1];
    const float* w_attn = (const float*)d_in[2];
    const float* b_attn = (const float*)d_in[3];
    const float* w_proj = (const float*)d_in[4];
    const float* b_proj = (const float*)d_in[5];
    float* out = (float*)d_out;

    __half *qkv_hi, *att_hi;
    __half *xa_hi, *wa_hi, *wp_hi, *wp_lo;
    cudaGetSymbolAddress((void**)&qkv_hi, g_qkv_hi);
    cudaGetSymbolAddress((void**)&att_hi, g_att_hi);
    cudaGetSymbolAddress((void**)&xa_hi, g_xa_hi);
    cudaGetSymbolAddress((void**)&wa_hi, g_wa_hi);
    cudaGetSymbolAddress((void**)&wp_hi, g_wp_hi);
    cudaGetSymbolAddress((void**)&wp_lo, g_wp_lo);

    const int SMEM_1T = 3 * 2 * TILE_B;   // 61440
    const int SMEM_2T = 3 * 3 * TILE_B;   // 92160
    cudaFuncSetAttribute((const void*)gemm_hmma<1, 1, 8>,
                         cudaFuncAttributeMaxDynamicSharedMemorySize, SMEM_1T);
    cudaFuncSetAttribute((const void*)gemm_hmma<2, 0, 4>,
                         cudaFuncAttributeMaxDynamicSharedMemorySize, SMEM_2T);
    cudaFuncSetAttribute((const void*)attn_hmma,
                         cudaFuncAttributeMaxDynamicSharedMemorySize, ATT_SMEM);

    // 1) all conversions in one launch
    prep_all<<<PREP_BLOCKS, 256>>>(x, xa_hi, w_attn, wa_hi,
                                   w_proj, wp_hi, wp_lo);

    // 2) qkv = xh @ Wh + b  -> f16 (1-term, 8 warps)
    gemm_hmma<1, 1, 8><<<dim3(3072 / 128, BT_ROWS / 128), 256, SMEM_1T>>>(
        xa_hi, wa_hi, nullptr, b_attn, nullptr, qkv_hi, 3072, 1024);

    // 3) attention -> att hi
    attn_hmma<<<dim3(T_SEQ / 128, 16, 2), 256, ATT_SMEM>>>(
        qkv_hi, mask, att_hi);

    // 4) out = ah @ (Wph + Wpl) + b  (fp32 out, 2-term, 4 warps)
    gemm_hmma<2, 0, 4><<<dim3(1024 / 128, BT_ROWS / 128), 128, SMEM_2T>>>(
        att_hi, wp_hi, wp_lo, b_proj, out, nullptr, 1024, 1024);
}